// round 9
// baseline (speedup 1.0000x reference)
#include <cuda_runtime.h>
#include <math.h>

// ---------------- scratch ----------------
__device__ __align__(16) float2 g_s3[16777216];  // [4][64][64][8][128] fwd-L out / inv-W out
__device__ __align__(16) float2 g_s2[8388608];   // [4][64][32][8][128] workspace (k_mid in-place)
__device__ __align__(16) float  g_W[8192];       // [4 mats][8 blk][16][16] folded MLP weights
__device__ __align__(16) float  g_Bias[512];     // [4][8][16] folded biases
// per-lane packed tf32 mma A-fragments: idx = ((mat*KT+kk)*MT+mt)*32+lane
__device__ __align__(16) float4 g_A4W[1024];     // fwd W/H: M=32,K=64 (cos|sin), 1/8 baked
__device__ __align__(16) float4 g_A4Wi[1024];    // inv W/H: M=64,K=32 (cos|sin), 1/8 baked

__constant__ float2 TW32[32] = {
  { 1.000000000f, 0.000000000f},{ 0.980785280f, 0.195090322f},{ 0.923879533f, 0.382683432f},{ 0.831469612f, 0.555570233f},
  { 0.707106781f, 0.707106781f},{ 0.555570233f, 0.831469612f},{ 0.382683432f, 0.923879533f},{ 0.195090322f, 0.980785280f},
  { 0.000000000f, 1.000000000f},{-0.195090322f, 0.980785280f},{-0.382683432f, 0.923879533f},{-0.555570233f, 0.831469612f},
  {-0.707106781f, 0.707106781f},{-0.831469612f, 0.555570233f},{-0.923879533f, 0.382683432f},{-0.980785280f, 0.195090322f},
  {-1.000000000f, 0.000000000f},{-0.980785280f,-0.195090322f},{-0.923879533f,-0.382683432f},{-0.831469612f,-0.555570233f},
  {-0.707106781f,-0.707106781f},{-0.555570233f,-0.831469612f},{-0.382683432f,-0.923879533f},{-0.195090322f,-0.980785280f},
  { 0.000000000f,-1.000000000f},{ 0.195090322f,-0.980785280f},{ 0.382683432f,-0.923879533f},{ 0.555570233f,-0.831469612f},
  { 0.707106781f,-0.707106781f},{ 0.831469612f,-0.555570233f},{ 0.923879533f,-0.382683432f},{ 0.980785280f,-0.195090322f}
};

__device__ __forceinline__ float gelu_f(float v){
  return 0.5f*v*(1.0f+erff(v*0.7071067811865476f));
}
__device__ __forceinline__ float tf32f(float f){
  unsigned u; asm("cvt.rna.tf32.f32 %0, %1;" : "=r"(u) : "f"(f));
  return __uint_as_float(u);
}
__device__ __forceinline__ void mma8(float4& d, float a0, float a1, float a2, float a3,
                                     float b0, float b1){
  asm volatile("mma.sync.aligned.m16n8k8.row.col.f32.tf32.tf32.f32 "
    "{%0,%1,%2,%3}, {%4,%5,%6,%7}, {%8,%9}, {%0,%1,%2,%3};"
    : "+f"(d.x), "+f"(d.y), "+f"(d.z), "+f"(d.w)
    : "r"(__float_as_uint(a0)), "r"(__float_as_uint(a1)),
      "r"(__float_as_uint(a2)), "r"(__float_as_uint(a3)),
      "r"(__float_as_uint(b0)), "r"(__float_as_uint(b1)));
}

// ---------------- K0a: build packed twiddle fragments ----------------
__device__ __forceinline__ float twval(int mat, int m, int k){
  double a = (double)(m*k)/32.0;
  return tf32f((float)((mat ? sinpi(a) : cospi(a))*0.125));
}
__global__ void k_init4(){
  int e = blockIdx.x*256 + threadIdx.x;   // 0..2047
  int lane = e&31, qid = lane>>2, rid = lane&3;
  int which = e>>10, j = e&1023;
  if (which==0){                           // fwd: MT=2, KT=8
    int mt=(j>>5)&1, kk=(j>>6)&7, mat=j>>9;
    int r0=mt*16+qid, r1=r0+8, k0=kk*8+rid, k1=k0+4;
    g_A4W[j] = make_float4(twval(mat,r0,k0), twval(mat,r1,k0),
                           twval(mat,r0,k1), twval(mat,r1,k1));
  } else {                                 // inv: MT=4, KT=4
    int mt=(j>>5)&3, kk=(j>>7)&3, mat=j>>9;
    int r0=mt*16+qid, r1=r0+8, k0=kk*8+rid, k1=k0+4;
    g_A4Wi[j] = make_float4(twval(mat,r0,k0), twval(mat,r1,k0),
                            twval(mat,r0,k1), twval(mat,r1,k1));
  }
}

// ---------------- K0: fold HydraLoRA ----------------
__global__ void k_prep(const float* __restrict__ w1, const float* __restrict__ b1,
                       const float* __restrict__ w2, const float* __restrict__ b2,
                       const float* __restrict__ A1r, const float* __restrict__ B1r,
                       const float* __restrict__ A1i, const float* __restrict__ B1i,
                       const float* __restrict__ A2r, const float* __restrict__ B2r,
                       const float* __restrict__ A2i, const float* __restrict__ B2i,
                       const float* __restrict__ ew){
  int k  = blockIdx.x;
  int io = threadIdx.x;
  int i = io >> 4, o = io & 15;
  float e0 = ew[0], e1 = ew[1], e2 = ew[2], e3 = ew[3];
  const float s = 0.03125f;
  const float* Ws[4] = { w1 + k*256, w1 + 2048 + k*256, w2 + k*256, w2 + 2048 + k*256 };
  const float* As[4] = { A1r + k*512, A1i + k*512, A2r + k*512, A2i + k*512 };
  const float* Bs[4] = { B1r + k*2048, B1i + k*2048, B2r + k*2048, B2i + k*2048 };
#pragma unroll
  for (int m = 0; m < 4; m++){
    const float* A  = As[m] + i*32;
    const float* Bb = Bs[m];
    float acc = 0.f;
    for (int r = 0; r < 32; r++){
      float bm = e0*Bb[r*16+o] + e1*Bb[512+r*16+o] + e2*Bb[1024+r*16+o] + e3*Bb[1536+r*16+o];
      acc = fmaf(A[r], bm, acc);
    }
    g_W[((m*8+k)*16+i)*16+o] = Ws[m][i*16+o] + s*acc;
  }
  if (io < 16){
    float b10 = b1[k*16+io], b11 = b1[128+k*16+io];
    float b20 = b2[k*16+io], b21 = b2[128+k*16+io];
    g_Bias[      k*16+io] = b10 - b11;
    g_Bias[128 + k*16+io] = b10 + b11;
    g_Bias[256 + k*16+io] = b20 - b21;
    g_Bias[384 + k*16+io] = b20 + b21;
  }
}

// ---------------- K1: forward rfft over L (radix-2, channel-pair float2) ----------------
__global__ void k_fwd_l(const float* __restrict__ x){
  __shared__ float2 tw[32];
  if (threadIdx.x < 32) tw[threadIdx.x] = TW32[threadIdx.x];
  __syncthreads();
  int site = blockIdx.x;          // b*4096 + y*64 + xx
  int c = threadIdx.x;            // 0..63 channel pair
  const float2* xp = (const float2*)(x + (size_t)site*4096) + c;
  float2 u[16], dd[16];
#pragma unroll
  for (int t=0;t<16;t++){
    float2 a = xp[t*64], b2 = xp[(t+16)*64];
    u[t]  = make_float2(a.x+b2.x, a.y+b2.y);
    dd[t] = make_float2(a.x-b2.x, a.y-b2.y);
  }
  float2 ar[8], ai[8];
#pragma unroll
  for (int l=0;l<8;l++){ ar[l]=make_float2(0.f,0.f); ai[l]=make_float2(0.f,0.f); }
#pragma unroll
  for (int t=0;t<16;t++){
#pragma unroll
    for (int j=0;j<4;j++){
      float2 we = tw[(t*2*j)&31];
      ar[2*j].x = fmaf( u[t].x, we.x, ar[2*j].x);
      ar[2*j].y = fmaf( u[t].y, we.x, ar[2*j].y);
      ai[2*j].x = fmaf(-u[t].x, we.y, ai[2*j].x);
      ai[2*j].y = fmaf(-u[t].y, we.y, ai[2*j].y);
      float2 wo = tw[(t*(2*j+1))&31];
      ar[2*j+1].x = fmaf( dd[t].x, wo.x, ar[2*j+1].x);
      ar[2*j+1].y = fmaf( dd[t].y, wo.x, ar[2*j+1].y);
      ai[2*j+1].x = fmaf(-dd[t].x, wo.y, ai[2*j+1].x);
      ai[2*j+1].y = fmaf(-dd[t].y, wo.y, ai[2*j+1].y);
    }
  }
  const float s = 0.1767766952966369f;
  float4* op = (float4*)(g_s3 + (size_t)site*1024) + c;
#pragma unroll
  for (int l=0;l<8;l++)
    op[l*64] = make_float4(ar[l].x*s, ai[l].x*s, ar[l].y*s, ai[l].y*s);
}

// ---------------- complex DFT GEMM stage (pair-split B layout) ----------------
template<int M, int K, int SGN, int MINB>
__global__ void __launch_bounds__(128, MINB) k_dft_mma(const float* __restrict__ in,
                                                 float* __restrict__ out,
                                                 const float4* __restrict__ A4,
                                                 int rowLen2, size_t inStride2,
                                                 size_t outStride2){
  constexpr int KT = K/8;
  constexpr int MT = M/16;
  constexpr int PH = (K/2)*72;
  __shared__ __align__(16) float Bs[2*PH];
  int tid = threadIdx.x;
  {
    const float* src = in + (size_t)blockIdx.y*inStride2 + blockIdx.x*64;
    for (int i = tid; i < K*16; i += 128){
      int k = i >> 4, c4 = (i & 15)*4;
      float4 v = *(const float4*)(src + (size_t)k*rowLen2 + c4);
      float4 t = make_float4(tf32f(v.x), tf32f(v.y), tf32f(v.z), tf32f(v.w));
      *(float4*)(Bs + ((k>>2)&1)*PH + ((k>>3)*4 + (k&3))*72 + c4) = t;
    }
  }
  __syncthreads();
  int warp = tid>>5, lane = tid&31;
  int qid = lane>>2, rid = lane&3;
  int wcol = warp*16;
  float4 C[2][MT][2];
#pragma unroll
  for (int a=0;a<2;a++)
#pragma unroll
    for (int b=0;b<MT;b++)
#pragma unroll
      for (int c=0;c<2;c++) C[a][b][c] = make_float4(0.f,0.f,0.f,0.f);
#pragma unroll
  for (int kk=0; kk<KT; kk++){
    int sb = (kk*4 + rid)*72;
    float b00 = Bs[sb + wcol + qid];
    float b01 = Bs[PH + sb + wcol + qid];
    float b10 = Bs[sb + wcol + 8 + qid];
    float b11 = Bs[PH + sb + wcol + 8 + qid];
#pragma unroll
    for (int mm=0; mm<2; mm++){
#pragma unroll
      for (int mt=0; mt<MT; mt++){
        float4 af = __ldg(A4 + ((mm*KT+kk)*MT+mt)*32 + lane);
        mma8(C[mm][mt][0], af.x, af.y, af.z, af.w, b00, b01);
        mma8(C[mm][mt][1], af.x, af.y, af.z, af.w, b10, b11);
      }
    }
  }
  float* ob = out + (size_t)blockIdx.y*outStride2 + blockIdx.x*64;
#pragma unroll
  for (int mt=0; mt<MT; mt++){
#pragma unroll
    for (int nt=0; nt<2; nt++){
      float4 cr = C[0][mt][nt], ci = C[1][mt][nt];
      int col = wcol + nt*8 + rid*2;
      int m0 = mt*16 + qid;
      float2 v0, v1;
      if (SGN > 0){
        v0 = make_float2(cr.x + ci.y, cr.y - ci.x);
        v1 = make_float2(cr.z + ci.w, cr.w - ci.z);
      } else {
        v0 = make_float2(cr.x - ci.y, cr.y + ci.x);
        v1 = make_float2(cr.z - ci.w, cr.w + ci.z);
      }
      *(float2*)(ob + (size_t)m0*rowLen2 + col) = v0;
      *(float2*)(ob + (size_t)(m0+8)*rowLen2 + col) = v1;
    }
  }
}

// ---------------- K_mid: fwd-H + MLP + inv-H in place, quarter-split ----------------
// grid (1024 = w*32+l*4+cq, b=4), 128 thr, 32 complex channels (2 MLP blocks) per CTA.
// smem floats: sW[2048]@0 | sBias[144]@2048 | U[4608]@2192 | U2[2304]@6800 = 9104 fl = 36416 B
__global__ void __launch_bounds__(128,5) k_mid(){
  extern __shared__ float sm[];
  float* sW    = sm;
  float* sBias = sm + 2048;
  float* U     = sm + 2192;
  float* U2    = sm + 6800;
  const int PH1 = 2304;   // 32*72
  const int PH2 = 1152;   // 16*72
  int tid = threadIdx.x;
  int bx = blockIdx.x, b = blockIdx.y;
  int w = bx>>5, l = (bx>>2)&7, cq = bx&3;
  for (int i=tid; i<512; i+=128){
    int mg=i>>7, nb0=(i>>6)&1;
    ((float4*)sW)[i] = ((const float4*)g_W)[(mg*8+cq*2+nb0)*64 + (i&63)];
  }
  { int mg=tid>>5, nb0=(tid>>4)&1, o=tid&15;
    sBias[(mg*2+nb0)*17+o] = g_Bias[mg*128 + (cq*2+nb0)*16 + o]; }
  float2* gs = g_s2 + (size_t)b*2097152 + (size_t)w*1024 + l*128 + cq*32;
  for (int i=tid; i<2048; i+=128){
    int yy=i>>5, c2=i&31;
    float2 v = gs[(size_t)yy*32768 + c2];
    *(float2*)(U + ((yy>>2)&1)*PH1 + ((yy>>3)*4+(yy&3))*72 + 2*c2)
        = make_float2(tf32f(v.x), tf32f(v.y));
  }
  __syncthreads();
  int warp=tid>>5, lane=tid&31, qid=lane>>2, rid=lane&3;
  // GEMM1 fwd-H: M=32, K=64, N=64
  float4 C1[2][2][2];
#pragma unroll
  for (int a=0;a<2;a++)
#pragma unroll
    for (int m=0;m<2;m++)
#pragma unroll
      for (int n=0;n<2;n++) C1[a][m][n] = make_float4(0.f,0.f,0.f,0.f);
#pragma unroll
  for (int kk=0; kk<8; kk++){
    int sb = (kk*4+rid)*72;
    float b00 = U[sb + warp*16 + qid];
    float b01 = U[PH1 + sb + warp*16 + qid];
    float b10 = U[sb + warp*16 + 8 + qid];
    float b11 = U[PH1 + sb + warp*16 + 8 + qid];
#pragma unroll
    for (int mat=0; mat<2; mat++){
#pragma unroll
      for (int mt=0; mt<2; mt++){
        float4 af = __ldg(&g_A4W[((mat*8+kk)*2+mt)*32 + lane]);
        mma8(C1[mat][mt][0], af.x,af.y,af.z,af.w, b00, b01);
        mma8(C1[mat][mt][1], af.x,af.y,af.z,af.w, b10, b11);
      }
    }
  }
  __syncthreads();
  float2* sSpec = (float2*)U;   // 32 rows x stride 33 f2 = 2112 fl (< 4608)
#pragma unroll
  for (int mt=0; mt<2; mt++)
#pragma unroll
    for (int nt=0; nt<2; nt++){
      float4 cc = C1[0][mt][nt], cs = C1[1][mt][nt];
      int c2 = warp*8+nt*4+rid, h0 = mt*16+qid;
      sSpec[h0*33 + c2]     = make_float2(cc.x+cs.y, cc.y-cs.x);
      sSpec[(h0+8)*33 + c2] = make_float2(cc.z+cs.w, cc.w-cs.z);
    }
  __syncthreads();
  // MLP: 64 instances (nb0 in 0..1, h in 0..31), 2 threads each (half)
  {
    int inst=tid>>1, half=tid&1, nb0=inst>>5, h=inst&31;
    const float* W1R = sW + nb0*256;
    const float* W1I = sW + (2+nb0)*256;
    const float* W2R = sW + (4+nb0)*256;
    const float* W2I = sW + (6+nb0)*256;
    const float* Bb0 = sBias + nb0*17;
    const float* Bb1 = sBias + (2+nb0)*17;
    const float* Bb2 = sBias + (4+nb0)*17;
    const float* Bb3 = sBias + (6+nb0)*17;
    float xr[16], xi[16];
#pragma unroll
    for (int i=0;i<16;i++){ float2 v = sSpec[h*33 + nb0*16 + i]; xr[i]=v.x; xi[i]=v.y; }
    float pr[16], pi[16];
#pragma unroll
    for (int o=0;o<16;o++){ pr[o]=Bb0[o]; pi[o]=Bb1[o]; }
#pragma unroll
    for (int i=0;i<16;i++){
      float xrv = xr[i], xiv = xi[i];
#pragma unroll
      for (int o4=0;o4<4;o4++){
        float4 wr = *(const float4*)(W1R + i*16 + o4*4);
        float4 wi = *(const float4*)(W1I + i*16 + o4*4);
        pr[o4*4+0] += xrv*wr.x - xiv*wi.x;  pi[o4*4+0] += xiv*wr.x + xrv*wi.x;
        pr[o4*4+1] += xrv*wr.y - xiv*wi.y;  pi[o4*4+1] += xiv*wr.y + xrv*wi.y;
        pr[o4*4+2] += xrv*wr.z - xiv*wi.z;  pi[o4*4+2] += xiv*wr.z + xrv*wi.z;
        pr[o4*4+3] += xrv*wr.w - xiv*wi.w;  pi[o4*4+3] += xiv*wr.w + xrv*wi.w;
      }
    }
#pragma unroll
    for (int o=0;o<16;o++){ pr[o]=gelu_f(pr[o]); pi[o]=gelu_f(pi[o]); }
    float qr[8], qi[8];
#pragma unroll
    for (int oo=0;oo<8;oo++){ int o=half*8+oo; qr[oo]=Bb2[o]; qi[oo]=Bb3[o]; }
#pragma unroll
    for (int i=0;i<16;i++){
      float prv = pr[i], piv = pi[i];
#pragma unroll
      for (int o4=0;o4<2;o4++){
        float4 wr = *(const float4*)(W2R + i*16 + half*8 + o4*4);
        float4 wi = *(const float4*)(W2I + i*16 + half*8 + o4*4);
        qr[o4*4+0] += prv*wr.x - piv*wi.x;  qi[o4*4+0] += piv*wr.x + prv*wi.x;
        qr[o4*4+1] += prv*wr.y - piv*wi.y;  qi[o4*4+1] += piv*wr.y + prv*wi.y;
        qr[o4*4+2] += prv*wr.z - piv*wi.z;  qi[o4*4+2] += piv*wr.z + prv*wi.z;
        qr[o4*4+3] += prv*wr.w - piv*wi.w;  qi[o4*4+3] += piv*wr.w + prv*wi.w;
      }
    }
    float* d = U2 + ((h>>2)&1)*PH2 + ((h>>3)*4+(h&3))*72 + 2*(nb0*16+half*8);
#pragma unroll
    for (int j=0;j<4;j++){
      *(float4*)(d + 4*j) = make_float4(tf32f(qr[2*j]), tf32f(qi[2*j]),
                                        tf32f(qr[2*j+1]), tf32f(qi[2*j+1]));
    }
  }
  __syncthreads();
  // GEMM2 inv-H: M=64, K=32, N=64; 2 passes over M-halves to halve C registers
#pragma unroll
  for (int p=0; p<2; p++){
    float4 C3[2][2][2];
#pragma unroll
    for (int a=0;a<2;a++)
#pragma unroll
      for (int m=0;m<2;m++)
#pragma unroll
        for (int n=0;n<2;n++) C3[a][m][n] = make_float4(0.f,0.f,0.f,0.f);
#pragma unroll
    for (int kk=0; kk<4; kk++){
      int sb = (kk*4+rid)*72;
      float b00 = U2[sb + warp*16 + qid];
      float b01 = U2[PH2 + sb + warp*16 + qid];
      float b10 = U2[sb + warp*16 + 8 + qid];
      float b11 = U2[PH2 + sb + warp*16 + 8 + qid];
#pragma unroll
      for (int mat=0; mat<2; mat++){
#pragma unroll
        for (int mti=0; mti<2; mti++){
          int mt = p*2 + mti;
          float4 af = __ldg(&g_A4Wi[((mat*4+kk)*4+mt)*32 + lane]);
          mma8(C3[mat][mti][0], af.x,af.y,af.z,af.w, b00, b01);
          mma8(C3[mat][mti][1], af.x,af.y,af.z,af.w, b10, b11);
        }
      }
    }
#pragma unroll
    for (int mti=0; mti<2; mti++)
#pragma unroll
      for (int nt=0; nt<2; nt++){
        float4 cc = C3[0][mti][nt], cs = C3[1][mti][nt];
        int c2 = warp*8+nt*4+rid, y0 = (p*2+mti)*16+qid;
        gs[(size_t)y0*32768 + c2]     = make_float2(cc.x-cs.y, cc.y+cs.x);
        gs[(size_t)(y0+8)*32768 + c2] = make_float2(cc.z-cs.w, cc.w+cs.z);
      }
  }
}

// ---------------- K7: inverse rfft over L (radix-2, channel-pair) + residual ----------------
__global__ void k_inv_l(const float* __restrict__ xin, float* __restrict__ out){
  __shared__ float2 tw[32];
  if (threadIdx.x < 32) tw[threadIdx.x] = TW32[threadIdx.x];
  __syncthreads();
  int site = blockIdx.x;
  int c = threadIdx.x;            // 0..63 channel pair
  const float4* ip = (const float4*)(g_s3 + (size_t)site*1024) + c;
  float2 Xr[8], Xi[8];
#pragma unroll
  for (int l=0;l<8;l++){
    float4 v = ip[l*64];
    Xr[l] = make_float2(v.x, v.z);
    Xi[l] = make_float2(v.y, v.w);
  }
#pragma unroll
  for (int l=1;l<8;l++){ Xr[l].x*=2.f; Xr[l].y*=2.f; Xi[l].x*=2.f; Xi[l].y*=2.f; }
  const float s = 0.1767766952966369f;
  const float2* rp = (const float2*)(xin + (size_t)site*4096) + c;
  float2* op = (float2*)(out + (size_t)site*4096) + c;
#pragma unroll
  for (int t=0;t<16;t++){
    float2 E = Xr[0];
    float2 O = make_float2(0.f,0.f);
#pragma unroll
    for (int j=1;j<4;j++){
      float2 we = tw[(2*j*t)&31];
      E.x += Xr[2*j].x*we.x - Xi[2*j].x*we.y;
      E.y += Xr[2*j].y*we.x - Xi[2*j].y*we.y;
    }
#pragma unroll
    for (int j=0;j<4;j++){
      float2 wo = tw[((2*j+1)*t)&31];
      O.x += Xr[2*j+1].x*wo.x - Xi[2*j+1].x*wo.y;
      O.y += Xr[2*j+1].y*wo.x - Xi[2*j+1].y*wo.y;
    }
    float2 r0 = rp[t*64], r1 = rp[(t+16)*64];
    op[t*64]      = make_float2(fmaf(E.x+O.x, s, r0.x), fmaf(E.y+O.y, s, r0.y));
    op[(t+16)*64] = make_float2(fmaf(E.x-O.x, s, r1.x), fmaf(E.y-O.y, s, r1.y));
  }
}

// ---------------- launch ----------------
extern "C" void kernel_launch(void* const* d_in, const int* in_sizes, int n_in,
                              void* d_out, int out_size){
  (void)in_sizes; (void)n_in; (void)out_size;
  const float* x = (const float*)d_in[0];
  void *ps3, *ps2, *paw, *pawi;
  cudaGetSymbolAddress(&ps3,  g_s3);
  cudaGetSymbolAddress(&ps2,  g_s2);
  cudaGetSymbolAddress(&paw,  g_A4W);
  cudaGetSymbolAddress(&pawi, g_A4Wi);
  const float* s3 = (const float*)ps3;
  const float* s2 = (const float*)ps2;
  const float4* aw  = (const float4*)paw;
  const float4* awi = (const float4*)pawi;
  cudaFuncSetAttribute(k_mid, cudaFuncAttributeMaxDynamicSharedMemorySize, 36416);

  k_prep<<<8,256>>>((const float*)d_in[1], (const float*)d_in[2], (const float*)d_in[3],
                    (const float*)d_in[4], (const float*)d_in[5], (const float*)d_in[6],
                    (const float*)d_in[7], (const float*)d_in[8], (const float*)d_in[9],
                    (const float*)d_in[10], (const float*)d_in[11], (const float*)d_in[12],
                    (const float*)d_in[13]);
  k_init4<<<8,256>>>();
  k_fwd_l<<<16384,64>>>(x);
  // fwd W: Out[32][1024c] = T @ In[64][1024c], 256 (b,y) batches
  k_dft_mma<32,64, 1,8><<<dim3(32,256),128>>>(s3, (float*)s2, aw, 2048, 131072, 65536);
  // fwd H + MLP + inv H, in place on g_s2
  k_mid<<<dim3(1024,4),128,36416>>>();
  // inv W: Out[64][1024c] = T @ In[32][1024c]
  k_dft_mma<64,32,-1,6><<<dim3(32,256),128>>>(s2, (float*)s3, awi, 2048, 65536, 131072);
  k_inv_l<<<16384,64>>>(x, (float*)d_out);
}

// round 10
// speedup vs baseline: 1.0131x; 1.0131x over previous
#include <cuda_runtime.h>
#include <math.h>

// ---------------- scratch ----------------
__device__ __align__(16) float2 g_s3[16777216];  // [4][64][64][8][128] fwd-L out / inv-W out
__device__ __align__(16) float2 g_s2[8388608];   // [4][64][32][8][128] workspace (k_mid in-place)
__device__ __align__(16) float  g_W[8192];       // [4 mats][8 blk][16][16] folded MLP weights
__device__ __align__(16) float  g_Bias[512];     // [4][8][16] folded biases
// per-lane packed tf32 mma A-fragments: idx = ((mat*KT+kk)*MT+mt)*32+lane
__device__ __align__(16) float4 g_A4W[1024];     // fwd W/H: M=32,K=64 (cos|sin), 1/8 baked
__device__ __align__(16) float4 g_A4Wi[1024];    // inv W/H: M=64,K=32 (cos|sin), 1/8 baked

__constant__ float2 TW32[32] = {
  { 1.000000000f, 0.000000000f},{ 0.980785280f, 0.195090322f},{ 0.923879533f, 0.382683432f},{ 0.831469612f, 0.555570233f},
  { 0.707106781f, 0.707106781f},{ 0.555570233f, 0.831469612f},{ 0.382683432f, 0.923879533f},{ 0.195090322f, 0.980785280f},
  { 0.000000000f, 1.000000000f},{-0.195090322f, 0.980785280f},{-0.382683432f, 0.923879533f},{-0.555570233f, 0.831469612f},
  {-0.707106781f, 0.707106781f},{-0.831469612f, 0.555570233f},{-0.923879533f, 0.382683432f},{-0.980785280f, 0.195090322f},
  {-1.000000000f, 0.000000000f},{-0.980785280f,-0.195090322f},{-0.923879533f,-0.382683432f},{-0.831469612f,-0.555570233f},
  {-0.707106781f,-0.707106781f},{-0.555570233f,-0.831469612f},{-0.382683432f,-0.923879533f},{-0.195090322f,-0.980785280f},
  { 0.000000000f,-1.000000000f},{ 0.195090322f,-0.980785280f},{ 0.382683432f,-0.923879533f},{ 0.555570233f,-0.831469612f},
  { 0.707106781f,-0.707106781f},{ 0.831469612f,-0.555570233f},{ 0.923879533f,-0.382683432f},{ 0.980785280f,-0.195090322f}
};

__device__ __forceinline__ float gelu_f(float v){
  return 0.5f*v*(1.0f+erff(v*0.7071067811865476f));
}
__device__ __forceinline__ float tf32f(float f){
  unsigned u; asm("cvt.rna.tf32.f32 %0, %1;" : "=r"(u) : "f"(f));
  return __uint_as_float(u);
}
__device__ __forceinline__ void mma8(float4& d, float a0, float a1, float a2, float a3,
                                     float b0, float b1){
  asm volatile("mma.sync.aligned.m16n8k8.row.col.f32.tf32.tf32.f32 "
    "{%0,%1,%2,%3}, {%4,%5,%6,%7}, {%8,%9}, {%0,%1,%2,%3};"
    : "+f"(d.x), "+f"(d.y), "+f"(d.z), "+f"(d.w)
    : "r"(__float_as_uint(a0)), "r"(__float_as_uint(a1)),
      "r"(__float_as_uint(a2)), "r"(__float_as_uint(a3)),
      "r"(__float_as_uint(b0)), "r"(__float_as_uint(b1)));
}

// ---------------- K0a: build packed twiddle fragments ----------------
__device__ __forceinline__ float twval(int mat, int m, int k){
  double a = (double)(m*k)/32.0;
  return tf32f((float)((mat ? sinpi(a) : cospi(a))*0.125));
}
__global__ void k_init4(){
  int e = blockIdx.x*256 + threadIdx.x;   // 0..2047
  int lane = e&31, qid = lane>>2, rid = lane&3;
  int which = e>>10, j = e&1023;
  if (which==0){                           // fwd: MT=2, KT=8
    int mt=(j>>5)&1, kk=(j>>6)&7, mat=j>>9;
    int r0=mt*16+qid, r1=r0+8, k0=kk*8+rid, k1=k0+4;
    g_A4W[j] = make_float4(twval(mat,r0,k0), twval(mat,r1,k0),
                           twval(mat,r0,k1), twval(mat,r1,k1));
  } else {                                 // inv: MT=4, KT=4
    int mt=(j>>5)&3, kk=(j>>7)&3, mat=j>>9;
    int r0=mt*16+qid, r1=r0+8, k0=kk*8+rid, k1=k0+4;
    g_A4Wi[j] = make_float4(twval(mat,r0,k0), twval(mat,r1,k0),
                            twval(mat,r0,k1), twval(mat,r1,k1));
  }
}

// ---------------- K0: fold HydraLoRA ----------------
__global__ void k_prep(const float* __restrict__ w1, const float* __restrict__ b1,
                       const float* __restrict__ w2, const float* __restrict__ b2,
                       const float* __restrict__ A1r, const float* __restrict__ B1r,
                       const float* __restrict__ A1i, const float* __restrict__ B1i,
                       const float* __restrict__ A2r, const float* __restrict__ B2r,
                       const float* __restrict__ A2i, const float* __restrict__ B2i,
                       const float* __restrict__ ew){
  int k  = blockIdx.x;
  int io = threadIdx.x;
  int i = io >> 4, o = io & 15;
  float e0 = ew[0], e1 = ew[1], e2 = ew[2], e3 = ew[3];
  const float s = 0.03125f;
  const float* Ws[4] = { w1 + k*256, w1 + 2048 + k*256, w2 + k*256, w2 + 2048 + k*256 };
  const float* As[4] = { A1r + k*512, A1i + k*512, A2r + k*512, A2i + k*512 };
  const float* Bs[4] = { B1r + k*2048, B1i + k*2048, B2r + k*2048, B2i + k*2048 };
#pragma unroll
  for (int m = 0; m < 4; m++){
    const float* A  = As[m] + i*32;
    const float* Bb = Bs[m];
    float acc = 0.f;
    for (int r = 0; r < 32; r++){
      float bm = e0*Bb[r*16+o] + e1*Bb[512+r*16+o] + e2*Bb[1024+r*16+o] + e3*Bb[1536+r*16+o];
      acc = fmaf(A[r], bm, acc);
    }
    g_W[((m*8+k)*16+i)*16+o] = Ws[m][i*16+o] + s*acc;
  }
  if (io < 16){
    float b10 = b1[k*16+io], b11 = b1[128+k*16+io];
    float b20 = b2[k*16+io], b21 = b2[128+k*16+io];
    g_Bias[      k*16+io] = b10 - b11;
    g_Bias[128 + k*16+io] = b10 + b11;
    g_Bias[256 + k*16+io] = b20 - b21;
    g_Bias[384 + k*16+io] = b20 + b21;
  }
}

// ---------------- K1: forward rfft over L (radix-2, channel-pair, 2 sites/CTA) ----------------
__global__ void __launch_bounds__(128) k_fwd_l(const float* __restrict__ x){
  __shared__ float2 tw[32];
  if (threadIdx.x < 32) tw[threadIdx.x] = TW32[threadIdx.x];
  __syncthreads();
  int site = blockIdx.x*2 + (threadIdx.x>>6);   // b*4096 + y*64 + xx
  int c = threadIdx.x & 63;                     // channel pair
  const float2* xp = (const float2*)(x + (size_t)site*4096) + c;
  float2 u[16], dd[16];
#pragma unroll
  for (int t=0;t<16;t++){
    float2 a = xp[t*64], b2 = xp[(t+16)*64];
    u[t]  = make_float2(a.x+b2.x, a.y+b2.y);
    dd[t] = make_float2(a.x-b2.x, a.y-b2.y);
  }
  float2 ar[8], ai[8];
#pragma unroll
  for (int l=0;l<8;l++){ ar[l]=make_float2(0.f,0.f); ai[l]=make_float2(0.f,0.f); }
#pragma unroll
  for (int t=0;t<16;t++){
#pragma unroll
    for (int j=0;j<4;j++){
      float2 we = tw[(t*2*j)&31];
      ar[2*j].x = fmaf( u[t].x, we.x, ar[2*j].x);
      ar[2*j].y = fmaf( u[t].y, we.x, ar[2*j].y);
      ai[2*j].x = fmaf(-u[t].x, we.y, ai[2*j].x);
      ai[2*j].y = fmaf(-u[t].y, we.y, ai[2*j].y);
      float2 wo = tw[(t*(2*j+1))&31];
      ar[2*j+1].x = fmaf( dd[t].x, wo.x, ar[2*j+1].x);
      ar[2*j+1].y = fmaf( dd[t].y, wo.x, ar[2*j+1].y);
      ai[2*j+1].x = fmaf(-dd[t].x, wo.y, ai[2*j+1].x);
      ai[2*j+1].y = fmaf(-dd[t].y, wo.y, ai[2*j+1].y);
    }
  }
  const float s = 0.1767766952966369f;
  float4* op = (float4*)(g_s3 + (size_t)site*1024) + c;
#pragma unroll
  for (int l=0;l<8;l++)
    op[l*64] = make_float4(ar[l].x*s, ai[l].x*s, ar[l].y*s, ai[l].y*s);
}

// ---------------- complex DFT GEMM stage (pair-split B layout) ----------------
template<int M, int K, int SGN, int MINB>
__global__ void __launch_bounds__(128, MINB) k_dft_mma(const float* __restrict__ in,
                                                 float* __restrict__ out,
                                                 const float4* __restrict__ A4,
                                                 int rowLen2, size_t inStride2,
                                                 size_t outStride2){
  constexpr int KT = K/8;
  constexpr int MT = M/16;
  constexpr int PH = (K/2)*72;
  __shared__ __align__(16) float Bs[2*PH];
  int tid = threadIdx.x;
  {
    const float* src = in + (size_t)blockIdx.y*inStride2 + blockIdx.x*64;
    for (int i = tid; i < K*16; i += 128){
      int k = i >> 4, c4 = (i & 15)*4;
      float4 v = *(const float4*)(src + (size_t)k*rowLen2 + c4);
      float4 t = make_float4(tf32f(v.x), tf32f(v.y), tf32f(v.z), tf32f(v.w));
      *(float4*)(Bs + ((k>>2)&1)*PH + ((k>>3)*4 + (k&3))*72 + c4) = t;
    }
  }
  __syncthreads();
  int warp = tid>>5, lane = tid&31;
  int qid = lane>>2, rid = lane&3;
  int wcol = warp*16;
  float4 C[2][MT][2];
#pragma unroll
  for (int a=0;a<2;a++)
#pragma unroll
    for (int b=0;b<MT;b++)
#pragma unroll
      for (int c=0;c<2;c++) C[a][b][c] = make_float4(0.f,0.f,0.f,0.f);
#pragma unroll
  for (int kk=0; kk<KT; kk++){
    int sb = (kk*4 + rid)*72;
    float b00 = Bs[sb + wcol + qid];
    float b01 = Bs[PH + sb + wcol + qid];
    float b10 = Bs[sb + wcol + 8 + qid];
    float b11 = Bs[PH + sb + wcol + 8 + qid];
#pragma unroll
    for (int mm=0; mm<2; mm++){
#pragma unroll
      for (int mt=0; mt<MT; mt++){
        float4 af = __ldg(A4 + ((mm*KT+kk)*MT+mt)*32 + lane);
        mma8(C[mm][mt][0], af.x, af.y, af.z, af.w, b00, b01);
        mma8(C[mm][mt][1], af.x, af.y, af.z, af.w, b10, b11);
      }
    }
  }
  float* ob = out + (size_t)blockIdx.y*outStride2 + blockIdx.x*64;
#pragma unroll
  for (int mt=0; mt<MT; mt++){
#pragma unroll
    for (int nt=0; nt<2; nt++){
      float4 cr = C[0][mt][nt], ci = C[1][mt][nt];
      int col = wcol + nt*8 + rid*2;
      int m0 = mt*16 + qid;
      float2 v0, v1;
      if (SGN > 0){
        v0 = make_float2(cr.x + ci.y, cr.y - ci.x);
        v1 = make_float2(cr.z + ci.w, cr.w - ci.z);
      } else {
        v0 = make_float2(cr.x - ci.y, cr.y + ci.x);
        v1 = make_float2(cr.z - ci.w, cr.w + ci.z);
      }
      *(float2*)(ob + (size_t)m0*rowLen2 + col) = v0;
      *(float2*)(ob + (size_t)(m0+8)*rowLen2 + col) = v1;
    }
  }
}

// ---------------- K_mid: fwd-H + MLP + inv-H in place (R8 256-thread version) ----------------
// smem floats: sW[4096]@0 | sBias[272]@4096 | U[8704]@4368 | U2[4352]@13072 = 69696 B
__global__ void __launch_bounds__(256,3) k_mid(){
  extern __shared__ float sm[];
  float* sW    = sm;
  float* sBias = sm + 4096;
  float* U     = sm + 4368;
  float* U2    = sm + 13072;
  const int PH1 = 4352;   // 32*136
  const int PH2 = 2176;   // 16*136
  int tid = threadIdx.x;
  int bx = blockIdx.x, b = blockIdx.y;
  int w = bx>>4, l = (bx>>1)&7, chalf = bx&1;
  for (int i=tid; i<1024; i+=256){
    int mg=i>>8, nb0=(i>>6)&3;
    ((float4*)sW)[i] = ((const float4*)g_W)[(mg*8+chalf*4+nb0)*64 + (i&63)];
  }
  { int mg=tid>>6, nb0=(tid>>4)&3, o=tid&15;
    sBias[(mg*4+nb0)*17+o] = g_Bias[mg*128 + (chalf*4+nb0)*16 + o]; }
  float2* gs = g_s2 + (size_t)b*2097152 + (size_t)w*1024 + l*128 + chalf*64;
  for (int i=tid; i<4096; i+=256){
    int yy=i>>6, c2=i&63;
    float2 v = gs[(size_t)yy*32768 + c2];
    float* d = U + ((yy>>2)&1)*PH1 + ((yy>>3)*4+(yy&3))*136 + 2*c2;
    *(float2*)d = make_float2(tf32f(v.x), tf32f(v.y));
  }
  __syncthreads();
  int warp=tid>>5, lane=tid&31, qid=lane>>2, rid=lane&3;
  // GEMM1 fwd-H: M=32,K=64,N=128
  float4 C1[2][2][2];
#pragma unroll
  for (int a=0;a<2;a++)
#pragma unroll
    for (int m=0;m<2;m++)
#pragma unroll
      for (int n=0;n<2;n++) C1[a][m][n] = make_float4(0.f,0.f,0.f,0.f);
#pragma unroll
  for (int kk=0; kk<8; kk++){
    int sb = (kk*4+rid)*136;
    float b00 = U[sb + warp*16 + qid];
    float b01 = U[PH1 + sb + warp*16 + qid];
    float b10 = U[sb + warp*16 + 8 + qid];
    float b11 = U[PH1 + sb + warp*16 + 8 + qid];
#pragma unroll
    for (int mat=0; mat<2; mat++){
#pragma unroll
      for (int mt=0; mt<2; mt++){
        float4 af = __ldg(&g_A4W[((mat*8+kk)*2+mt)*32 + lane]);
        mma8(C1[mat][mt][0], af.x,af.y,af.z,af.w, b00, b01);
        mma8(C1[mat][mt][1], af.x,af.y,af.z,af.w, b10, b11);
      }
    }
  }
  __syncthreads();
  float2* sSpec = (float2*)U;   // stride 65 f2
#pragma unroll
  for (int mt=0; mt<2; mt++)
#pragma unroll
    for (int nt=0; nt<2; nt++){
      float4 cc = C1[0][mt][nt], cs = C1[1][mt][nt];
      int c2 = warp*8+nt*4+rid, h0 = mt*16+qid;
      sSpec[h0*65 + c2]     = make_float2(cc.x+cs.y, cc.y-cs.x);
      sSpec[(h0+8)*65 + c2] = make_float2(cc.z+cs.w, cc.w-cs.z);
    }
  __syncthreads();
  // MLP: inst=(nb0,h), 2 threads each (half)
  {
    int inst=tid>>1, half=tid&1, nb0=inst>>5, h=inst&31;
    const float* W1R = sW + nb0*256;
    const float* W1I = sW + (4+nb0)*256;
    const float* W2R = sW + (8+nb0)*256;
    const float* W2I = sW + (12+nb0)*256;
    const float* Bb0 = sBias + nb0*17;
    const float* Bb1 = sBias + (4+nb0)*17;
    const float* Bb2 = sBias + (8+nb0)*17;
    const float* Bb3 = sBias + (12+nb0)*17;
    float xr[16], xi[16];
#pragma unroll
    for (int i=0;i<16;i++){ float2 v = sSpec[h*65 + nb0*16 + i]; xr[i]=v.x; xi[i]=v.y; }
    float pr[16], pi[16];
#pragma unroll
    for (int o=0;o<16;o++){ pr[o]=Bb0[o]; pi[o]=Bb1[o]; }
#pragma unroll
    for (int i=0;i<16;i++){
      float xrv = xr[i], xiv = xi[i];
#pragma unroll
      for (int o4=0;o4<4;o4++){
        float4 wr = *(const float4*)(W1R + i*16 + o4*4);
        float4 wi = *(const float4*)(W1I + i*16 + o4*4);
        pr[o4*4+0] += xrv*wr.x - xiv*wi.x;  pi[o4*4+0] += xiv*wr.x + xrv*wi.x;
        pr[o4*4+1] += xrv*wr.y - xiv*wi.y;  pi[o4*4+1] += xiv*wr.y + xrv*wi.y;
        pr[o4*4+2] += xrv*wr.z - xiv*wi.z;  pi[o4*4+2] += xiv*wr.z + xrv*wi.z;
        pr[o4*4+3] += xrv*wr.w - xiv*wi.w;  pi[o4*4+3] += xiv*wr.w + xrv*wi.w;
      }
    }
#pragma unroll
    for (int o=0;o<16;o++){ pr[o]=gelu_f(pr[o]); pi[o]=gelu_f(pi[o]); }
    float qr[8], qi[8];
#pragma unroll
    for (int oo=0;oo<8;oo++){ int o=half*8+oo; qr[oo]=Bb2[o]; qi[oo]=Bb3[o]; }
#pragma unroll
    for (int i=0;i<16;i++){
      float prv = pr[i], piv = pi[i];
#pragma unroll
      for (int o4=0;o4<2;o4++){
        float4 wr = *(const float4*)(W2R + i*16 + half*8 + o4*4);
        float4 wi = *(const float4*)(W2I + i*16 + half*8 + o4*4);
        qr[o4*4+0] += prv*wr.x - piv*wi.x;  qi[o4*4+0] += piv*wr.x + prv*wi.x;
        qr[o4*4+1] += prv*wr.y - piv*wi.y;  qi[o4*4+1] += piv*wr.y + prv*wi.y;
        qr[o4*4+2] += prv*wr.z - piv*wi.z;  qi[o4*4+2] += piv*wr.z + prv*wi.z;
        qr[o4*4+3] += prv*wr.w - piv*wi.w;  qi[o4*4+3] += piv*wr.w + prv*wi.w;
      }
    }
    float* d = U2 + ((h>>2)&1)*PH2 + ((h>>3)*4+(h&3))*136 + 2*(nb0*16+half*8);
#pragma unroll
    for (int j=0;j<4;j++){
      *(float4*)(d + 4*j) = make_float4(tf32f(qr[2*j]), tf32f(qi[2*j]),
                                        tf32f(qr[2*j+1]), tf32f(qi[2*j+1]));
    }
  }
  __syncthreads();
  // GEMM2 inv-H: M=64,K=32,N=128
  float4 C3[2][4][2];
#pragma unroll
  for (int a=0;a<2;a++)
#pragma unroll
    for (int m=0;m<4;m++)
#pragma unroll
      for (int n=0;n<2;n++) C3[a][m][n] = make_float4(0.f,0.f,0.f,0.f);
#pragma unroll
  for (int kk=0; kk<4; kk++){
    int sb = (kk*4+rid)*136;
    float b00 = U2[sb + warp*16 + qid];
    float b01 = U2[PH2 + sb + warp*16 + qid];
    float b10 = U2[sb + warp*16 + 8 + qid];
    float b11 = U2[PH2 + sb + warp*16 + 8 + qid];
#pragma unroll
    for (int mat=0; mat<2; mat++){
#pragma unroll
      for (int mt=0; mt<4; mt++){
        float4 af = __ldg(&g_A4Wi[((mat*4+kk)*4+mt)*32 + lane]);
        mma8(C3[mat][mt][0], af.x,af.y,af.z,af.w, b00, b01);
        mma8(C3[mat][mt][1], af.x,af.y,af.z,af.w, b10, b11);
      }
    }
  }
#pragma unroll
  for (int mt=0; mt<4; mt++)
#pragma unroll
    for (int nt=0; nt<2; nt++){
      float4 cc = C3[0][mt][nt], cs = C3[1][mt][nt];
      int c2 = warp*8+nt*4+rid, y0 = mt*16+qid;
      gs[(size_t)y0*32768 + c2]     = make_float2(cc.x-cs.y, cc.y+cs.x);
      gs[(size_t)(y0+8)*32768 + c2] = make_float2(cc.z-cs.w, cc.w+cs.z);
    }
}

// ---------------- K7: inverse rfft over L (radix-2, channel-pair, 2 sites/CTA) + residual ----------------
__global__ void __launch_bounds__(128) k_inv_l(const float* __restrict__ xin, float* __restrict__ out){
  __shared__ float2 tw[32];
  if (threadIdx.x < 32) tw[threadIdx.x] = TW32[threadIdx.x];
  __syncthreads();
  int site = blockIdx.x*2 + (threadIdx.x>>6);
  int c = threadIdx.x & 63;       // channel pair
  const float4* ip = (const float4*)(g_s3 + (size_t)site*1024) + c;
  float2 Xr[8], Xi[8];
#pragma unroll
  for (int l=0;l<8;l++){
    float4 v = ip[l*64];
    Xr[l] = make_float2(v.x, v.z);
    Xi[l] = make_float2(v.y, v.w);
  }
#pragma unroll
  for (int l=1;l<8;l++){ Xr[l].x*=2.f; Xr[l].y*=2.f; Xi[l].x*=2.f; Xi[l].y*=2.f; }
  const float s = 0.1767766952966369f;
  const float2* rp = (const float2*)(xin + (size_t)site*4096) + c;
  float2* op = (float2*)(out + (size_t)site*4096) + c;
#pragma unroll
  for (int t=0;t<16;t++){
    float2 E = Xr[0];
    float2 O = make_float2(0.f,0.f);
#pragma unroll
    for (int j=1;j<4;j++){
      float2 we = tw[(2*j*t)&31];
      E.x += Xr[2*j].x*we.x - Xi[2*j].x*we.y;
      E.y += Xr[2*j].y*we.x - Xi[2*j].y*we.y;
    }
#pragma unroll
    for (int j=0;j<4;j++){
      float2 wo = tw[((2*j+1)*t)&31];
      O.x += Xr[2*j+1].x*wo.x - Xi[2*j+1].x*wo.y;
      O.y += Xr[2*j+1].y*wo.x - Xi[2*j+1].y*wo.y;
    }
    float2 r0 = rp[t*64], r1 = rp[(t+16)*64];
    op[t*64]      = make_float2(fmaf(E.x+O.x, s, r0.x), fmaf(E.y+O.y, s, r0.y));
    op[(t+16)*64] = make_float2(fmaf(E.x-O.x, s, r1.x), fmaf(E.y-O.y, s, r1.y));
  }
}

// ---------------- launch ----------------
extern "C" void kernel_launch(void* const* d_in, const int* in_sizes, int n_in,
                              void* d_out, int out_size){
  (void)in_sizes; (void)n_in; (void)out_size;
  const float* x = (const float*)d_in[0];
  void *ps3, *ps2, *paw, *pawi;
  cudaGetSymbolAddress(&ps3,  g_s3);
  cudaGetSymbolAddress(&ps2,  g_s2);
  cudaGetSymbolAddress(&paw,  g_A4W);
  cudaGetSymbolAddress(&pawi, g_A4Wi);
  const float* s3 = (const float*)ps3;
  const float* s2 = (const float*)ps2;
  const float4* aw  = (const float4*)paw;
  const float4* awi = (const float4*)pawi;
  cudaFuncSetAttribute(k_mid, cudaFuncAttributeMaxDynamicSharedMemorySize, 69696);

  k_prep<<<8,256>>>((const float*)d_in[1], (const float*)d_in[2], (const float*)d_in[3],
                    (const float*)d_in[4], (const float*)d_in[5], (const float*)d_in[6],
                    (const float*)d_in[7], (const float*)d_in[8], (const float*)d_in[9],
                    (const float*)d_in[10], (const float*)d_in[11], (const float*)d_in[12],
                    (const float*)d_in[13]);
  k_init4<<<8,256>>>();
  k_fwd_l<<<8192,128>>>(x);
  // fwd W: Out[32][1024c] = T @ In[64][1024c], 256 (b,y) batches
  k_dft_mma<32,64, 1,8><<<dim3(32,256),128>>>(s3, (float*)s2, aw, 2048, 131072, 65536);
  // fwd H + MLP + inv H, in place on g_s2
  k_mid<<<dim3(512,4),256,69696>>>();
  // inv W: Out[64][1024c] = T @ In[32][1024c]
  k_dft_mma<64,32,-1,6><<<dim3(32,256),128>>>(s2, (float*)s3, awi, 2048, 65536, 131072);
  k_inv_l<<<8192,128>>>(x, (float*)d_out);
}

// round 11
// speedup vs baseline: 1.1165x; 1.1021x over previous
#include <cuda_runtime.h>
#include <cuda_bf16.h>
#include <math.h>

// ---------------- scratch (bf16x2 complex intermediates) ----------------
__device__ __align__(16) unsigned g_s3h[16777216]; // [4][64][64][8][128] complexes (bf16 re,im)
__device__ __align__(16) unsigned g_s2h[8388608];  // [4][64][32][8][128] complexes
__device__ __align__(16) float  g_W[8192];
__device__ __align__(16) float  g_Bias[512];
__device__ __align__(16) float4 g_A4W[1024];       // fwd W/H tf32 fragments, 1/8 baked
__device__ __align__(16) float4 g_A4Wi[1024];      // inv W/H

__constant__ float2 TW32[32] = {
  { 1.000000000f, 0.000000000f},{ 0.980785280f, 0.195090322f},{ 0.923879533f, 0.382683432f},{ 0.831469612f, 0.555570233f},
  { 0.707106781f, 0.707106781f},{ 0.555570233f, 0.831469612f},{ 0.382683432f, 0.923879533f},{ 0.195090322f, 0.980785280f},
  { 0.000000000f, 1.000000000f},{-0.195090322f, 0.980785280f},{-0.382683432f, 0.923879533f},{-0.555570233f, 0.831469612f},
  {-0.707106781f, 0.707106781f},{-0.831469612f, 0.555570233f},{-0.923879533f, 0.382683432f},{-0.980785280f, 0.195090322f},
  {-1.000000000f, 0.000000000f},{-0.980785280f,-0.195090322f},{-0.923879533f,-0.382683432f},{-0.831469612f,-0.555570233f},
  {-0.707106781f,-0.707106781f},{-0.555570233f,-0.831469612f},{-0.382683432f,-0.923879533f},{-0.195090322f,-0.980785280f},
  { 0.000000000f,-1.000000000f},{ 0.195090322f,-0.980785280f},{ 0.382683432f,-0.923879533f},{ 0.555570233f,-0.831469612f},
  { 0.707106781f,-0.707106781f},{ 0.831469612f,-0.555570233f},{ 0.923879533f,-0.382683432f},{ 0.980785280f,-0.195090322f}
};

__device__ __forceinline__ float gelu_f(float v){
  return 0.5f*v*(1.0f+erff(v*0.7071067811865476f));
}
__device__ __forceinline__ float tf32f(float f){
  unsigned u; asm("cvt.rna.tf32.f32 %0, %1;" : "=r"(u) : "f"(f));
  return __uint_as_float(u);
}
__device__ __forceinline__ unsigned bf2(float a, float b){
  __nv_bfloat162 h = __floats2bfloat162_rn(a, b);
  return *reinterpret_cast<unsigned*>(&h);
}
__device__ __forceinline__ float2 unbf2(unsigned u){
  __nv_bfloat162 h = *reinterpret_cast<__nv_bfloat162*>(&u);
  return __bfloat1622float2(h);
}
__device__ __forceinline__ void mma8(float4& d, float a0, float a1, float a2, float a3,
                                     float b0, float b1){
  asm volatile("mma.sync.aligned.m16n8k8.row.col.f32.tf32.tf32.f32 "
    "{%0,%1,%2,%3}, {%4,%5,%6,%7}, {%8,%9}, {%0,%1,%2,%3};"
    : "+f"(d.x), "+f"(d.y), "+f"(d.z), "+f"(d.w)
    : "r"(__float_as_uint(a0)), "r"(__float_as_uint(a1)),
      "r"(__float_as_uint(a2)), "r"(__float_as_uint(a3)),
      "r"(__float_as_uint(b0)), "r"(__float_as_uint(b1)));
}

// ---------------- K0a: build packed twiddle fragments ----------------
__device__ __forceinline__ float twval(int mat, int m, int k){
  double a = (double)(m*k)/32.0;
  return tf32f((float)((mat ? sinpi(a) : cospi(a))*0.125));
}
__global__ void k_init4(){
  int e = blockIdx.x*256 + threadIdx.x;   // 0..2047
  int lane = e&31, qid = lane>>2, rid = lane&3;
  int which = e>>10, j = e&1023;
  if (which==0){                           // fwd: MT=2, KT=8
    int mt=(j>>5)&1, kk=(j>>6)&7, mat=j>>9;
    int r0=mt*16+qid, r1=r0+8, k0=kk*8+rid, k1=k0+4;
    g_A4W[j] = make_float4(twval(mat,r0,k0), twval(mat,r1,k0),
                           twval(mat,r0,k1), twval(mat,r1,k1));
  } else {                                 // inv: MT=4, KT=4
    int mt=(j>>5)&3, kk=(j>>7)&3, mat=j>>9;
    int r0=mt*16+qid, r1=r0+8, k0=kk*8+rid, k1=k0+4;
    g_A4Wi[j] = make_float4(twval(mat,r0,k0), twval(mat,r1,k0),
                            twval(mat,r0,k1), twval(mat,r1,k1));
  }
}

// ---------------- K0: fold HydraLoRA ----------------
__global__ void k_prep(const float* __restrict__ w1, const float* __restrict__ b1,
                       const float* __restrict__ w2, const float* __restrict__ b2,
                       const float* __restrict__ A1r, const float* __restrict__ B1r,
                       const float* __restrict__ A1i, const float* __restrict__ B1i,
                       const float* __restrict__ A2r, const float* __restrict__ B2r,
                       const float* __restrict__ A2i, const float* __restrict__ B2i,
                       const float* __restrict__ ew){
  int k  = blockIdx.x;
  int io = threadIdx.x;
  int i = io >> 4, o = io & 15;
  float e0 = ew[0], e1 = ew[1], e2 = ew[2], e3 = ew[3];
  const float s = 0.03125f;
  const float* Ws[4] = { w1 + k*256, w1 + 2048 + k*256, w2 + k*256, w2 + 2048 + k*256 };
  const float* As[4] = { A1r + k*512, A1i + k*512, A2r + k*512, A2i + k*512 };
  const float* Bs[4] = { B1r + k*2048, B1i + k*2048, B2r + k*2048, B2i + k*2048 };
#pragma unroll
  for (int m = 0; m < 4; m++){
    const float* A  = As[m] + i*32;
    const float* Bb = Bs[m];
    float acc = 0.f;
    for (int r = 0; r < 32; r++){
      float bm = e0*Bb[r*16+o] + e1*Bb[512+r*16+o] + e2*Bb[1024+r*16+o] + e3*Bb[1536+r*16+o];
      acc = fmaf(A[r], bm, acc);
    }
    g_W[((m*8+k)*16+i)*16+o] = Ws[m][i*16+o] + s*acc;
  }
  if (io < 16){
    float b10 = b1[k*16+io], b11 = b1[128+k*16+io];
    float b20 = b2[k*16+io], b21 = b2[128+k*16+io];
    g_Bias[      k*16+io] = b10 - b11;
    g_Bias[128 + k*16+io] = b10 + b11;
    g_Bias[256 + k*16+io] = b20 - b21;
    g_Bias[384 + k*16+io] = b20 + b21;
  }
}

// ---------------- K1: forward rfft over L (radix-2, channel-pair, 2 sites/CTA) ----------------
__global__ void __launch_bounds__(128) k_fwd_l(const float* __restrict__ x){
  __shared__ float2 tw[32];
  if (threadIdx.x < 32) tw[threadIdx.x] = TW32[threadIdx.x];
  __syncthreads();
  int site = blockIdx.x*2 + (threadIdx.x>>6);
  int c = threadIdx.x & 63;
  const float2* xp = (const float2*)(x + (size_t)site*4096) + c;
  float2 u[16], dd[16];
#pragma unroll
  for (int t=0;t<16;t++){
    float2 a = xp[t*64], b2 = xp[(t+16)*64];
    u[t]  = make_float2(a.x+b2.x, a.y+b2.y);
    dd[t] = make_float2(a.x-b2.x, a.y-b2.y);
  }
  float2 ar[8], ai[8];
#pragma unroll
  for (int l=0;l<8;l++){ ar[l]=make_float2(0.f,0.f); ai[l]=make_float2(0.f,0.f); }
#pragma unroll
  for (int t=0;t<16;t++){
#pragma unroll
    for (int j=0;j<4;j++){
      float2 we = tw[(t*2*j)&31];
      ar[2*j].x = fmaf( u[t].x, we.x, ar[2*j].x);
      ar[2*j].y = fmaf( u[t].y, we.x, ar[2*j].y);
      ai[2*j].x = fmaf(-u[t].x, we.y, ai[2*j].x);
      ai[2*j].y = fmaf(-u[t].y, we.y, ai[2*j].y);
      float2 wo = tw[(t*(2*j+1))&31];
      ar[2*j+1].x = fmaf( dd[t].x, wo.x, ar[2*j+1].x);
      ar[2*j+1].y = fmaf( dd[t].y, wo.x, ar[2*j+1].y);
      ai[2*j+1].x = fmaf(-dd[t].x, wo.y, ai[2*j+1].x);
      ai[2*j+1].y = fmaf(-dd[t].y, wo.y, ai[2*j+1].y);
    }
  }
  const float s = 0.1767766952966369f;
  uint2* op = (uint2*)g_s3h + (size_t)site*512 + c;
#pragma unroll
  for (int l=0;l<8;l++)
    op[l*64] = make_uint2(bf2(ar[l].x*s, ai[l].x*s), bf2(ar[l].y*s, ai[l].y*s));
}

// ---------------- complex DFT GEMM stage (bf16 complex I/O, pair-split B) ----------------
// in/out: 1 unsigned per complex; row = 1024 complexes; tile = 32 complexes.
template<int M, int K, int SGN, int MINB>
__global__ void __launch_bounds__(128, MINB) k_dft_mma(const unsigned* __restrict__ in,
                                                 unsigned* __restrict__ out,
                                                 const float4* __restrict__ A4,
                                                 size_t inStrideC, size_t outStrideC){
  constexpr int KT = K/8;
  constexpr int MT = M/16;
  constexpr int PH = (K/2)*72;
  __shared__ __align__(16) float Bs[2*PH];
  int tid = threadIdx.x;
  {
    const unsigned* src = in + blockIdx.y*inStrideC + blockIdx.x*32;
    for (int i = tid; i < K*8; i += 128){
      int k = i >> 3, j4 = (i & 7)*4;
      uint4 v = *(const uint4*)(src + (size_t)k*1024 + j4);
      float2 f0=unbf2(v.x), f1=unbf2(v.y), f2=unbf2(v.z), f3=unbf2(v.w);
      float* d = Bs + ((k>>2)&1)*PH + ((k>>3)*4 + (k&3))*72 + 2*j4;
      *(float4*)d     = make_float4(f0.x, f0.y, f1.x, f1.y);
      *(float4*)(d+4) = make_float4(f2.x, f2.y, f3.x, f3.y);
    }
  }
  __syncthreads();
  int warp = tid>>5, lane = tid&31;
  int qid = lane>>2, rid = lane&3;
  int wcol = warp*16;
  float4 C[2][MT][2];
#pragma unroll
  for (int a=0;a<2;a++)
#pragma unroll
    for (int b=0;b<MT;b++)
#pragma unroll
      for (int c=0;c<2;c++) C[a][b][c] = make_float4(0.f,0.f,0.f,0.f);
#pragma unroll
  for (int kk=0; kk<KT; kk++){
    int sb = (kk*4 + rid)*72;
    float b00 = Bs[sb + wcol + qid];
    float b01 = Bs[PH + sb + wcol + qid];
    float b10 = Bs[sb + wcol + 8 + qid];
    float b11 = Bs[PH + sb + wcol + 8 + qid];
#pragma unroll
    for (int mm=0; mm<2; mm++){
#pragma unroll
      for (int mt=0; mt<MT; mt++){
        float4 af = __ldg(A4 + ((mm*KT+kk)*MT+mt)*32 + lane);
        mma8(C[mm][mt][0], af.x, af.y, af.z, af.w, b00, b01);
        mma8(C[mm][mt][1], af.x, af.y, af.z, af.w, b10, b11);
      }
    }
  }
  unsigned* ob = out + blockIdx.y*outStrideC + blockIdx.x*32;
#pragma unroll
  for (int mt=0; mt<MT; mt++){
#pragma unroll
    for (int nt=0; nt<2; nt++){
      float4 cr = C[0][mt][nt], ci = C[1][mt][nt];
      int colC = warp*8 + nt*4 + rid;
      int m0 = mt*16 + qid;
      if (SGN > 0){
        ob[(size_t)m0*1024 + colC]     = bf2(cr.x + ci.y, cr.y - ci.x);
        ob[(size_t)(m0+8)*1024 + colC] = bf2(cr.z + ci.w, cr.w - ci.z);
      } else {
        ob[(size_t)m0*1024 + colC]     = bf2(cr.x - ci.y, cr.y + ci.x);
        ob[(size_t)(m0+8)*1024 + colC] = bf2(cr.z - ci.w, cr.w + ci.z);
      }
    }
  }
}

// ---------------- K_mid: fwd-H + MLP + inv-H in place (bf16 complex I/O) ----------------
// smem floats: sW[4096]@0 | sBias[272]@4096 | U[8704]@4368 | U2[4352]@13072 = 69696 B
__global__ void __launch_bounds__(256,3) k_mid(){
  extern __shared__ float sm[];
  float* sW    = sm;
  float* sBias = sm + 4096;
  float* U     = sm + 4368;
  float* U2    = sm + 13072;
  const int PH1 = 4352;   // 32*136
  const int PH2 = 2176;   // 16*136
  int tid = threadIdx.x;
  int bx = blockIdx.x, b = blockIdx.y;
  int w = bx>>4, l = (bx>>1)&7, chalf = bx&1;
  for (int i=tid; i<1024; i+=256){
    int mg=i>>8, nb0=(i>>6)&3;
    ((float4*)sW)[i] = ((const float4*)g_W)[(mg*8+chalf*4+nb0)*64 + (i&63)];
  }
  { int mg=tid>>6, nb0=(tid>>4)&3, o=tid&15;
    sBias[(mg*4+nb0)*17+o] = g_Bias[mg*128 + (chalf*4+nb0)*16 + o]; }
  unsigned* gs = g_s2h + (size_t)b*2097152 + (size_t)w*1024 + l*128 + chalf*64;
  for (int i=tid; i<2048; i+=256){
    int yy=i>>5, cp=i&31;
    uint2 v = *(const uint2*)(gs + (size_t)yy*32768 + 2*cp);
    float2 f0 = unbf2(v.x), f1 = unbf2(v.y);
    float* d = U + ((yy>>2)&1)*PH1 + ((yy>>3)*4+(yy&3))*136 + 4*cp;
    *(float4*)d = make_float4(f0.x, f0.y, f1.x, f1.y);
  }
  __syncthreads();
  int warp=tid>>5, lane=tid&31, qid=lane>>2, rid=lane&3;
  // GEMM1 fwd-H: M=32,K=64,N=128
  float4 C1[2][2][2];
#pragma unroll
  for (int a=0;a<2;a++)
#pragma unroll
    for (int m=0;m<2;m++)
#pragma unroll
      for (int n=0;n<2;n++) C1[a][m][n] = make_float4(0.f,0.f,0.f,0.f);
#pragma unroll
  for (int kk=0; kk<8; kk++){
    int sb = (kk*4+rid)*136;
    float b00 = U[sb + warp*16 + qid];
    float b01 = U[PH1 + sb + warp*16 + qid];
    float b10 = U[sb + warp*16 + 8 + qid];
    float b11 = U[PH1 + sb + warp*16 + 8 + qid];
#pragma unroll
    for (int mat=0; mat<2; mat++){
#pragma unroll
      for (int mt=0; mt<2; mt++){
        float4 af = __ldg(&g_A4W[((mat*8+kk)*2+mt)*32 + lane]);
        mma8(C1[mat][mt][0], af.x,af.y,af.z,af.w, b00, b01);
        mma8(C1[mat][mt][1], af.x,af.y,af.z,af.w, b10, b11);
      }
    }
  }
  __syncthreads();
  float2* sSpec = (float2*)U;   // stride 65 f2
#pragma unroll
  for (int mt=0; mt<2; mt++)
#pragma unroll
    for (int nt=0; nt<2; nt++){
      float4 cc = C1[0][mt][nt], cs = C1[1][mt][nt];
      int c2 = warp*8+nt*4+rid, h0 = mt*16+qid;
      sSpec[h0*65 + c2]     = make_float2(cc.x+cs.y, cc.y-cs.x);
      sSpec[(h0+8)*65 + c2] = make_float2(cc.z+cs.w, cc.w-cs.z);
    }
  __syncthreads();
  // MLP: inst=(nb0,h), 2 threads each (half)
  {
    int inst=tid>>1, half=tid&1, nb0=inst>>5, h=inst&31;
    const float* W1R = sW + nb0*256;
    const float* W1I = sW + (4+nb0)*256;
    const float* W2R = sW + (8+nb0)*256;
    const float* W2I = sW + (12+nb0)*256;
    const float* Bb0 = sBias + nb0*17;
    const float* Bb1 = sBias + (4+nb0)*17;
    const float* Bb2 = sBias + (8+nb0)*17;
    const float* Bb3 = sBias + (12+nb0)*17;
    float xr[16], xi[16];
#pragma unroll
    for (int i=0;i<16;i++){ float2 v = sSpec[h*65 + nb0*16 + i]; xr[i]=v.x; xi[i]=v.y; }
    float pr[16], pi[16];
#pragma unroll
    for (int o=0;o<16;o++){ pr[o]=Bb0[o]; pi[o]=Bb1[o]; }
#pragma unroll
    for (int i=0;i<16;i++){
      float xrv = xr[i], xiv = xi[i];
#pragma unroll
      for (int o4=0;o4<4;o4++){
        float4 wr = *(const float4*)(W1R + i*16 + o4*4);
        float4 wi = *(const float4*)(W1I + i*16 + o4*4);
        pr[o4*4+0] += xrv*wr.x - xiv*wi.x;  pi[o4*4+0] += xiv*wr.x + xrv*wi.x;
        pr[o4*4+1] += xrv*wr.y - xiv*wi.y;  pi[o4*4+1] += xiv*wr.y + xrv*wi.y;
        pr[o4*4+2] += xrv*wr.z - xiv*wi.z;  pi[o4*4+2] += xiv*wr.z + xrv*wi.z;
        pr[o4*4+3] += xrv*wr.w - xiv*wi.w;  pi[o4*4+3] += xiv*wr.w + xrv*wi.w;
      }
    }
#pragma unroll
    for (int o=0;o<16;o++){ pr[o]=gelu_f(pr[o]); pi[o]=gelu_f(pi[o]); }
    float qr[8], qi[8];
#pragma unroll
    for (int oo=0;oo<8;oo++){ int o=half*8+oo; qr[oo]=Bb2[o]; qi[oo]=Bb3[o]; }
#pragma unroll
    for (int i=0;i<16;i++){
      float prv = pr[i], piv = pi[i];
#pragma unroll
      for (int o4=0;o4<2;o4++){
        float4 wr = *(const float4*)(W2R + i*16 + half*8 + o4*4);
        float4 wi = *(const float4*)(W2I + i*16 + half*8 + o4*4);
        qr[o4*4+0] += prv*wr.x - piv*wi.x;  qi[o4*4+0] += piv*wr.x + prv*wi.x;
        qr[o4*4+1] += prv*wr.y - piv*wi.y;  qi[o4*4+1] += piv*wr.y + prv*wi.y;
        qr[o4*4+2] += prv*wr.z - piv*wi.z;  qi[o4*4+2] += piv*wr.z + prv*wi.z;
        qr[o4*4+3] += prv*wr.w - piv*wi.w;  qi[o4*4+3] += piv*wr.w + prv*wi.w;
      }
    }
    float* d = U2 + ((h>>2)&1)*PH2 + ((h>>3)*4+(h&3))*136 + 2*(nb0*16+half*8);
#pragma unroll
    for (int j=0;j<4;j++){
      *(float4*)(d + 4*j) = make_float4(tf32f(qr[2*j]), tf32f(qi[2*j]),
                                        tf32f(qr[2*j+1]), tf32f(qi[2*j+1]));
    }
  }
  __syncthreads();
  // GEMM2 inv-H: M=64,K=32,N=128
  float4 C3[2][4][2];
#pragma unroll
  for (int a=0;a<2;a++)
#pragma unroll
    for (int m=0;m<4;m++)
#pragma unroll
      for (int n=0;n<2;n++) C3[a][m][n] = make_float4(0.f,0.f,0.f,0.f);
#pragma unroll
  for (int kk=0; kk<4; kk++){
    int sb = (kk*4+rid)*136;
    float b00 = U2[sb + warp*16 + qid];
    float b01 = U2[PH2 + sb + warp*16 + qid];
    float b10 = U2[sb + warp*16 + 8 + qid];
    float b11 = U2[PH2 + sb + warp*16 + 8 + qid];
#pragma unroll
    for (int mat=0; mat<2; mat++){
#pragma unroll
      for (int mt=0; mt<4; mt++){
        float4 af = __ldg(&g_A4Wi[((mat*4+kk)*4+mt)*32 + lane]);
        mma8(C3[mat][mt][0], af.x,af.y,af.z,af.w, b00, b01);
        mma8(C3[mat][mt][1], af.x,af.y,af.z,af.w, b10, b11);
      }
    }
  }
#pragma unroll
  for (int mt=0; mt<4; mt++)
#pragma unroll
    for (int nt=0; nt<2; nt++){
      float4 cc = C3[0][mt][nt], cs = C3[1][mt][nt];
      int c2 = warp*8+nt*4+rid, y0 = mt*16+qid;
      gs[(size_t)y0*32768 + c2]     = bf2(cc.x-cs.y, cc.y+cs.x);
      gs[(size_t)(y0+8)*32768 + c2] = bf2(cc.z-cs.w, cc.w+cs.z);
    }
}

// ---------------- K7: inverse rfft over L (radix-2, channel-pair, 2 sites/CTA) + residual ----------------
__global__ void __launch_bounds__(128) k_inv_l(const float* __restrict__ xin, float* __restrict__ out){
  __shared__ float2 tw[32];
  if (threadIdx.x < 32) tw[threadIdx.x] = TW32[threadIdx.x];
  __syncthreads();
  int site = blockIdx.x*2 + (threadIdx.x>>6);
  int c = threadIdx.x & 63;
  const uint2* ip = (const uint2*)g_s3h + (size_t)site*512 + c;
  float2 Xr[8], Xi[8];
#pragma unroll
  for (int l=0;l<8;l++){
    uint2 v = ip[l*64];
    float2 f0 = unbf2(v.x), f1 = unbf2(v.y);
    Xr[l] = make_float2(f0.x, f1.x);
    Xi[l] = make_float2(f0.y, f1.y);
  }
#pragma unroll
  for (int l=1;l<8;l++){ Xr[l].x*=2.f; Xr[l].y*=2.f; Xi[l].x*=2.f; Xi[l].y*=2.f; }
  const float s = 0.1767766952966369f;
  const float2* rp = (const float2*)(xin + (size_t)site*4096) + c;
  float2* op = (float2*)(out + (size_t)site*4096) + c;
#pragma unroll
  for (int t=0;t<16;t++){
    float2 E = Xr[0];
    float2 O = make_float2(0.f,0.f);
#pragma unroll
    for (int j=1;j<4;j++){
      float2 we = tw[(2*j*t)&31];
      E.x += Xr[2*j].x*we.x - Xi[2*j].x*we.y;
      E.y += Xr[2*j].y*we.x - Xi[2*j].y*we.y;
    }
#pragma unroll
    for (int j=0;j<4;j++){
      float2 wo = tw[((2*j+1)*t)&31];
      O.x += Xr[2*j+1].x*wo.x - Xi[2*j+1].x*wo.y;
      O.y += Xr[2*j+1].y*wo.x - Xi[2*j+1].y*wo.y;
    }
    float2 r0 = rp[t*64], r1 = rp[(t+16)*64];
    op[t*64]      = make_float2(fmaf(E.x+O.x, s, r0.x), fmaf(E.y+O.y, s, r0.y));
    op[(t+16)*64] = make_float2(fmaf(E.x-O.x, s, r1.x), fmaf(E.y-O.y, s, r1.y));
  }
}

// ---------------- launch ----------------
extern "C" void kernel_launch(void* const* d_in, const int* in_sizes, int n_in,
                              void* d_out, int out_size){
  (void)in_sizes; (void)n_in; (void)out_size;
  const float* x = (const float*)d_in[0];
  void *ps3, *ps2, *paw, *pawi;
  cudaGetSymbolAddress(&ps3,  g_s3h);
  cudaGetSymbolAddress(&ps2,  g_s2h);
  cudaGetSymbolAddress(&paw,  g_A4W);
  cudaGetSymbolAddress(&pawi, g_A4Wi);
  const unsigned* s3 = (const unsigned*)ps3;
  const unsigned* s2 = (const unsigned*)ps2;
  const float4* aw  = (const float4*)paw;
  const float4* awi = (const float4*)pawi;
  cudaFuncSetAttribute(k_mid, cudaFuncAttributeMaxDynamicSharedMemorySize, 69696);

  k_prep<<<8,256>>>((const float*)d_in[1], (const float*)d_in[2], (const float*)d_in[3],
                    (const float*)d_in[4], (const float*)d_in[5], (const float*)d_in[6],
                    (const float*)d_in[7], (const float*)d_in[8], (const float*)d_in[9],
                    (const float*)d_in[10], (const float*)d_in[11], (const float*)d_in[12],
                    (const float*)d_in[13]);
  k_init4<<<8,256>>>();
  k_fwd_l<<<8192,128>>>(x);
  // fwd W: Out[32 w][1024C] = T @ In[64 xx][1024C], 256 (b,y) batches
  k_dft_mma<32,64, 1,8><<<dim3(32,256),128>>>(s3, (unsigned*)s2, aw, 65536, 32768);
  // fwd H + MLP + inv H, in place on g_s2h
  k_mid<<<dim3(512,4),256,69696>>>();
  // inv W: Out[64 xx][1024C] = T @ In[32 w][1024C]
  k_dft_mma<64,32,-1,6><<<dim3(32,256),128>>>(s2, (unsigned*)s3, awi, 32768, 65536);
  k_inv_l<<<8192,128>>>(x, (float*)d_out);
}

// round 12
// speedup vs baseline: 1.1809x; 1.0577x over previous
#include <cuda_runtime.h>
#include <cuda_bf16.h>
#include <math.h>

// ---------------- scratch (bf16x2 complex intermediates) ----------------
__device__ __align__(16) unsigned g_s3h[16777216]; // [4][64][64][8][128] complexes (bf16 re,im)
__device__ __align__(16) unsigned g_s2h[8388608];  // [4][64][32][8][128] complexes
__device__ __align__(16) float  g_W[8192];
__device__ __align__(16) float  g_Bias[512];
__device__ __align__(16) float4 g_A4W[1024];       // k_mid fwd tf32 fragments, 1/8 baked
__device__ __align__(16) float4 g_A4Wi[1024];      // k_mid inv tf32 fragments
__device__ __align__(16) uint4  g_A4H[1024];       // dft bf16 m16n8k16 fragments: [fwd 512 | inv 512]

__constant__ float2 TW32[32] = {
  { 1.000000000f, 0.000000000f},{ 0.980785280f, 0.195090322f},{ 0.923879533f, 0.382683432f},{ 0.831469612f, 0.555570233f},
  { 0.707106781f, 0.707106781f},{ 0.555570233f, 0.831469612f},{ 0.382683432f, 0.923879533f},{ 0.195090322f, 0.980785280f},
  { 0.000000000f, 1.000000000f},{-0.195090322f, 0.980785280f},{-0.382683432f, 0.923879533f},{-0.555570233f, 0.831469612f},
  {-0.707106781f, 0.707106781f},{-0.831469612f, 0.555570233f},{-0.923879533f, 0.382683432f},{-0.980785280f, 0.195090322f},
  {-1.000000000f, 0.000000000f},{-0.980785280f,-0.195090322f},{-0.923879533f,-0.382683432f},{-0.831469612f,-0.555570233f},
  {-0.707106781f,-0.707106781f},{-0.555570233f,-0.831469612f},{-0.382683432f,-0.923879533f},{-0.195090322f,-0.980785280f},
  { 0.000000000f,-1.000000000f},{ 0.195090322f,-0.980785280f},{ 0.382683432f,-0.923879533f},{ 0.555570233f,-0.831469612f},
  { 0.707106781f,-0.707106781f},{ 0.831469612f,-0.555570233f},{ 0.923879533f,-0.382683432f},{ 0.980785280f,-0.195090322f}
};

__device__ __forceinline__ float gelu_f(float v){
  return 0.5f*v*(1.0f+erff(v*0.7071067811865476f));
}
__device__ __forceinline__ float tf32f(float f){
  unsigned u; asm("cvt.rna.tf32.f32 %0, %1;" : "=r"(u) : "f"(f));
  return __uint_as_float(u);
}
__device__ __forceinline__ unsigned bf2(float a, float b){
  __nv_bfloat162 h = __floats2bfloat162_rn(a, b);
  return *reinterpret_cast<unsigned*>(&h);
}
__device__ __forceinline__ float2 unbf2(unsigned u){
  __nv_bfloat162 h = *reinterpret_cast<__nv_bfloat162*>(&u);
  return __bfloat1622float2(h);
}
__device__ __forceinline__ void mma8(float4& d, float a0, float a1, float a2, float a3,
                                     float b0, float b1){
  asm volatile("mma.sync.aligned.m16n8k8.row.col.f32.tf32.tf32.f32 "
    "{%0,%1,%2,%3}, {%4,%5,%6,%7}, {%8,%9}, {%0,%1,%2,%3};"
    : "+f"(d.x), "+f"(d.y), "+f"(d.z), "+f"(d.w)
    : "r"(__float_as_uint(a0)), "r"(__float_as_uint(a1)),
      "r"(__float_as_uint(a2)), "r"(__float_as_uint(a3)),
      "r"(__float_as_uint(b0)), "r"(__float_as_uint(b1)));
}
__device__ __forceinline__ void mma16(float4& d, uint4 a, unsigned b0, unsigned b1){
  asm volatile("mma.sync.aligned.m16n8k16.row.col.f32.bf16.bf16.f32 "
    "{%0,%1,%2,%3}, {%4,%5,%6,%7}, {%8,%9}, {%0,%1,%2,%3};"
    : "+f"(d.x), "+f"(d.y), "+f"(d.z), "+f"(d.w)
    : "r"(a.x), "r"(a.y), "r"(a.z), "r"(a.w), "r"(b0), "r"(b1));
}

// ---------------- K0a: packed twiddle fragments (tf32 for k_mid) ----------------
__device__ __forceinline__ float twval(int mat, int m, int k){
  double a = (double)(m*k)/32.0;
  return tf32f((float)((mat ? sinpi(a) : cospi(a))*0.125));
}
__global__ void k_init4(){
  int e = blockIdx.x*256 + threadIdx.x;   // 0..2047
  int lane = e&31, qid = lane>>2, rid = lane&3;
  int which = e>>10, j = e&1023;
  if (which==0){                           // fwd: MT=2, KT=8
    int mt=(j>>5)&1, kk=(j>>6)&7, mat=j>>9;
    int r0=mt*16+qid, r1=r0+8, k0=kk*8+rid, k1=k0+4;
    g_A4W[j] = make_float4(twval(mat,r0,k0), twval(mat,r1,k0),
                           twval(mat,r0,k1), twval(mat,r1,k1));
  } else {                                 // inv: MT=4, KT=4
    int mt=(j>>5)&3, kk=(j>>7)&3, mat=j>>9;
    int r0=mt*16+qid, r1=r0+8, k0=kk*8+rid, k1=k0+4;
    g_A4Wi[j] = make_float4(twval(mat,r0,k0), twval(mat,r1,k0),
                            twval(mat,r0,k1), twval(mat,r1,k1));
  }
}
// bf16 m16n8k16 fragments for the dft kernels
__global__ void k_init4h(){
  int j = blockIdx.x*256 + threadIdx.x;   // 0..1023
  int lane = j&31, qid = lane>>2, rid = lane&3;
  int which = j>>9, t = j&511;
  int mat, kk16, mt;
  if (which==0){ mt=(t>>5)&1; kk16=(t>>6)&3; mat=t>>8; }   // fwd: M=32,K=64
  else         { mt=(t>>5)&3; kk16=(t>>7)&1; mat=t>>8; }   // inv: M=64,K=32
  int r0 = mt*16+qid, r1 = r0+8, k0 = kk16*16 + 2*rid;
  float v[8];
#pragma unroll
  for (int q=0; q<8; q++){
    int m = (q&1) ? r1 : r0;
    int k = k0 + (q>>2)*8 + ((q>>1)&1);
    double a = (double)(m*k)/32.0;
    v[q] = (float)((mat ? sinpi(a) : cospi(a))*0.125);
  }
  g_A4H[j] = make_uint4(bf2(v[0],v[2]), bf2(v[1],v[3]), bf2(v[4],v[6]), bf2(v[5],v[7]));
}

// ---------------- K0: fold HydraLoRA ----------------
__global__ void k_prep(const float* __restrict__ w1, const float* __restrict__ b1,
                       const float* __restrict__ w2, const float* __restrict__ b2,
                       const float* __restrict__ A1r, const float* __restrict__ B1r,
                       const float* __restrict__ A1i, const float* __restrict__ B1i,
                       const float* __restrict__ A2r, const float* __restrict__ B2r,
                       const float* __restrict__ A2i, const float* __restrict__ B2i,
                       const float* __restrict__ ew){
  int k  = blockIdx.x;
  int io = threadIdx.x;
  int i = io >> 4, o = io & 15;
  float e0 = ew[0], e1 = ew[1], e2 = ew[2], e3 = ew[3];
  const float s = 0.03125f;
  const float* Ws[4] = { w1 + k*256, w1 + 2048 + k*256, w2 + k*256, w2 + 2048 + k*256 };
  const float* As[4] = { A1r + k*512, A1i + k*512, A2r + k*512, A2i + k*512 };
  const float* Bs[4] = { B1r + k*2048, B1i + k*2048, B2r + k*2048, B2i + k*2048 };
#pragma unroll
  for (int m = 0; m < 4; m++){
    const float* A  = As[m] + i*32;
    const float* Bb = Bs[m];
    float acc = 0.f;
    for (int r = 0; r < 32; r++){
      float bm = e0*Bb[r*16+o] + e1*Bb[512+r*16+o] + e2*Bb[1024+r*16+o] + e3*Bb[1536+r*16+o];
      acc = fmaf(A[r], bm, acc);
    }
    g_W[((m*8+k)*16+i)*16+o] = Ws[m][i*16+o] + s*acc;
  }
  if (io < 16){
    float b10 = b1[k*16+io], b11 = b1[128+k*16+io];
    float b20 = b2[k*16+io], b21 = b2[128+k*16+io];
    g_Bias[      k*16+io] = b10 - b11;
    g_Bias[128 + k*16+io] = b10 + b11;
    g_Bias[256 + k*16+io] = b20 - b21;
    g_Bias[384 + k*16+io] = b20 + b21;
  }
}

// ---------------- K1: forward rfft over L ----------------
__global__ void __launch_bounds__(128) k_fwd_l(const float* __restrict__ x){
  __shared__ float2 tw[32];
  if (threadIdx.x < 32) tw[threadIdx.x] = TW32[threadIdx.x];
  __syncthreads();
  int site = blockIdx.x*2 + (threadIdx.x>>6);
  int c = threadIdx.x & 63;
  const float2* xp = (const float2*)(x + (size_t)site*4096) + c;
  float2 u[16], dd[16];
#pragma unroll
  for (int t=0;t<16;t++){
    float2 a = xp[t*64], b2 = xp[(t+16)*64];
    u[t]  = make_float2(a.x+b2.x, a.y+b2.y);
    dd[t] = make_float2(a.x-b2.x, a.y-b2.y);
  }
  float2 ar[8], ai[8];
#pragma unroll
  for (int l=0;l<8;l++){ ar[l]=make_float2(0.f,0.f); ai[l]=make_float2(0.f,0.f); }
#pragma unroll
  for (int t=0;t<16;t++){
#pragma unroll
    for (int j=0;j<4;j++){
      float2 we = tw[(t*2*j)&31];
      ar[2*j].x = fmaf( u[t].x, we.x, ar[2*j].x);
      ar[2*j].y = fmaf( u[t].y, we.x, ar[2*j].y);
      ai[2*j].x = fmaf(-u[t].x, we.y, ai[2*j].x);
      ai[2*j].y = fmaf(-u[t].y, we.y, ai[2*j].y);
      float2 wo = tw[(t*(2*j+1))&31];
      ar[2*j+1].x = fmaf( dd[t].x, wo.x, ar[2*j+1].x);
      ar[2*j+1].y = fmaf( dd[t].y, wo.x, ar[2*j+1].y);
      ai[2*j+1].x = fmaf(-dd[t].x, wo.y, ai[2*j+1].x);
      ai[2*j+1].y = fmaf(-dd[t].y, wo.y, ai[2*j+1].y);
    }
  }
  const float s = 0.1767766952966369f;
  uint2* op = (uint2*)g_s3h + (size_t)site*512 + c;
#pragma unroll
  for (int l=0;l<8;l++)
    op[l*64] = make_uint2(bf2(ar[l].x*s, ai[l].x*s), bf2(ar[l].y*s, ai[l].y*s));
}

// ---------------- complex DFT GEMM (bf16 m16n8k16, paired-k B layout) ----------------
// Bs word (k2, n) = (B[2k2,n] , B[2k2+1,n]) bf16x2; slice stride 72 words.
template<int M, int K, int SGN, int MINB>
__global__ void __launch_bounds__(128, MINB) k_dft_mma(const unsigned* __restrict__ in,
                                                 unsigned* __restrict__ out,
                                                 const uint4* __restrict__ A4,
                                                 size_t inStrideC, size_t outStrideC){
  constexpr int KT16 = K/16;
  constexpr int MT = M/16;
  constexpr int K2 = K/2;
  __shared__ __align__(16) unsigned Bs[K2*72];
  int tid = threadIdx.x;
  const unsigned* src = in + blockIdx.y*inStrideC + blockIdx.x*32;
  for (int i = tid; i < K2*16; i += 128){
    int k2 = i>>4, j2p = i&15;
    uint2 a = *(const uint2*)(src + (size_t)(2*k2)*1024 + 2*j2p);
    uint2 b = *(const uint2*)(src + (size_t)(2*k2+1)*1024 + 2*j2p);
    *(uint4*)(Bs + k2*72 + 4*j2p) = make_uint4(
      __byte_perm(a.x, b.x, 0x5410), __byte_perm(a.x, b.x, 0x7632),
      __byte_perm(a.y, b.y, 0x5410), __byte_perm(a.y, b.y, 0x7632));
  }
  __syncthreads();
  int warp = tid>>5, lane = tid&31;
  int qid = lane>>2, rid = lane&3;
  int wcol = warp*16;
  float4 C[2][MT][2];
#pragma unroll
  for (int a=0;a<2;a++)
#pragma unroll
    for (int b=0;b<MT;b++)
#pragma unroll
      for (int c=0;c<2;c++) C[a][b][c] = make_float4(0.f,0.f,0.f,0.f);
#pragma unroll
  for (int kk=0; kk<KT16; kk++){
    int s0 = (kk*8 + rid)*72, s1 = (kk*8 + rid + 4)*72;
    unsigned b0n0 = Bs[s0 + wcol + qid];
    unsigned b1n0 = Bs[s1 + wcol + qid];
    unsigned b0n1 = Bs[s0 + wcol + 8 + qid];
    unsigned b1n1 = Bs[s1 + wcol + 8 + qid];
#pragma unroll
    for (int mm=0; mm<2; mm++){
#pragma unroll
      for (int mt=0; mt<MT; mt++){
        uint4 af = __ldg(A4 + ((mm*KT16+kk)*MT+mt)*32 + lane);
        mma16(C[mm][mt][0], af, b0n0, b1n0);
        mma16(C[mm][mt][1], af, b0n1, b1n1);
      }
    }
  }
  unsigned* ob = out + blockIdx.y*outStrideC + blockIdx.x*32;
#pragma unroll
  for (int mt=0; mt<MT; mt++){
#pragma unroll
    for (int nt=0; nt<2; nt++){
      float4 cr = C[0][mt][nt], ci = C[1][mt][nt];
      int colC = warp*8 + nt*4 + rid;
      int m0 = mt*16 + qid;
      if (SGN > 0){
        ob[(size_t)m0*1024 + colC]     = bf2(cr.x + ci.y, cr.y - ci.x);
        ob[(size_t)(m0+8)*1024 + colC] = bf2(cr.z + ci.w, cr.w - ci.z);
      } else {
        ob[(size_t)m0*1024 + colC]     = bf2(cr.x - ci.y, cr.y + ci.x);
        ob[(size_t)(m0+8)*1024 + colC] = bf2(cr.z - ci.w, cr.w + ci.z);
      }
    }
  }
}

// ---------------- K_mid: fwd-H + MLP + inv-H in place (unchanged from R11) ----------------
__global__ void __launch_bounds__(256,3) k_mid(){
  extern __shared__ float sm[];
  float* sW    = sm;
  float* sBias = sm + 4096;
  float* U     = sm + 4368;
  float* U2    = sm + 13072;
  const int PH1 = 4352;   // 32*136
  const int PH2 = 2176;   // 16*136
  int tid = threadIdx.x;
  int bx = blockIdx.x, b = blockIdx.y;
  int w = bx>>4, l = (bx>>1)&7, chalf = bx&1;
  for (int i=tid; i<1024; i+=256){
    int mg=i>>8, nb0=(i>>6)&3;
    ((float4*)sW)[i] = ((const float4*)g_W)[(mg*8+chalf*4+nb0)*64 + (i&63)];
  }
  { int mg=tid>>6, nb0=(tid>>4)&3, o=tid&15;
    sBias[(mg*4+nb0)*17+o] = g_Bias[mg*128 + (chalf*4+nb0)*16 + o]; }
  unsigned* gs = g_s2h + (size_t)b*2097152 + (size_t)w*1024 + l*128 + chalf*64;
  for (int i=tid; i<2048; i+=256){
    int yy=i>>5, cp=i&31;
    uint2 v = *(const uint2*)(gs + (size_t)yy*32768 + 2*cp);
    float2 f0 = unbf2(v.x), f1 = unbf2(v.y);
    float* d = U + ((yy>>2)&1)*PH1 + ((yy>>3)*4+(yy&3))*136 + 4*cp;
    *(float4*)d = make_float4(f0.x, f0.y, f1.x, f1.y);
  }
  __syncthreads();
  int warp=tid>>5, lane=tid&31, qid=lane>>2, rid=lane&3;
  float4 C1[2][2][2];
#pragma unroll
  for (int a=0;a<2;a++)
#pragma unroll
    for (int m=0;m<2;m++)
#pragma unroll
      for (int n=0;n<2;n++) C1[a][m][n] = make_float4(0.f,0.f,0.f,0.f);
#pragma unroll
  for (int kk=0; kk<8; kk++){
    int sb = (kk*4+rid)*136;
    float b00 = U[sb + warp*16 + qid];
    float b01 = U[PH1 + sb + warp*16 + qid];
    float b10 = U[sb + warp*16 + 8 + qid];
    float b11 = U[PH1 + sb + warp*16 + 8 + qid];
#pragma unroll
    for (int mat=0; mat<2; mat++){
#pragma unroll
      for (int mt=0; mt<2; mt++){
        float4 af = __ldg(&g_A4W[((mat*8+kk)*2+mt)*32 + lane]);
        mma8(C1[mat][mt][0], af.x,af.y,af.z,af.w, b00, b01);
        mma8(C1[mat][mt][1], af.x,af.y,af.z,af.w, b10, b11);
      }
    }
  }
  __syncthreads();
  float2* sSpec = (float2*)U;   // stride 65 f2
#pragma unroll
  for (int mt=0; mt<2; mt++)
#pragma unroll
    for (int nt=0; nt<2; nt++){
      float4 cc = C1[0][mt][nt], cs = C1[1][mt][nt];
      int c2 = warp*8+nt*4+rid, h0 = mt*16+qid;
      sSpec[h0*65 + c2]     = make_float2(cc.x+cs.y, cc.y-cs.x);
      sSpec[(h0+8)*65 + c2] = make_float2(cc.z+cs.w, cc.w-cs.z);
    }
  __syncthreads();
  {
    int inst=tid>>1, half=tid&1, nb0=inst>>5, h=inst&31;
    const float* W1R = sW + nb0*256;
    const float* W1I = sW + (4+nb0)*256;
    const float* W2R = sW + (8+nb0)*256;
    const float* W2I = sW + (12+nb0)*256;
    const float* Bb0 = sBias + nb0*17;
    const float* Bb1 = sBias + (4+nb0)*17;
    const float* Bb2 = sBias + (8+nb0)*17;
    const float* Bb3 = sBias + (12+nb0)*17;
    float xr[16], xi[16];
#pragma unroll
    for (int i=0;i<16;i++){ float2 v = sSpec[h*65 + nb0*16 + i]; xr[i]=v.x; xi[i]=v.y; }
    float pr[16], pi[16];
#pragma unroll
    for (int o=0;o<16;o++){ pr[o]=Bb0[o]; pi[o]=Bb1[o]; }
#pragma unroll
    for (int i=0;i<16;i++){
      float xrv = xr[i], xiv = xi[i];
#pragma unroll
      for (int o4=0;o4<4;o4++){
        float4 wr = *(const float4*)(W1R + i*16 + o4*4);
        float4 wi = *(const float4*)(W1I + i*16 + o4*4);
        pr[o4*4+0] += xrv*wr.x - xiv*wi.x;  pi[o4*4+0] += xiv*wr.x + xrv*wi.x;
        pr[o4*4+1] += xrv*wr.y - xiv*wi.y;  pi[o4*4+1] += xiv*wr.y + xrv*wi.y;
        pr[o4*4+2] += xrv*wr.z - xiv*wi.z;  pi[o4*4+2] += xiv*wr.z + xrv*wi.z;
        pr[o4*4+3] += xrv*wr.w - xiv*wi.w;  pi[o4*4+3] += xiv*wr.w + xrv*wi.w;
      }
    }
#pragma unroll
    for (int o=0;o<16;o++){ pr[o]=gelu_f(pr[o]); pi[o]=gelu_f(pi[o]); }
    float qr[8], qi[8];
#pragma unroll
    for (int oo=0;oo<8;oo++){ int o=half*8+oo; qr[oo]=Bb2[o]; qi[oo]=Bb3[o]; }
#pragma unroll
    for (int i=0;i<16;i++){
      float prv = pr[i], piv = pi[i];
#pragma unroll
      for (int o4=0;o4<2;o4++){
        float4 wr = *(const float4*)(W2R + i*16 + half*8 + o4*4);
        float4 wi = *(const float4*)(W2I + i*16 + half*8 + o4*4);
        qr[o4*4+0] += prv*wr.x - piv*wi.x;  qi[o4*4+0] += piv*wr.x + prv*wi.x;
        qr[o4*4+1] += prv*wr.y - piv*wi.y;  qi[o4*4+1] += piv*wr.y + prv*wi.y;
        qr[o4*4+2] += prv*wr.z - piv*wi.z;  qi[o4*4+2] += piv*wr.z + prv*wi.z;
        qr[o4*4+3] += prv*wr.w - piv*wi.w;  qi[o4*4+3] += piv*wr.w + prv*wi.w;
      }
    }
    float* d = U2 + ((h>>2)&1)*PH2 + ((h>>3)*4+(h&3))*136 + 2*(nb0*16+half*8);
#pragma unroll
    for (int j=0;j<4;j++){
      *(float4*)(d + 4*j) = make_float4(tf32f(qr[2*j]), tf32f(qi[2*j]),
                                        tf32f(qr[2*j+1]), tf32f(qi[2*j+1]));
    }
  }
  __syncthreads();
  float4 C3[2][4][2];
#pragma unroll
  for (int a=0;a<2;a++)
#pragma unroll
    for (int m=0;m<4;m++)
#pragma unroll
      for (int n=0;n<2;n++) C3[a][m][n] = make_float4(0.f,0.f,0.f,0.f);
#pragma unroll
  for (int kk=0; kk<4; kk++){
    int sb = (kk*4+rid)*136;
    float b00 = U2[sb + warp*16 + qid];
    float b01 = U2[PH2 + sb + warp*16 + qid];
    float b10 = U2[sb + warp*16 + 8 + qid];
    float b11 = U2[PH2 + sb + warp*16 + 8 + qid];
#pragma unroll
    for (int mat=0; mat<2; mat++){
#pragma unroll
      for (int mt=0; mt<4; mt++){
        float4 af = __ldg(&g_A4Wi[((mat*4+kk)*4+mt)*32 + lane]);
        mma8(C3[mat][mt][0], af.x,af.y,af.z,af.w, b00, b01);
        mma8(C3[mat][mt][1], af.x,af.y,af.z,af.w, b10, b11);
      }
    }
  }
#pragma unroll
  for (int mt=0; mt<4; mt++)
#pragma unroll
    for (int nt=0; nt<2; nt++){
      float4 cc = C3[0][mt][nt], cs = C3[1][mt][nt];
      int c2 = warp*8+nt*4+rid, y0 = mt*16+qid;
      gs[(size_t)y0*32768 + c2]     = bf2(cc.x-cs.y, cc.y+cs.x);
      gs[(size_t)(y0+8)*32768 + c2] = bf2(cc.z-cs.w, cc.w+cs.z);
    }
}

// ---------------- K7: inverse rfft over L + residual ----------------
__global__ void __launch_bounds__(128) k_inv_l(const float* __restrict__ xin, float* __restrict__ out){
  __shared__ float2 tw[32];
  if (threadIdx.x < 32) tw[threadIdx.x] = TW32[threadIdx.x];
  __syncthreads();
  int site = blockIdx.x*2 + (threadIdx.x>>6);
  int c = threadIdx.x & 63;
  const uint2* ip = (const uint2*)g_s3h + (size_t)site*512 + c;
  float2 Xr[8], Xi[8];
#pragma unroll
  for (int l=0;l<8;l++){
    uint2 v = ip[l*64];
    float2 f0 = unbf2(v.x), f1 = unbf2(v.y);
    Xr[l] = make_float2(f0.x, f1.x);
    Xi[l] = make_float2(f0.y, f1.y);
  }
#pragma unroll
  for (int l=1;l<8;l++){ Xr[l].x*=2.f; Xr[l].y*=2.f; Xi[l].x*=2.f; Xi[l].y*=2.f; }
  const float s = 0.1767766952966369f;
  const float2* rp = (const float2*)(xin + (size_t)site*4096) + c;
  float2* op = (float2*)(out + (size_t)site*4096) + c;
#pragma unroll
  for (int t=0;t<16;t++){
    float2 E = Xr[0];
    float2 O = make_float2(0.f,0.f);
#pragma unroll
    for (int j=1;j<4;j++){
      float2 we = tw[(2*j*t)&31];
      E.x += Xr[2*j].x*we.x - Xi[2*j].x*we.y;
      E.y += Xr[2*j].y*we.x - Xi[2*j].y*we.y;
    }
#pragma unroll
    for (int j=0;j<4;j++){
      float2 wo = tw[((2*j+1)*t)&31];
      O.x += Xr[2*j+1].x*wo.x - Xi[2*j+1].x*wo.y;
      O.y += Xr[2*j+1].y*wo.x - Xi[2*j+1].y*wo.y;
    }
    float2 r0 = rp[t*64], r1 = rp[(t+16)*64];
    op[t*64]      = make_float2(fmaf(E.x+O.x, s, r0.x), fmaf(E.y+O.y, s, r0.y));
    op[(t+16)*64] = make_float2(fmaf(E.x-O.x, s, r1.x), fmaf(E.y-O.y, s, r1.y));
  }
}

// ---------------- launch ----------------
extern "C" void kernel_launch(void* const* d_in, const int* in_sizes, int n_in,
                              void* d_out, int out_size){
  (void)in_sizes; (void)n_in; (void)out_size;
  const float* x = (const float*)d_in[0];
  void *ps3, *ps2, *pah;
  cudaGetSymbolAddress(&ps3, g_s3h);
  cudaGetSymbolAddress(&ps2, g_s2h);
  cudaGetSymbolAddress(&pah, g_A4H);
  const unsigned* s3 = (const unsigned*)ps3;
  const unsigned* s2 = (const unsigned*)ps2;
  const uint4* ah = (const uint4*)pah;
  cudaFuncSetAttribute(k_mid, cudaFuncAttributeMaxDynamicSharedMemorySize, 69696);

  k_prep<<<8,256>>>((const float*)d_in[1], (const float*)d_in[2], (const float*)d_in[3],
                    (const float*)d_in[4], (const float*)d_in[5], (const float*)d_in[6],
                    (const float*)d_in[7], (const float*)d_in[8], (const float*)d_in[9],
                    (const float*)d_in[10], (const float*)d_in[11], (const float*)d_in[12],
                    (const float*)d_in[13]);
  k_init4<<<8,256>>>();
  k_init4h<<<4,256>>>();
  k_fwd_l<<<8192,128>>>(x);
  // fwd W: Out[32 w][1024C] = T @ In[64 xx][1024C], 256 (b,y) batches
  k_dft_mma<32,64, 1,8><<<dim3(32,256),128>>>(s3, (unsigned*)s2, ah, 65536, 32768);
  // fwd H + MLP + inv H, in place on g_s2h
  k_mid<<<dim3(512,4),256,69696>>>();
  // inv W: Out[64 xx][1024C] = T @ In[32 w][1024C]
  k_dft_mma<64,32,-1,6><<<dim3(32,256),128>>>(s2, (unsigned*)s3, ah + 512, 32768, 65536);
  k_inv_l<<<8192,128>>>(x, (float*)d_out);
}

// round 13
// speedup vs baseline: 1.2478x; 1.0567x over previous
#include <cuda_runtime.h>
#include <cuda_bf16.h>
#include <math.h>

// ---------------- scratch (bf16x2 complex intermediates) ----------------
__device__ __align__(16) unsigned g_s3h[16777216]; // [4][64][64][8][128] complexes (bf16 re,im)
__device__ __align__(16) unsigned g_s2h[8388608];  // [4][64][32][8][128] complexes
__device__ __align__(16) float  g_W[8192];
__device__ __align__(16) float  g_Bias[512];
__device__ __align__(16) uint4  g_A4H[1024];       // bf16 m16n8k16 fragments: [fwd M32K64: 512 | inv M64K32: 512]

__constant__ float2 TW32[32] = {
  { 1.000000000f, 0.000000000f},{ 0.980785280f, 0.195090322f},{ 0.923879533f, 0.382683432f},{ 0.831469612f, 0.555570233f},
  { 0.707106781f, 0.707106781f},{ 0.555570233f, 0.831469612f},{ 0.382683432f, 0.923879533f},{ 0.195090322f, 0.980785280f},
  { 0.000000000f, 1.000000000f},{-0.195090322f, 0.980785280f},{-0.382683432f, 0.923879533f},{-0.555570233f, 0.831469612f},
  {-0.707106781f, 0.707106781f},{-0.831469612f, 0.555570233f},{-0.923879533f, 0.382683432f},{-0.980785280f, 0.195090322f},
  {-1.000000000f, 0.000000000f},{-0.980785280f,-0.195090322f},{-0.923879533f,-0.382683432f},{-0.831469612f,-0.555570233f},
  {-0.707106781f,-0.707106781f},{-0.555570233f,-0.831469612f},{-0.382683432f,-0.923879533f},{-0.195090322f,-0.980785280f},
  { 0.000000000f,-1.000000000f},{ 0.195090322f,-0.980785280f},{ 0.382683432f,-0.923879533f},{ 0.555570233f,-0.831469612f},
  { 0.707106781f,-0.707106781f},{ 0.831469612f,-0.555570233f},{ 0.923879533f,-0.382683432f},{ 0.980785280f,-0.195090322f}
};

__device__ __forceinline__ float gelu_f(float v){
  return 0.5f*v*(1.0f+erff(v*0.7071067811865476f));
}
__device__ __forceinline__ unsigned bf2(float a, float b){
  __nv_bfloat162 h = __floats2bfloat162_rn(a, b);
  return *reinterpret_cast<unsigned*>(&h);
}
__device__ __forceinline__ float2 unbf2(unsigned u){
  __nv_bfloat162 h = *reinterpret_cast<__nv_bfloat162*>(&u);
  return __bfloat1622float2(h);
}
__device__ __forceinline__ void mma16(float4& d, uint4 a, unsigned b0, unsigned b1){
  asm volatile("mma.sync.aligned.m16n8k16.row.col.f32.bf16.bf16.f32 "
    "{%0,%1,%2,%3}, {%4,%5,%6,%7}, {%8,%9}, {%0,%1,%2,%3};"
    : "+f"(d.x), "+f"(d.y), "+f"(d.z), "+f"(d.w)
    : "r"(a.x), "r"(a.y), "r"(a.z), "r"(a.w), "r"(b0), "r"(b1));
}

// ---------------- K0a: bf16 m16n8k16 twiddle fragments ----------------
__global__ void k_init4h(){
  int j = blockIdx.x*256 + threadIdx.x;   // 0..1023
  int lane = j&31, qid = lane>>2, rid = lane&3;
  int which = j>>9, t = j&511;
  int mat, kk16, mt;
  if (which==0){ mt=(t>>5)&1; kk16=(t>>6)&3; mat=t>>8; }   // fwd: M=32,K=64
  else         { mt=(t>>5)&3; kk16=(t>>7)&1; mat=t>>8; }   // inv: M=64,K=32
  int r0 = mt*16+qid, r1 = r0+8, k0 = kk16*16 + 2*rid;
  float v[8];
#pragma unroll
  for (int q=0; q<8; q++){
    int m = (q&1) ? r1 : r0;
    int k = k0 + (q>>2)*8 + ((q>>1)&1);
    double a = (double)(m*k)/32.0;
    v[q] = (float)((mat ? sinpi(a) : cospi(a))*0.125);
  }
  g_A4H[j] = make_uint4(bf2(v[0],v[2]), bf2(v[1],v[3]), bf2(v[4],v[6]), bf2(v[5],v[7]));
}

// ---------------- K0: fold HydraLoRA ----------------
__global__ void k_prep(const float* __restrict__ w1, const float* __restrict__ b1,
                       const float* __restrict__ w2, const float* __restrict__ b2,
                       const float* __restrict__ A1r, const float* __restrict__ B1r,
                       const float* __restrict__ A1i, const float* __restrict__ B1i,
                       const float* __restrict__ A2r, const float* __restrict__ B2r,
                       const float* __restrict__ A2i, const float* __restrict__ B2i,
                       const float* __restrict__ ew){
  int k  = blockIdx.x;
  int io = threadIdx.x;
  int i = io >> 4, o = io & 15;
  float e0 = ew[0], e1 = ew[1], e2 = ew[2], e3 = ew[3];
  const float s = 0.03125f;
  const float* Ws[4] = { w1 + k*256, w1 + 2048 + k*256, w2 + k*256, w2 + 2048 + k*256 };
  const float* As[4] = { A1r + k*512, A1i + k*512, A2r + k*512, A2i + k*512 };
  const float* Bs[4] = { B1r + k*2048, B1i + k*2048, B2r + k*2048, B2i + k*2048 };
#pragma unroll
  for (int m = 0; m < 4; m++){
    const float* A  = As[m] + i*32;
    const float* Bb = Bs[m];
    float acc = 0.f;
    for (int r = 0; r < 32; r++){
      float bm = e0*Bb[r*16+o] + e1*Bb[512+r*16+o] + e2*Bb[1024+r*16+o] + e3*Bb[1536+r*16+o];
      acc = fmaf(A[r], bm, acc);
    }
    g_W[((m*8+k)*16+i)*16+o] = Ws[m][i*16+o] + s*acc;
  }
  if (io < 16){
    float b10 = b1[k*16+io], b11 = b1[128+k*16+io];
    float b20 = b2[k*16+io], b21 = b2[128+k*16+io];
    g_Bias[      k*16+io] = b10 - b11;
    g_Bias[128 + k*16+io] = b10 + b11;
    g_Bias[256 + k*16+io] = b20 - b21;
    g_Bias[384 + k*16+io] = b20 + b21;
  }
}

// ---------------- K1: forward rfft over L ----------------
__global__ void __launch_bounds__(128) k_fwd_l(const float* __restrict__ x){
  __shared__ float2 tw[32];
  if (threadIdx.x < 32) tw[threadIdx.x] = TW32[threadIdx.x];
  __syncthreads();
  int site = blockIdx.x*2 + (threadIdx.x>>6);
  int c = threadIdx.x & 63;
  const float2* xp = (const float2*)(x + (size_t)site*4096) + c;
  float2 u[16], dd[16];
#pragma unroll
  for (int t=0;t<16;t++){
    float2 a = xp[t*64], b2 = xp[(t+16)*64];
    u[t]  = make_float2(a.x+b2.x, a.y+b2.y);
    dd[t] = make_float2(a.x-b2.x, a.y-b2.y);
  }
  float2 ar[8], ai[8];
#pragma unroll
  for (int l=0;l<8;l++){ ar[l]=make_float2(0.f,0.f); ai[l]=make_float2(0.f,0.f); }
#pragma unroll
  for (int t=0;t<16;t++){
#pragma unroll
    for (int j=0;j<4;j++){
      float2 we = tw[(t*2*j)&31];
      ar[2*j].x = fmaf( u[t].x, we.x, ar[2*j].x);
      ar[2*j].y = fmaf( u[t].y, we.x, ar[2*j].y);
      ai[2*j].x = fmaf(-u[t].x, we.y, ai[2*j].x);
      ai[2*j].y = fmaf(-u[t].y, we.y, ai[2*j].y);
      float2 wo = tw[(t*(2*j+1))&31];
      ar[2*j+1].x = fmaf( dd[t].x, wo.x, ar[2*j+1].x);
      ar[2*j+1].y = fmaf( dd[t].y, wo.x, ar[2*j+1].y);
      ai[2*j+1].x = fmaf(-dd[t].x, wo.y, ai[2*j+1].x);
      ai[2*j+1].y = fmaf(-dd[t].y, wo.y, ai[2*j+1].y);
    }
  }
  const float s = 0.1767766952966369f;
  uint2* op = (uint2*)g_s3h + (size_t)site*512 + c;
#pragma unroll
  for (int l=0;l<8;l++)
    op[l*64] = make_uint2(bf2(ar[l].x*s, ai[l].x*s), bf2(ar[l].y*s, ai[l].y*s));
}

// ---------------- complex DFT GEMM (bf16 m16n8k16, paired-k B layout) ----------------
template<int M, int K, int SGN, int MINB>
__global__ void __launch_bounds__(128, MINB) k_dft_mma(const unsigned* __restrict__ in,
                                                 unsigned* __restrict__ out,
                                                 const uint4* __restrict__ A4,
                                                 size_t inStrideC, size_t outStrideC){
  constexpr int KT16 = K/16;
  constexpr int MT = M/16;
  constexpr int K2 = K/2;
  __shared__ __align__(16) unsigned Bs[K2*72];
  int tid = threadIdx.x;
  const unsigned* src = in + blockIdx.y*inStrideC + blockIdx.x*32;
  for (int i = tid; i < K2*16; i += 128){
    int k2 = i>>4, j2p = i&15;
    uint2 a = *(const uint2*)(src + (size_t)(2*k2)*1024 + 2*j2p);
    uint2 b = *(const uint2*)(src + (size_t)(2*k2+1)*1024 + 2*j2p);
    *(uint4*)(Bs + k2*72 + 4*j2p) = make_uint4(
      __byte_perm(a.x, b.x, 0x5410), __byte_perm(a.x, b.x, 0x7632),
      __byte_perm(a.y, b.y, 0x5410), __byte_perm(a.y, b.y, 0x7632));
  }
  __syncthreads();
  int warp = tid>>5, lane = tid&31;
  int qid = lane>>2, rid = lane&3;
  int wcol = warp*16;
  float4 C[2][MT][2];
#pragma unroll
  for (int a=0;a<2;a++)
#pragma unroll
    for (int b=0;b<MT;b++)
#pragma unroll
      for (int c=0;c<2;c++) C[a][b][c] = make_float4(0.f,0.f,0.f,0.f);
#pragma unroll
  for (int kk=0; kk<KT16; kk++){
    int s0 = (kk*8 + rid)*72, s1 = (kk*8 + rid + 4)*72;
    unsigned b0n0 = Bs[s0 + wcol + qid];
    unsigned b1n0 = Bs[s1 + wcol + qid];
    unsigned b0n1 = Bs[s0 + wcol + 8 + qid];
    unsigned b1n1 = Bs[s1 + wcol + 8 + qid];
#pragma unroll
    for (int mm=0; mm<2; mm++){
#pragma unroll
      for (int mt=0; mt<MT; mt++){
        uint4 af = __ldg(A4 + ((mm*KT16+kk)*MT+mt)*32 + lane);
        mma16(C[mm][mt][0], af, b0n0, b1n0);
        mma16(C[mm][mt][1], af, b0n1, b1n1);
      }
    }
  }
  unsigned* ob = out + blockIdx.y*outStrideC + blockIdx.x*32;
#pragma unroll
  for (int mt=0; mt<MT; mt++){
#pragma unroll
    for (int nt=0; nt<2; nt++){
      float4 cr = C[0][mt][nt], ci = C[1][mt][nt];
      int colC = warp*8 + nt*4 + rid;
      int m0 = mt*16 + qid;
      if (SGN > 0){
        ob[(size_t)m0*1024 + colC]     = bf2(cr.x + ci.y, cr.y - ci.x);
        ob[(size_t)(m0+8)*1024 + colC] = bf2(cr.z + ci.w, cr.w - ci.z);
      } else {
        ob[(size_t)m0*1024 + colC]     = bf2(cr.x - ci.y, cr.y + ci.x);
        ob[(size_t)(m0+8)*1024 + colC] = bf2(cr.z - ci.w, cr.w + ci.z);
      }
    }
  }
}

// ---------------- K_mid: fwd-H + MLP + inv-H in place (bf16 mma16 both GEMMs) ----------------
// smem: sW[4096 f]@0 | sBias[272 f]@4096 | U[4352 u]@4368 | U2[2176 u]@8720 = 43584 B
__global__ void __launch_bounds__(256,3) k_mid(){
  extern __shared__ float sm[];
  float* sW    = sm;
  float* sBias = sm + 4096;
  unsigned* U  = (unsigned*)(sm + 4368);   // 32 k2-slices x 136 words (GEMM1 B)
  unsigned* U2 = (unsigned*)(sm + 8720);   // 16 k2-slices x 136 words (GEMM2 B)
  int tid = threadIdx.x;
  int bx = blockIdx.x, b = blockIdx.y;
  int w = bx>>4, l = (bx>>1)&7, chalf = bx&1;
  for (int i=tid; i<1024; i+=256){
    int mg=i>>8, nb0=(i>>6)&3;
    ((float4*)sW)[i] = ((const float4*)g_W)[(mg*8+chalf*4+nb0)*64 + (i&63)];
  }
  { int mg=tid>>6, nb0=(tid>>4)&3, o=tid&15;
    sBias[(mg*4+nb0)*17+o] = g_Bias[mg*128 + (chalf*4+nb0)*16 + o]; }
  unsigned* gs = g_s2h + (size_t)b*2097152 + (size_t)w*1024 + l*128 + chalf*64;
  // stage GEMM1 B: pack (y=2k2, 2k2+1) bf16 pairs per float column (128 cols)
  for (int i=tid; i<1024; i+=256){
    int k2 = i>>5, j2p = i&31;
    uint2 a = *(const uint2*)(gs + (size_t)(2*k2)*32768 + 2*j2p);
    uint2 bb = *(const uint2*)(gs + (size_t)(2*k2+1)*32768 + 2*j2p);
    *(uint4*)(U + k2*136 + 4*j2p) = make_uint4(
      __byte_perm(a.x, bb.x, 0x5410), __byte_perm(a.x, bb.x, 0x7632),
      __byte_perm(a.y, bb.y, 0x5410), __byte_perm(a.y, bb.y, 0x7632));
  }
  __syncthreads();
  int warp=tid>>5, lane=tid&31, qid=lane>>2, rid=lane&3;
  int wcol = warp*16;
  // GEMM1 fwd-H: M=32, K=64(y), N=128, bf16 mma16
  float4 C1[2][2][2];
#pragma unroll
  for (int a=0;a<2;a++)
#pragma unroll
    for (int m=0;m<2;m++)
#pragma unroll
      for (int n=0;n<2;n++) C1[a][m][n] = make_float4(0.f,0.f,0.f,0.f);
#pragma unroll
  for (int kk=0; kk<4; kk++){
    int s0 = (kk*8+rid)*136, s1 = (kk*8+rid+4)*136;
    unsigned b0n0 = U[s0 + wcol + qid];
    unsigned b1n0 = U[s1 + wcol + qid];
    unsigned b0n1 = U[s0 + wcol + 8 + qid];
    unsigned b1n1 = U[s1 + wcol + 8 + qid];
#pragma unroll
    for (int mat=0; mat<2; mat++){
#pragma unroll
      for (int mt=0; mt<2; mt++){
        uint4 af = __ldg(&g_A4H[((mat*4+kk)*2+mt)*32 + lane]);
        mma16(C1[mat][mt][0], af, b0n0, b1n0);
        mma16(C1[mat][mt][1], af, b0n1, b1n1);
      }
    }
  }
  __syncthreads();
  float2* sSpec = (float2*)U;   // 32 h-rows x stride 65 f2 (16640 B <= 17408 B)
#pragma unroll
  for (int mt=0; mt<2; mt++)
#pragma unroll
    for (int nt=0; nt<2; nt++){
      float4 cc = C1[0][mt][nt], cs = C1[1][mt][nt];
      int c2 = warp*8+nt*4+rid, h0 = mt*16+qid;
      sSpec[h0*65 + c2]     = make_float2(cc.x+cs.y, cc.y-cs.x);
      sSpec[(h0+8)*65 + c2] = make_float2(cc.z+cs.w, cc.w-cs.z);
    }
  __syncthreads();
  // MLP: inst=(nb0,h), 2 threads each (half); outputs stored bf16 into paired layout
  {
    int inst=tid>>1, half=tid&1, nb0=inst>>5, h=inst&31;
    const float* W1R = sW + nb0*256;
    const float* W1I = sW + (4+nb0)*256;
    const float* W2R = sW + (8+nb0)*256;
    const float* W2I = sW + (12+nb0)*256;
    const float* Bb0 = sBias + nb0*17;
    const float* Bb1 = sBias + (4+nb0)*17;
    const float* Bb2 = sBias + (8+nb0)*17;
    const float* Bb3 = sBias + (12+nb0)*17;
    float xr[16], xi[16];
#pragma unroll
    for (int i=0;i<16;i++){ float2 v = sSpec[h*65 + nb0*16 + i]; xr[i]=v.x; xi[i]=v.y; }
    float pr[16], pi[16];
#pragma unroll
    for (int o=0;o<16;o++){ pr[o]=Bb0[o]; pi[o]=Bb1[o]; }
#pragma unroll
    for (int i=0;i<16;i++){
      float xrv = xr[i], xiv = xi[i];
#pragma unroll
      for (int o4=0;o4<4;o4++){
        float4 wr = *(const float4*)(W1R + i*16 + o4*4);
        float4 wi = *(const float4*)(W1I + i*16 + o4*4);
        pr[o4*4+0] += xrv*wr.x - xiv*wi.x;  pi[o4*4+0] += xiv*wr.x + xrv*wi.x;
        pr[o4*4+1] += xrv*wr.y - xiv*wi.y;  pi[o4*4+1] += xiv*wr.y + xrv*wi.y;
        pr[o4*4+2] += xrv*wr.z - xiv*wi.z;  pi[o4*4+2] += xiv*wr.z + xrv*wi.z;
        pr[o4*4+3] += xrv*wr.w - xiv*wi.w;  pi[o4*4+3] += xiv*wr.w + xrv*wi.w;
      }
    }
#pragma unroll
    for (int o=0;o<16;o++){ pr[o]=gelu_f(pr[o]); pi[o]=gelu_f(pi[o]); }
    float qr[8], qi[8];
#pragma unroll
    for (int oo=0;oo<8;oo++){ int o=half*8+oo; qr[oo]=Bb2[o]; qi[oo]=Bb3[o]; }
#pragma unroll
    for (int i=0;i<16;i++){
      float prv = pr[i], piv = pi[i];
#pragma unroll
      for (int o4=0;o4<2;o4++){
        float4 wr = *(const float4*)(W2R + i*16 + half*8 + o4*4);
        float4 wi = *(const float4*)(W2I + i*16 + half*8 + o4*4);
        qr[o4*4+0] += prv*wr.x - piv*wi.x;  qi[o4*4+0] += piv*wr.x + prv*wi.x;
        qr[o4*4+1] += prv*wr.y - piv*wi.y;  qi[o4*4+1] += piv*wr.y + prv*wi.y;
        qr[o4*4+2] += prv*wr.z - piv*wi.z;  qi[o4*4+2] += piv*wr.z + prv*wi.z;
        qr[o4*4+3] += prv*wr.w - piv*wi.w;  qi[o4*4+3] += piv*wr.w + prv*wi.w;
      }
    }
    // 16-bit stores into paired layout: word (h>>1)*136 + n, half-word = h&1
    __nv_bfloat16* d16 = (__nv_bfloat16*)U2;
    int base = ((h>>1)*136)*2 + (h&1);
#pragma unroll
    for (int oo=0;oo<8;oo++){
      int n_re = 2*(nb0*16 + half*8 + oo);
      d16[base + n_re*2]     = __float2bfloat16_rn(qr[oo]);
      d16[base + (n_re+1)*2] = __float2bfloat16_rn(qi[oo]);
    }
  }
  __syncthreads();
  // GEMM2 inv-H: M=64, K=32(h), N=128, bf16 mma16
  float4 C3[2][4][2];
#pragma unroll
  for (int a=0;a<2;a++)
#pragma unroll
    for (int m=0;m<4;m++)
#pragma unroll
      for (int n=0;n<2;n++) C3[a][m][n] = make_float4(0.f,0.f,0.f,0.f);
#pragma unroll
  for (int kk=0; kk<2; kk++){
    int s0 = (kk*8+rid)*136, s1 = (kk*8+rid+4)*136;
    unsigned b0n0 = U2[s0 + wcol + qid];
    unsigned b1n0 = U2[s1 + wcol + qid];
    unsigned b0n1 = U2[s0 + wcol + 8 + qid];
    unsigned b1n1 = U2[s1 + wcol + 8 + qid];
#pragma unroll
    for (int mat=0; mat<2; mat++){
#pragma unroll
      for (int mt=0; mt<4; mt++){
        uint4 af = __ldg(&g_A4H[512 + ((mat*2+kk)*4+mt)*32 + lane]);
        mma16(C3[mat][mt][0], af, b0n0, b1n0);
        mma16(C3[mat][mt][1], af, b0n1, b1n1);
      }
    }
  }
#pragma unroll
  for (int mt=0; mt<4; mt++)
#pragma unroll
    for (int nt=0; nt<2; nt++){
      float4 cc = C3[0][mt][nt], cs = C3[1][mt][nt];
      int c2 = warp*8+nt*4+rid, y0 = mt*16+qid;
      gs[(size_t)y0*32768 + c2]     = bf2(cc.x-cs.y, cc.y+cs.x);
      gs[(size_t)(y0+8)*32768 + c2] = bf2(cc.z-cs.w, cc.w+cs.z);
    }
}

// ---------------- K7: inverse rfft over L + residual ----------------
__global__ void __launch_bounds__(128) k_inv_l(const float* __restrict__ xin, float* __restrict__ out){
  __shared__ float2 tw[32];
  if (threadIdx.x < 32) tw[threadIdx.x] = TW32[threadIdx.x];
  __syncthreads();
  int site = blockIdx.x*2 + (threadIdx.x>>6);
  int c = threadIdx.x & 63;
  const uint2* ip = (const uint2*)g_s3h + (size_t)site*512 + c;
  float2 Xr[8], Xi[8];
#pragma unroll
  for (int l=0;l<8;l++){
    uint2 v = ip[l*64];
    float2 f0 = unbf2(v.x), f1 = unbf2(v.y);
    Xr[l] = make_float2(f0.x, f1.x);
    Xi[l] = make_float2(f0.y, f1.y);
  }
#pragma unroll
  for (int l=1;l<8;l++){ Xr[l].x*=2.f; Xr[l].y*=2.f; Xi[l].x*=2.f; Xi[l].y*=2.f; }
  const float s = 0.1767766952966369f;
  const float2* rp = (const float2*)(xin + (size_t)site*4096) + c;
  float2* op = (float2*)(out + (size_t)site*4096) + c;
#pragma unroll
  for (int t=0;t<16;t++){
    float2 E = Xr[0];
    float2 O = make_float2(0.f,0.f);
#pragma unroll
    for (int j=1;j<4;j++){
      float2 we = tw[(2*j*t)&31];
      E.x += Xr[2*j].x*we.x - Xi[2*j].x*we.y;
      E.y += Xr[2*j].y*we.x - Xi[2*j].y*we.y;
    }
#pragma unroll
    for (int j=0;j<4;j++){
      float2 wo = tw[((2*j+1)*t)&31];
      O.x += Xr[2*j+1].x*wo.x - Xi[2*j+1].x*wo.y;
      O.y += Xr[2*j+1].y*wo.x - Xi[2*j+1].y*wo.y;
    }
    float2 r0 = rp[t*64], r1 = rp[(t+16)*64];
    op[t*64]      = make_float2(fmaf(E.x+O.x, s, r0.x), fmaf(E.y+O.y, s, r0.y));
    op[(t+16)*64] = make_float2(fmaf(E.x-O.x, s, r1.x), fmaf(E.y-O.y, s, r1.y));
  }
}

// ---------------- launch ----------------
extern "C" void kernel_launch(void* const* d_in, const int* in_sizes, int n_in,
                              void* d_out, int out_size){
  (void)in_sizes; (void)n_in; (void)out_size;
  const float* x = (const float*)d_in[0];
  void *ps3, *ps2, *pah;
  cudaGetSymbolAddress(&ps3, g_s3h);
  cudaGetSymbolAddress(&ps2, g_s2h);
  cudaGetSymbolAddress(&pah, g_A4H);
  const unsigned* s3 = (const unsigned*)ps3;
  const unsigned* s2 = (const unsigned*)ps2;
  const uint4* ah = (const uint4*)pah;
  cudaFuncSetAttribute(k_mid, cudaFuncAttributeMaxDynamicSharedMemorySize, 43584);

  k_prep<<<8,256>>>((const float*)d_in[1], (const float*)d_in[2], (const float*)d_in[3],
                    (const float*)d_in[4], (const float*)d_in[5], (const float*)d_in[6],
                    (const float*)d_in[7], (const float*)d_in[8], (const float*)d_in[9],
                    (const float*)d_in[10], (const float*)d_in[11], (const float*)d_in[12],
                    (const float*)d_in[13]);
  k_init4h<<<4,256>>>();
  k_fwd_l<<<8192,128>>>(x);
  // fwd W: Out[32 w][1024C] = T @ In[64 xx][1024C], 256 (b,y) batches
  k_dft_mma<32,64, 1,8><<<dim3(32,256),128>>>(s3, (unsigned*)s2, ah, 65536, 32768);
  // fwd H + MLP + inv H, in place on g_s2h
  k_mid<<<dim3(512,4),256,43584>>>();
  // inv W: Out[64 xx][1024C] = T @ In[32 w][1024C]
  k_dft_mma<64,32,-1,6><<<dim3(32,256),128>>>(s2, (unsigned*)s3, ah + 512, 32768, 65536);
  k_inv_l<<<8192,128>>>(x, (float*)d_out);
}

// round 14
// speedup vs baseline: 1.3202x; 1.0580x over previous
#include <cuda_runtime.h>
#include <cuda_bf16.h>
#include <math.h>

// ---------------- scratch (bf16x2 complex intermediates) ----------------
__device__ __align__(16) unsigned g_s3h[16777216]; // [4][64][64][8][128] complexes (bf16 re,im)
__device__ __align__(16) unsigned g_s2h[8388608];  // [4][64][32][8][128] complexes
__device__ __align__(16) float  g_W[8192];
__device__ __align__(16) float  g_Bias[512];
__device__ __align__(16) uint4  g_A4H[1024];       // bf16 m16n8k16 fragments: [fwd M32K64: 512 | inv M64K32: 512]

__constant__ float2 TW32[32] = {
  { 1.000000000f, 0.000000000f},{ 0.980785280f, 0.195090322f},{ 0.923879533f, 0.382683432f},{ 0.831469612f, 0.555570233f},
  { 0.707106781f, 0.707106781f},{ 0.555570233f, 0.831469612f},{ 0.382683432f, 0.923879533f},{ 0.195090322f, 0.980785280f},
  { 0.000000000f, 1.000000000f},{-0.195090322f, 0.980785280f},{-0.382683432f, 0.923879533f},{-0.555570233f, 0.831469612f},
  {-0.707106781f, 0.707106781f},{-0.831469612f, 0.555570233f},{-0.923879533f, 0.382683432f},{-0.980785280f, 0.195090322f},
  {-1.000000000f, 0.000000000f},{-0.980785280f,-0.195090322f},{-0.923879533f,-0.382683432f},{-0.831469612f,-0.555570233f},
  {-0.707106781f,-0.707106781f},{-0.555570233f,-0.831469612f},{-0.382683432f,-0.923879533f},{-0.195090322f,-0.980785280f},
  { 0.000000000f,-1.000000000f},{ 0.195090322f,-0.980785280f},{ 0.382683432f,-0.923879533f},{ 0.555570233f,-0.831469612f},
  { 0.707106781f,-0.707106781f},{ 0.831469612f,-0.555570233f},{ 0.923879533f,-0.382683432f},{ 0.980785280f,-0.195090322f}
};

__device__ __forceinline__ float gelu_f(float v){
  return 0.5f*v*(1.0f+erff(v*0.7071067811865476f));
}
__device__ __forceinline__ unsigned bf2(float a, float b){
  __nv_bfloat162 h = __floats2bfloat162_rn(a, b);
  return *reinterpret_cast<unsigned*>(&h);
}
__device__ __forceinline__ float2 unbf2(unsigned u){
  __nv_bfloat162 h = *reinterpret_cast<__nv_bfloat162*>(&u);
  return __bfloat1622float2(h);
}
__device__ __forceinline__ void mma16(float4& d, uint4 a, unsigned b0, unsigned b1){
  asm volatile("mma.sync.aligned.m16n8k16.row.col.f32.bf16.bf16.f32 "
    "{%0,%1,%2,%3}, {%4,%5,%6,%7}, {%8,%9}, {%0,%1,%2,%3};"
    : "+f"(d.x), "+f"(d.y), "+f"(d.z), "+f"(d.w)
    : "r"(a.x), "r"(a.y), "r"(a.z), "r"(a.w), "r"(b0), "r"(b1));
}

// ---------------- K0a: bf16 m16n8k16 twiddle fragments ----------------
__global__ void k_init4h(){
  int j = blockIdx.x*256 + threadIdx.x;   // 0..1023
  int lane = j&31, qid = lane>>2, rid = lane&3;
  int which = j>>9, t = j&511;
  int mat, kk16, mt;
  if (which==0){ mt=(t>>5)&1; kk16=(t>>6)&3; mat=t>>8; }   // fwd: M=32,K=64
  else         { mt=(t>>5)&3; kk16=(t>>7)&1; mat=t>>8; }   // inv: M=64,K=32
  int r0 = mt*16+qid, r1 = r0+8, k0 = kk16*16 + 2*rid;
  float v[8];
#pragma unroll
  for (int q=0; q<8; q++){
    int m = (q&1) ? r1 : r0;
    int k = k0 + (q>>2)*8 + ((q>>1)&1);
    double a = (double)(m*k)/32.0;
    v[q] = (float)((mat ? sinpi(a) : cospi(a))*0.125);
  }
  g_A4H[j] = make_uint4(bf2(v[0],v[2]), bf2(v[1],v[3]), bf2(v[4],v[6]), bf2(v[5],v[7]));
}

// ---------------- K0: fold HydraLoRA ----------------
__global__ void k_prep(const float* __restrict__ w1, const float* __restrict__ b1,
                       const float* __restrict__ w2, const float* __restrict__ b2,
                       const float* __restrict__ A1r, const float* __restrict__ B1r,
                       const float* __restrict__ A1i, const float* __restrict__ B1i,
                       const float* __restrict__ A2r, const float* __restrict__ B2r,
                       const float* __restrict__ A2i, const float* __restrict__ B2i,
                       const float* __restrict__ ew){
  int k  = blockIdx.x;
  int io = threadIdx.x;
  int i = io >> 4, o = io & 15;
  float e0 = ew[0], e1 = ew[1], e2 = ew[2], e3 = ew[3];
  const float s = 0.03125f;
  const float* Ws[4] = { w1 + k*256, w1 + 2048 + k*256, w2 + k*256, w2 + 2048 + k*256 };
  const float* As[4] = { A1r + k*512, A1i + k*512, A2r + k*512, A2i + k*512 };
  const float* Bs[4] = { B1r + k*2048, B1i + k*2048, B2r + k*2048, B2i + k*2048 };
#pragma unroll
  for (int m = 0; m < 4; m++){
    const float* A  = As[m] + i*32;
    const float* Bb = Bs[m];
    float acc = 0.f;
    for (int r = 0; r < 32; r++){
      float bm = e0*Bb[r*16+o] + e1*Bb[512+r*16+o] + e2*Bb[1024+r*16+o] + e3*Bb[1536+r*16+o];
      acc = fmaf(A[r], bm, acc);
    }
    g_W[((m*8+k)*16+i)*16+o] = Ws[m][i*16+o] + s*acc;
  }
  if (io < 16){
    float b10 = b1[k*16+io], b11 = b1[128+k*16+io];
    float b20 = b2[k*16+io], b21 = b2[128+k*16+io];
    g_Bias[      k*16+io] = b10 - b11;
    g_Bias[128 + k*16+io] = b10 + b11;
    g_Bias[256 + k*16+io] = b20 - b21;
    g_Bias[384 + k*16+io] = b20 + b21;
  }
}

// ---------------- K1: forward rfft over L ----------------
__global__ void __launch_bounds__(128) k_fwd_l(const float* __restrict__ x){
  __shared__ float2 tw[32];
  if (threadIdx.x < 32) tw[threadIdx.x] = TW32[threadIdx.x];
  __syncthreads();
  int site = blockIdx.x*2 + (threadIdx.x>>6);
  int c = threadIdx.x & 63;
  const float2* xp = (const float2*)(x + (size_t)site*4096) + c;
  float2 u[16], dd[16];
#pragma unroll
  for (int t=0;t<16;t++){
    float2 a = xp[t*64], b2 = xp[(t+16)*64];
    u[t]  = make_float2(a.x+b2.x, a.y+b2.y);
    dd[t] = make_float2(a.x-b2.x, a.y-b2.y);
  }
  float2 ar[8], ai[8];
#pragma unroll
  for (int l=0;l<8;l++){ ar[l]=make_float2(0.f,0.f); ai[l]=make_float2(0.f,0.f); }
#pragma unroll
  for (int t=0;t<16;t++){
#pragma unroll
    for (int j=0;j<4;j++){
      float2 we = tw[(t*2*j)&31];
      ar[2*j].x = fmaf( u[t].x, we.x, ar[2*j].x);
      ar[2*j].y = fmaf( u[t].y, we.x, ar[2*j].y);
      ai[2*j].x = fmaf(-u[t].x, we.y, ai[2*j].x);
      ai[2*j].y = fmaf(-u[t].y, we.y, ai[2*j].y);
      float2 wo = tw[(t*(2*j+1))&31];
      ar[2*j+1].x = fmaf( dd[t].x, wo.x, ar[2*j+1].x);
      ar[2*j+1].y = fmaf( dd[t].y, wo.x, ar[2*j+1].y);
      ai[2*j+1].x = fmaf(-dd[t].x, wo.y, ai[2*j+1].x);
      ai[2*j+1].y = fmaf(-dd[t].y, wo.y, ai[2*j+1].y);
    }
  }
  const float s = 0.1767766952966369f;
  uint2* op = (uint2*)g_s3h + (size_t)site*512 + c;
#pragma unroll
  for (int l=0;l<8;l++)
    op[l*64] = make_uint2(bf2(ar[l].x*s, ai[l].x*s), bf2(ar[l].y*s, ai[l].y*s));
}

// ---------------- complex DFT GEMM (bf16 m16n8k16, paired-k B layout) ----------------
template<int M, int K, int SGN, int MINB>
__global__ void __launch_bounds__(128, MINB) k_dft_mma(const unsigned* __restrict__ in,
                                                 unsigned* __restrict__ out,
                                                 const uint4* __restrict__ A4,
                                                 size_t inStrideC, size_t outStrideC){
  constexpr int KT16 = K/16;
  constexpr int MT = M/16;
  constexpr int K2 = K/2;
  __shared__ __align__(16) unsigned Bs[K2*72];
  int tid = threadIdx.x;
  const unsigned* src = in + blockIdx.y*inStrideC + blockIdx.x*32;
  for (int i = tid; i < K2*16; i += 128){
    int k2 = i>>4, j2p = i&15;
    uint2 a = *(const uint2*)(src + (size_t)(2*k2)*1024 + 2*j2p);
    uint2 b = *(const uint2*)(src + (size_t)(2*k2+1)*1024 + 2*j2p);
    *(uint4*)(Bs + k2*72 + 4*j2p) = make_uint4(
      __byte_perm(a.x, b.x, 0x5410), __byte_perm(a.x, b.x, 0x7632),
      __byte_perm(a.y, b.y, 0x5410), __byte_perm(a.y, b.y, 0x7632));
  }
  __syncthreads();
  int warp = tid>>5, lane = tid&31;
  int qid = lane>>2, rid = lane&3;
  int wcol = warp*16;
  float4 C[2][MT][2];
#pragma unroll
  for (int a=0;a<2;a++)
#pragma unroll
    for (int b=0;b<MT;b++)
#pragma unroll
      for (int c=0;c<2;c++) C[a][b][c] = make_float4(0.f,0.f,0.f,0.f);
#pragma unroll
  for (int kk=0; kk<KT16; kk++){
    int s0 = (kk*8 + rid)*72, s1 = (kk*8 + rid + 4)*72;
    unsigned b0n0 = Bs[s0 + wcol + qid];
    unsigned b1n0 = Bs[s1 + wcol + qid];
    unsigned b0n1 = Bs[s0 + wcol + 8 + qid];
    unsigned b1n1 = Bs[s1 + wcol + 8 + qid];
#pragma unroll
    for (int mm=0; mm<2; mm++){
#pragma unroll
      for (int mt=0; mt<MT; mt++){
        uint4 af = __ldg(A4 + ((mm*KT16+kk)*MT+mt)*32 + lane);
        mma16(C[mm][mt][0], af, b0n0, b1n0);
        mma16(C[mm][mt][1], af, b0n1, b1n1);
      }
    }
  }
  unsigned* ob = out + blockIdx.y*outStrideC + blockIdx.x*32;
#pragma unroll
  for (int mt=0; mt<MT; mt++){
#pragma unroll
    for (int nt=0; nt<2; nt++){
      float4 cr = C[0][mt][nt], ci = C[1][mt][nt];
      int colC = warp*8 + nt*4 + rid;
      int m0 = mt*16 + qid;
      if (SGN > 0){
        ob[(size_t)m0*1024 + colC]     = bf2(cr.x + ci.y, cr.y - ci.x);
        ob[(size_t)(m0+8)*1024 + colC] = bf2(cr.z + ci.w, cr.w - ci.z);
      } else {
        ob[(size_t)m0*1024 + colC]     = bf2(cr.x - ci.y, cr.y + ci.x);
        ob[(size_t)(m0+8)*1024 + colC] = bf2(cr.z - ci.w, cr.w + ci.z);
      }
    }
  }
}

// ---------------- K_mid: fwd-H + MLP + inv-H in place (o-split MLP, smem p-exchange) ----------------
// smem: sW[4096 f]@0 | sBias[272 f]@4096 | U[4352 u]@4368 | U2[2176 u]@8720 = 43584 B
__global__ void __launch_bounds__(256,3) k_mid(){
  extern __shared__ float sm[];
  float* sW    = sm;
  float* sBias = sm + 4096;
  unsigned* U  = (unsigned*)(sm + 4368);   // 32 k2-slices x 136 words (GEMM1 B)
  unsigned* U2 = (unsigned*)(sm + 8720);   // 16 k2-slices x 136 words (GEMM2 B)
  int tid = threadIdx.x;
  int bx = blockIdx.x, b = blockIdx.y;
  int w = bx>>4, l = (bx>>1)&7, chalf = bx&1;
  for (int i=tid; i<1024; i+=256){
    int mg=i>>8, nb0=(i>>6)&3;
    ((float4*)sW)[i] = ((const float4*)g_W)[(mg*8+chalf*4+nb0)*64 + (i&63)];
  }
  { int mg=tid>>6, nb0=(tid>>4)&3, o=tid&15;
    sBias[(mg*4+nb0)*17+o] = g_Bias[mg*128 + (chalf*4+nb0)*16 + o]; }
  unsigned* gs = g_s2h + (size_t)b*2097152 + (size_t)w*1024 + l*128 + chalf*64;
  for (int i=tid; i<1024; i+=256){
    int k2 = i>>5, j2p = i&31;
    uint2 a = *(const uint2*)(gs + (size_t)(2*k2)*32768 + 2*j2p);
    uint2 bb = *(const uint2*)(gs + (size_t)(2*k2+1)*32768 + 2*j2p);
    *(uint4*)(U + k2*136 + 4*j2p) = make_uint4(
      __byte_perm(a.x, bb.x, 0x5410), __byte_perm(a.x, bb.x, 0x7632),
      __byte_perm(a.y, bb.y, 0x5410), __byte_perm(a.y, bb.y, 0x7632));
  }
  __syncthreads();
  int warp=tid>>5, lane=tid&31, qid=lane>>2, rid=lane&3;
  int wcol = warp*16;
  // GEMM1 fwd-H: M=32, K=64(y), N=128, bf16 mma16
  float4 C1[2][2][2];
#pragma unroll
  for (int a=0;a<2;a++)
#pragma unroll
    for (int m=0;m<2;m++)
#pragma unroll
      for (int n=0;n<2;n++) C1[a][m][n] = make_float4(0.f,0.f,0.f,0.f);
#pragma unroll
  for (int kk=0; kk<4; kk++){
    int s0 = (kk*8+rid)*136, s1 = (kk*8+rid+4)*136;
    unsigned b0n0 = U[s0 + wcol + qid];
    unsigned b1n0 = U[s1 + wcol + qid];
    unsigned b0n1 = U[s0 + wcol + 8 + qid];
    unsigned b1n1 = U[s1 + wcol + 8 + qid];
#pragma unroll
    for (int mat=0; mat<2; mat++){
#pragma unroll
      for (int mt=0; mt<2; mt++){
        uint4 af = __ldg(&g_A4H[((mat*4+kk)*2+mt)*32 + lane]);
        mma16(C1[mat][mt][0], af, b0n0, b1n0);
        mma16(C1[mat][mt][1], af, b0n1, b1n1);
      }
    }
  }
  __syncthreads();
  float2* sSpec = (float2*)U;   // 32 h-rows x stride 65 f2 (16640 B <= 17408 B)
#pragma unroll
  for (int mt=0; mt<2; mt++)
#pragma unroll
    for (int nt=0; nt<2; nt++){
      float4 cc = C1[0][mt][nt], cs = C1[1][mt][nt];
      int c2 = warp*8+nt*4+rid, h0 = mt*16+qid;
      sSpec[h0*65 + c2]     = make_float2(cc.x+cs.y, cc.y-cs.x);
      sSpec[(h0+8)*65 + c2] = make_float2(cc.z+cs.w, cc.w-cs.z);
    }
  __syncthreads();
  // MLP: inst=(nb0,h), 2 threads each; layer1 o-split, p exchanged in-place via sSpec
  {
    int inst=tid>>1, half=tid&1, nb0=inst>>5, h=inst&31;
    const float* W1R = sW + nb0*256;
    const float* W1I = sW + (4+nb0)*256;
    const float* W2R = sW + (8+nb0)*256;
    const float* W2I = sW + (12+nb0)*256;
    const float* Bb0 = sBias + nb0*17;
    const float* Bb1 = sBias + (4+nb0)*17;
    const float* Bb2 = sBias + (8+nb0)*17;
    const float* Bb3 = sBias + (12+nb0)*17;
    float2* myx = sSpec + h*65 + nb0*16;
    float xr[16], xi[16];
#pragma unroll
    for (int i=0;i<16;i++){ float2 v = myx[i]; xr[i]=v.x; xi[i]=v.y; }
    __syncthreads();   // all x reads done before in-place overwrite
    // layer1: this thread's 8 outputs only
    float pr[8], pi[8];
#pragma unroll
    for (int oo=0;oo<8;oo++){ int o=half*8+oo; pr[oo]=Bb0[o]; pi[oo]=Bb1[o]; }
#pragma unroll
    for (int i=0;i<16;i++){
      float xrv = xr[i], xiv = xi[i];
#pragma unroll
      for (int o4=0;o4<2;o4++){
        float4 wr = *(const float4*)(W1R + i*16 + half*8 + o4*4);
        float4 wi = *(const float4*)(W1I + i*16 + half*8 + o4*4);
        pr[o4*4+0] += xrv*wr.x - xiv*wi.x;  pi[o4*4+0] += xiv*wr.x + xrv*wi.x;
        pr[o4*4+1] += xrv*wr.y - xiv*wi.y;  pi[o4*4+1] += xiv*wr.y + xrv*wi.y;
        pr[o4*4+2] += xrv*wr.z - xiv*wi.z;  pi[o4*4+2] += xiv*wr.z + xrv*wi.z;
        pr[o4*4+3] += xrv*wr.w - xiv*wi.w;  pi[o4*4+3] += xiv*wr.w + xrv*wi.w;
      }
    }
#pragma unroll
    for (int oo=0;oo<8;oo++){ pr[oo]=gelu_f(pr[oo]); pi[oo]=gelu_f(pi[oo]); }
#pragma unroll
    for (int oo=0;oo<8;oo++) myx[half*8+oo] = make_float2(pr[oo], pi[oo]);
    __syncthreads();   // full p visible
    // layer2: this thread's 8 outputs, full p from smem
    float qr[8], qi[8];
#pragma unroll
    for (int oo=0;oo<8;oo++){ int o=half*8+oo; qr[oo]=Bb2[o]; qi[oo]=Bb3[o]; }
#pragma unroll
    for (int i=0;i<16;i++){
      float2 p = myx[i];
#pragma unroll
      for (int o4=0;o4<2;o4++){
        float4 wr = *(const float4*)(W2R + i*16 + half*8 + o4*4);
        float4 wi = *(const float4*)(W2I + i*16 + half*8 + o4*4);
        qr[o4*4+0] += p.x*wr.x - p.y*wi.x;  qi[o4*4+0] += p.y*wr.x + p.x*wi.x;
        qr[o4*4+1] += p.x*wr.y - p.y*wi.y;  qi[o4*4+1] += p.y*wr.y + p.x*wi.y;
        qr[o4*4+2] += p.x*wr.z - p.y*wi.z;  qi[o4*4+2] += p.y*wr.z + p.x*wi.z;
        qr[o4*4+3] += p.x*wr.w - p.y*wi.w;  qi[o4*4+3] += p.y*wr.w + p.x*wi.w;
      }
    }
    // 16-bit stores into paired layout: word (h>>1)*136 + n, half-word = h&1
    __nv_bfloat16* d16 = (__nv_bfloat16*)U2;
    int base = ((h>>1)*136)*2 + (h&1);
#pragma unroll
    for (int oo=0;oo<8;oo++){
      int n_re = 2*(nb0*16 + half*8 + oo);
      d16[base + n_re*2]     = __float2bfloat16_rn(qr[oo]);
      d16[base + (n_re+1)*2] = __float2bfloat16_rn(qi[oo]);
    }
  }
  __syncthreads();
  // GEMM2 inv-H: M=64, K=32(h), N=128, bf16 mma16
  float4 C3[2][4][2];
#pragma unroll
  for (int a=0;a<2;a++)
#pragma unroll
    for (int m=0;m<4;m++)
#pragma unroll
      for (int n=0;n<2;n++) C3[a][m][n] = make_float4(0.f,0.f,0.f,0.f);
#pragma unroll
  for (int kk=0; kk<2; kk++){
    int s0 = (kk*8+rid)*136, s1 = (kk*8+rid+4)*136;
    unsigned b0n0 = U2[s0 + wcol + qid];
    unsigned b1n0 = U2[s1 + wcol + qid];
    unsigned b0n1 = U2[s0 + wcol + 8 + qid];
    unsigned b1n1 = U2[s1 + wcol + 8 + qid];
#pragma unroll
    for (int mat=0; mat<2; mat++){
#pragma unroll
      for (int mt=0; mt<4; mt++){
        uint4 af = __ldg(&g_A4H[512 + ((mat*2+kk)*4+mt)*32 + lane]);
        mma16(C3[mat][mt][0], af, b0n0, b1n0);
        mma16(C3[mat][mt][1], af, b0n1, b1n1);
      }
    }
  }
#pragma unroll
  for (int mt=0; mt<4; mt++)
#pragma unroll
    for (int nt=0; nt<2; nt++){
      float4 cc = C3[0][mt][nt], cs = C3[1][mt][nt];
      int c2 = warp*8+nt*4+rid, y0 = mt*16+qid;
      gs[(size_t)y0*32768 + c2]     = bf2(cc.x-cs.y, cc.y+cs.x);
      gs[(size_t)(y0+8)*32768 + c2] = bf2(cc.z-cs.w, cc.w+cs.z);
    }
}

// ---------------- K7: inverse rfft over L + residual ----------------
__global__ void __launch_bounds__(128) k_inv_l(const float* __restrict__ xin, float* __restrict__ out){
  __shared__ float2 tw[32];
  if (threadIdx.x < 32) tw[threadIdx.x] = TW32[threadIdx.x];
  __syncthreads();
  int site = blockIdx.x*2 + (threadIdx.x>>6);
  int c = threadIdx.x & 63;
  const uint2* ip = (const uint2*)g_s3h + (size_t)site*512 + c;
  float2 Xr[8], Xi[8];
#pragma unroll
  for (int l=0;l<8;l++){
    uint2 v = ip[l*64];
    float2 f0 = unbf2(v.x), f1 = unbf2(v.y);
    Xr[l] = make_float2(f0.x, f1.x);
    Xi[l] = make_float2(f0.y, f1.y);
  }
#pragma unroll
  for (int l=1;l<8;l++){ Xr[l].x*=2.f; Xr[l].y*=2.f; Xi[l].x*=2.f; Xi[l].y*=2.f; }
  const float s = 0.1767766952966369f;
  const float2* rp = (const float2*)(xin + (size_t)site*4096) + c;
  float2* op = (float2*)(out + (size_t)site*4096) + c;
#pragma unroll
  for (int t=0;t<16;t++){
    float2 E = Xr[0];
    float2 O = make_float2(0.f,0.f);
#pragma unroll
    for (int j=1;j<4;j++){
      float2 we = tw[(2*j*t)&31];
      E.x += Xr[2*j].x*we.x - Xi[2*j].x*we.y;
      E.y += Xr[2*j].y*we.x - Xi[2*j].y*we.y;
    }
#pragma unroll
    for (int j=0;j<4;j++){
      float2 wo = tw[((2*j+1)*t)&31];
      O.x += Xr[2*j+1].x*wo.x - Xi[2*j+1].x*wo.y;
      O.y += Xr[2*j+1].y*wo.x - Xi[2*j+1].y*wo.y;
    }
    float2 r0 = rp[t*64], r1 = rp[(t+16)*64];
    op[t*64]      = make_float2(fmaf(E.x+O.x, s, r0.x), fmaf(E.y+O.y, s, r0.y));
    op[(t+16)*64] = make_float2(fmaf(E.x-O.x, s, r1.x), fmaf(E.y-O.y, s, r1.y));
  }
}

// ---------------- launch ----------------
extern "C" void kernel_launch(void* const* d_in, const int* in_sizes, int n_in,
                              void* d_out, int out_size){
  (void)in_sizes; (void)n_in; (void)out_size;
  const float* x = (const float*)d_in[0];
  void *ps3, *ps2, *pah;
  cudaGetSymbolAddress(&ps3, g_s3h);
  cudaGetSymbolAddress(&ps2, g_s2h);
  cudaGetSymbolAddress(&pah, g_A4H);
  const unsigned* s3 = (const unsigned*)ps3;
  const unsigned* s2 = (const unsigned*)ps2;
  const uint4* ah = (const uint4*)pah;
  cudaFuncSetAttribute(k_mid, cudaFuncAttributeMaxDynamicSharedMemorySize, 43584);

  k_prep<<<8,256>>>((const float*)d_in[1], (const float*)d_in[2], (const float*)d_in[3],
                    (const float*)d_in[4], (const float*)d_in[5], (const float*)d_in[6],
                    (const float*)d_in[7], (const float*)d_in[8], (const float*)d_in[9],
                    (const float*)d_in[10], (const float*)d_in[11], (const float*)d_in[12],
                    (const float*)d_in[13]);
  k_init4h<<<4,256>>>();
  k_fwd_l<<<8192,128>>>(x);
  // fwd W: Out[32 w][1024C] = T @ In[64 xx][1024C], 256 (b,y) batches
  k_dft_mma<32,64, 1,8><<<dim3(32,256),128>>>(s3, (unsigned*)s2, ah, 65536, 32768);
  // fwd H + MLP + inv H, in place on g_s2h
  k_mid<<<dim3(512,4),256,43584>>>();
  // inv W: Out[64 xx][1024C] = T @ In[32 w][1024C]
  k_dft_mma<64,32,-1,6><<<dim3(32,256),128>>>(s2, (unsigned*)s3, ah + 512, 32768, 65536);
  k_inv_l<<<8192,128>>>(x, (float*)d_out);
}

// round 15
// speedup vs baseline: 1.3278x; 1.0057x over previous
#include <cuda_runtime.h>
#include <cuda_bf16.h>
#include <math.h>

// ---------------- scratch (bf16x2 complex intermediates) ----------------
__device__ __align__(16) unsigned g_s3h[16777216]; // [4][64][64][8][128] complexes (bf16 re,im)
__device__ __align__(16) unsigned g_s2h[8388608];  // [4][64][32][8][128] complexes
__device__ __align__(16) float  g_W[8192];
__device__ __align__(16) float  g_Bias[512];
__device__ __align__(16) uint4  g_A4H[1024];       // bf16 m16n8k16 fragments: [fwd M32K64: 512 | inv M64K32: 512]

__constant__ float2 TW32[32] = {
  { 1.000000000f, 0.000000000f},{ 0.980785280f, 0.195090322f},{ 0.923879533f, 0.382683432f},{ 0.831469612f, 0.555570233f},
  { 0.707106781f, 0.707106781f},{ 0.555570233f, 0.831469612f},{ 0.382683432f, 0.923879533f},{ 0.195090322f, 0.980785280f},
  { 0.000000000f, 1.000000000f},{-0.195090322f, 0.980785280f},{-0.382683432f, 0.923879533f},{-0.555570233f, 0.831469612f},
  {-0.707106781f, 0.707106781f},{-0.831469612f, 0.555570233f},{-0.923879533f, 0.382683432f},{-0.980785280f, 0.195090322f},
  {-1.000000000f, 0.000000000f},{-0.980785280f,-0.195090322f},{-0.923879533f,-0.382683432f},{-0.831469612f,-0.555570233f},
  {-0.707106781f,-0.707106781f},{-0.555570233f,-0.831469612f},{-0.382683432f,-0.923879533f},{-0.195090322f,-0.980785280f},
  { 0.000000000f,-1.000000000f},{ 0.195090322f,-0.980785280f},{ 0.382683432f,-0.923879533f},{ 0.555570233f,-0.831469612f},
  { 0.707106781f,-0.707106781f},{ 0.831469612f,-0.555570233f},{ 0.923879533f,-0.382683432f},{ 0.980785280f,-0.195090322f}
};

__device__ __forceinline__ float gelu_f(float v){
  return 0.5f*v*(1.0f+erff(v*0.7071067811865476f));
}
__device__ __forceinline__ unsigned bf2(float a, float b){
  __nv_bfloat162 h = __floats2bfloat162_rn(a, b);
  return *reinterpret_cast<unsigned*>(&h);
}
__device__ __forceinline__ float2 unbf2(unsigned u){
  __nv_bfloat162 h = *reinterpret_cast<__nv_bfloat162*>(&u);
  return __bfloat1622float2(h);
}
__device__ __forceinline__ void mma16(float4& d, uint4 a, unsigned b0, unsigned b1){
  asm volatile("mma.sync.aligned.m16n8k16.row.col.f32.bf16.bf16.f32 "
    "{%0,%1,%2,%3}, {%4,%5,%6,%7}, {%8,%9}, {%0,%1,%2,%3};"
    : "+f"(d.x), "+f"(d.y), "+f"(d.z), "+f"(d.w)
    : "r"(a.x), "r"(a.y), "r"(a.z), "r"(a.w), "r"(b0), "r"(b1));
}

// ---------------- K0a: bf16 m16n8k16 twiddle fragments ----------------
__global__ void k_init4h(){
  int j = blockIdx.x*256 + threadIdx.x;   // 0..1023
  int lane = j&31, qid = lane>>2, rid = lane&3;
  int which = j>>9, t = j&511;
  int mat, kk16, mt;
  if (which==0){ mt=(t>>5)&1; kk16=(t>>6)&3; mat=t>>8; }   // fwd: M=32,K=64
  else         { mt=(t>>5)&3; kk16=(t>>7)&1; mat=t>>8; }   // inv: M=64,K=32
  int r0 = mt*16+qid, r1 = r0+8, k0 = kk16*16 + 2*rid;
  float v[8];
#pragma unroll
  for (int q=0; q<8; q++){
    int m = (q&1) ? r1 : r0;
    int k = k0 + (q>>2)*8 + ((q>>1)&1);
    double a = (double)(m*k)/32.0;
    v[q] = (float)((mat ? sinpi(a) : cospi(a))*0.125);
  }
  g_A4H[j] = make_uint4(bf2(v[0],v[2]), bf2(v[1],v[3]), bf2(v[4],v[6]), bf2(v[5],v[7]));
}

// ---------------- K0: fold HydraLoRA ----------------
__global__ void k_prep(const float* __restrict__ w1, const float* __restrict__ b1,
                       const float* __restrict__ w2, const float* __restrict__ b2,
                       const float* __restrict__ A1r, const float* __restrict__ B1r,
                       const float* __restrict__ A1i, const float* __restrict__ B1i,
                       const float* __restrict__ A2r, const float* __restrict__ B2r,
                       const float* __restrict__ A2i, const float* __restrict__ B2i,
                       const float* __restrict__ ew){
  int k  = blockIdx.x;
  int io = threadIdx.x;
  int i = io >> 4, o = io & 15;
  float e0 = ew[0], e1 = ew[1], e2 = ew[2], e3 = ew[3];
  const float s = 0.03125f;
  const float* Ws[4] = { w1 + k*256, w1 + 2048 + k*256, w2 + k*256, w2 + 2048 + k*256 };
  const float* As[4] = { A1r + k*512, A1i + k*512, A2r + k*512, A2i + k*512 };
  const float* Bs[4] = { B1r + k*2048, B1i + k*2048, B2r + k*2048, B2i + k*2048 };
#pragma unroll
  for (int m = 0; m < 4; m++){
    const float* A  = As[m] + i*32;
    const float* Bb = Bs[m];
    float acc = 0.f;
    for (int r = 0; r < 32; r++){
      float bm = e0*Bb[r*16+o] + e1*Bb[512+r*16+o] + e2*Bb[1024+r*16+o] + e3*Bb[1536+r*16+o];
      acc = fmaf(A[r], bm, acc);
    }
    g_W[((m*8+k)*16+i)*16+o] = Ws[m][i*16+o] + s*acc;
  }
  if (io < 16){
    float b10 = b1[k*16+io], b11 = b1[128+k*16+io];
    float b20 = b2[k*16+io], b21 = b2[128+k*16+io];
    g_Bias[      k*16+io] = b10 - b11;
    g_Bias[128 + k*16+io] = b10 + b11;
    g_Bias[256 + k*16+io] = b20 - b21;
    g_Bias[384 + k*16+io] = b20 + b21;
  }
}

// ---------------- K1: forward rfft over L ----------------
__global__ void __launch_bounds__(128) k_fwd_l(const float* __restrict__ x){
  __shared__ float2 tw[32];
  if (threadIdx.x < 32) tw[threadIdx.x] = TW32[threadIdx.x];
  __syncthreads();
  int site = blockIdx.x*2 + (threadIdx.x>>6);
  int c = threadIdx.x & 63;
  const float2* xp = (const float2*)(x + (size_t)site*4096) + c;
  float2 u[16], dd[16];
#pragma unroll
  for (int t=0;t<16;t++){
    float2 a = xp[t*64], b2 = xp[(t+16)*64];
    u[t]  = make_float2(a.x+b2.x, a.y+b2.y);
    dd[t] = make_float2(a.x-b2.x, a.y-b2.y);
  }
  float2 ar[8], ai[8];
#pragma unroll
  for (int l=0;l<8;l++){ ar[l]=make_float2(0.f,0.f); ai[l]=make_float2(0.f,0.f); }
#pragma unroll
  for (int t=0;t<16;t++){
#pragma unroll
    for (int j=0;j<4;j++){
      float2 we = tw[(t*2*j)&31];
      ar[2*j].x = fmaf( u[t].x, we.x, ar[2*j].x);
      ar[2*j].y = fmaf( u[t].y, we.x, ar[2*j].y);
      ai[2*j].x = fmaf(-u[t].x, we.y, ai[2*j].x);
      ai[2*j].y = fmaf(-u[t].y, we.y, ai[2*j].y);
      float2 wo = tw[(t*(2*j+1))&31];
      ar[2*j+1].x = fmaf( dd[t].x, wo.x, ar[2*j+1].x);
      ar[2*j+1].y = fmaf( dd[t].y, wo.x, ar[2*j+1].y);
      ai[2*j+1].x = fmaf(-dd[t].x, wo.y, ai[2*j+1].x);
      ai[2*j+1].y = fmaf(-dd[t].y, wo.y, ai[2*j+1].y);
    }
  }
  const float s = 0.1767766952966369f;
  uint2* op = (uint2*)g_s3h + (size_t)site*512 + c;
#pragma unroll
  for (int l=0;l<8;l++)
    op[l*64] = make_uint2(bf2(ar[l].x*s, ai[l].x*s), bf2(ar[l].y*s, ai[l].y*s));
}

// ---------------- complex DFT GEMM (bf16 m16n8k16) + coalesced smem epilogue ----------------
template<int M, int K, int SGN, int MINB>
__global__ void __launch_bounds__(128, MINB) k_dft_mma(const unsigned* __restrict__ in,
                                                 unsigned* __restrict__ out,
                                                 const uint4* __restrict__ A4,
                                                 size_t inStrideC, size_t outStrideC){
  constexpr int KT16 = K/16;
  constexpr int MT = M/16;
  constexpr int K2 = K/2;
  constexpr int SMW = (K2*72 > M*36) ? K2*72 : M*36;
  __shared__ __align__(16) unsigned Bs[SMW];
  int tid = threadIdx.x;
  const unsigned* src = in + blockIdx.y*inStrideC + blockIdx.x*32;
  for (int i = tid; i < K2*16; i += 128){
    int k2 = i>>4, j2p = i&15;
    uint2 a = *(const uint2*)(src + (size_t)(2*k2)*1024 + 2*j2p);
    uint2 b = *(const uint2*)(src + (size_t)(2*k2+1)*1024 + 2*j2p);
    *(uint4*)(Bs + k2*72 + 4*j2p) = make_uint4(
      __byte_perm(a.x, b.x, 0x5410), __byte_perm(a.x, b.x, 0x7632),
      __byte_perm(a.y, b.y, 0x5410), __byte_perm(a.y, b.y, 0x7632));
  }
  __syncthreads();
  int warp = tid>>5, lane = tid&31;
  int qid = lane>>2, rid = lane&3;
  int wcol = warp*16;
  float4 C[2][MT][2];
#pragma unroll
  for (int a=0;a<2;a++)
#pragma unroll
    for (int b=0;b<MT;b++)
#pragma unroll
      for (int c=0;c<2;c++) C[a][b][c] = make_float4(0.f,0.f,0.f,0.f);
#pragma unroll
  for (int kk=0; kk<KT16; kk++){
    int s0 = (kk*8 + rid)*72, s1 = (kk*8 + rid + 4)*72;
    unsigned b0n0 = Bs[s0 + wcol + qid];
    unsigned b1n0 = Bs[s1 + wcol + qid];
    unsigned b0n1 = Bs[s0 + wcol + 8 + qid];
    unsigned b1n1 = Bs[s1 + wcol + 8 + qid];
#pragma unroll
    for (int mm=0; mm<2; mm++){
#pragma unroll
      for (int mt=0; mt<MT; mt++){
        uint4 af = __ldg(A4 + ((mm*KT16+kk)*MT+mt)*32 + lane);
        mma16(C[mm][mt][0], af, b0n0, b1n0);
        mma16(C[mm][mt][1], af, b0n1, b1n1);
      }
    }
  }
  // epilogue: combine -> smem transpose (stride 36, conflict-free STS) -> coalesced STG.128
  __syncthreads();
#pragma unroll
  for (int mt=0; mt<MT; mt++){
#pragma unroll
    for (int nt=0; nt<2; nt++){
      float4 cr = C[0][mt][nt], ci = C[1][mt][nt];
      int colC = warp*8 + nt*4 + rid;
      int m0 = mt*16 + qid;
      if (SGN > 0){
        Bs[m0*36 + colC]     = bf2(cr.x + ci.y, cr.y - ci.x);
        Bs[(m0+8)*36 + colC] = bf2(cr.z + ci.w, cr.w - ci.z);
      } else {
        Bs[m0*36 + colC]     = bf2(cr.x - ci.y, cr.y + ci.x);
        Bs[(m0+8)*36 + colC] = bf2(cr.z - ci.w, cr.w + ci.z);
      }
    }
  }
  __syncthreads();
  unsigned* ob = out + blockIdx.y*outStrideC + blockIdx.x*32;
#pragma unroll
  for (int i = tid; i < M*4; i += 128){
    int r = i>>2, sg = i&3;
    uint4 w0 = *(const uint4*)(Bs + r*36 + sg*8);
    uint4 w1 = *(const uint4*)(Bs + r*36 + sg*8 + 4);
    *(uint4*)(ob + (size_t)r*1024 + sg*8)     = w0;
    *(uint4*)(ob + (size_t)r*1024 + sg*8 + 4) = w1;
  }
}

// ---------------- K_mid: fwd-H + MLP + inv-H in place (o-split MLP, coalesced epilogue) ----------------
// smem: sW[4096 f]@0 | sBias[272 f]@4096 | U[4352 u]@4368 | U2[2176 u]@8720 = 43584 B
__global__ void __launch_bounds__(256,3) k_mid(){
  extern __shared__ float sm[];
  float* sW    = sm;
  float* sBias = sm + 4096;
  unsigned* U  = (unsigned*)(sm + 4368);   // 32 k2-slices x 136 words (GEMM1 B) / later 64x68 transpose
  unsigned* U2 = (unsigned*)(sm + 8720);   // 16 k2-slices x 136 words (GEMM2 B)
  int tid = threadIdx.x;
  int bx = blockIdx.x, b = blockIdx.y;
  int w = bx>>4, l = (bx>>1)&7, chalf = bx&1;
  for (int i=tid; i<1024; i+=256){
    int mg=i>>8, nb0=(i>>6)&3;
    ((float4*)sW)[i] = ((const float4*)g_W)[(mg*8+chalf*4+nb0)*64 + (i&63)];
  }
  { int mg=tid>>6, nb0=(tid>>4)&3, o=tid&15;
    sBias[(mg*4+nb0)*17+o] = g_Bias[mg*128 + (chalf*4+nb0)*16 + o]; }
  unsigned* gs = g_s2h + (size_t)b*2097152 + (size_t)w*1024 + l*128 + chalf*64;
  for (int i=tid; i<1024; i+=256){
    int k2 = i>>5, j2p = i&31;
    uint2 a = *(const uint2*)(gs + (size_t)(2*k2)*32768 + 2*j2p);
    uint2 bb = *(const uint2*)(gs + (size_t)(2*k2+1)*32768 + 2*j2p);
    *(uint4*)(U + k2*136 + 4*j2p) = make_uint4(
      __byte_perm(a.x, bb.x, 0x5410), __byte_perm(a.x, bb.x, 0x7632),
      __byte_perm(a.y, bb.y, 0x5410), __byte_perm(a.y, bb.y, 0x7632));
  }
  __syncthreads();
  int warp=tid>>5, lane=tid&31, qid=lane>>2, rid=lane&3;
  int wcol = warp*16;
  // GEMM1 fwd-H: M=32, K=64(y), N=128, bf16 mma16
  float4 C1[2][2][2];
#pragma unroll
  for (int a=0;a<2;a++)
#pragma unroll
    for (int m=0;m<2;m++)
#pragma unroll
      for (int n=0;n<2;n++) C1[a][m][n] = make_float4(0.f,0.f,0.f,0.f);
#pragma unroll
  for (int kk=0; kk<4; kk++){
    int s0 = (kk*8+rid)*136, s1 = (kk*8+rid+4)*136;
    unsigned b0n0 = U[s0 + wcol + qid];
    unsigned b1n0 = U[s1 + wcol + qid];
    unsigned b0n1 = U[s0 + wcol + 8 + qid];
    unsigned b1n1 = U[s1 + wcol + 8 + qid];
#pragma unroll
    for (int mat=0; mat<2; mat++){
#pragma unroll
      for (int mt=0; mt<2; mt++){
        uint4 af = __ldg(&g_A4H[((mat*4+kk)*2+mt)*32 + lane]);
        mma16(C1[mat][mt][0], af, b0n0, b1n0);
        mma16(C1[mat][mt][1], af, b0n1, b1n1);
      }
    }
  }
  __syncthreads();
  float2* sSpec = (float2*)U;   // 32 h-rows x stride 65 f2 (16640 B <= 17408 B)
#pragma unroll
  for (int mt=0; mt<2; mt++)
#pragma unroll
    for (int nt=0; nt<2; nt++){
      float4 cc = C1[0][mt][nt], cs = C1[1][mt][nt];
      int c2 = warp*8+nt*4+rid, h0 = mt*16+qid;
      sSpec[h0*65 + c2]     = make_float2(cc.x+cs.y, cc.y-cs.x);
      sSpec[(h0+8)*65 + c2] = make_float2(cc.z+cs.w, cc.w-cs.z);
    }
  __syncthreads();
  // MLP: inst=(nb0,h), 2 threads each; layer1 o-split, p exchanged in-place via sSpec
  {
    int inst=tid>>1, half=tid&1, nb0=inst>>5, h=inst&31;
    const float* W1R = sW + nb0*256;
    const float* W1I = sW + (4+nb0)*256;
    const float* W2R = sW + (8+nb0)*256;
    const float* W2I = sW + (12+nb0)*256;
    const float* Bb0 = sBias + nb0*17;
    const float* Bb1 = sBias + (4+nb0)*17;
    const float* Bb2 = sBias + (8+nb0)*17;
    const float* Bb3 = sBias + (12+nb0)*17;
    float2* myx = sSpec + h*65 + nb0*16;
    float xr[16], xi[16];
#pragma unroll
    for (int i=0;i<16;i++){ float2 v = myx[i]; xr[i]=v.x; xi[i]=v.y; }
    __syncthreads();   // all x reads done before in-place overwrite
    float pr[8], pi[8];
#pragma unroll
    for (int oo=0;oo<8;oo++){ int o=half*8+oo; pr[oo]=Bb0[o]; pi[oo]=Bb1[o]; }
#pragma unroll
    for (int i=0;i<16;i++){
      float xrv = xr[i], xiv = xi[i];
#pragma unroll
      for (int o4=0;o4<2;o4++){
        float4 wr = *(const float4*)(W1R + i*16 + half*8 + o4*4);
        float4 wi = *(const float4*)(W1I + i*16 + half*8 + o4*4);
        pr[o4*4+0] += xrv*wr.x - xiv*wi.x;  pi[o4*4+0] += xiv*wr.x + xrv*wi.x;
        pr[o4*4+1] += xrv*wr.y - xiv*wi.y;  pi[o4*4+1] += xiv*wr.y + xrv*wi.y;
        pr[o4*4+2] += xrv*wr.z - xiv*wi.z;  pi[o4*4+2] += xiv*wr.z + xrv*wi.z;
        pr[o4*4+3] += xrv*wr.w - xiv*wi.w;  pi[o4*4+3] += xiv*wr.w + xrv*wi.w;
      }
    }
#pragma unroll
    for (int oo=0;oo<8;oo++){ pr[oo]=gelu_f(pr[oo]); pi[oo]=gelu_f(pi[oo]); }
#pragma unroll
    for (int oo=0;oo<8;oo++) myx[half*8+oo] = make_float2(pr[oo], pi[oo]);
    __syncthreads();   // full p visible
    float qr[8], qi[8];
#pragma unroll
    for (int oo=0;oo<8;oo++){ int o=half*8+oo; qr[oo]=Bb2[o]; qi[oo]=Bb3[o]; }
#pragma unroll
    for (int i=0;i<16;i++){
      float2 p = myx[i];
#pragma unroll
      for (int o4=0;o4<2;o4++){
        float4 wr = *(const float4*)(W2R + i*16 + half*8 + o4*4);
        float4 wi = *(const float4*)(W2I + i*16 + half*8 + o4*4);
        qr[o4*4+0] += p.x*wr.x - p.y*wi.x;  qi[o4*4+0] += p.y*wr.x + p.x*wi.x;
        qr[o4*4+1] += p.x*wr.y - p.y*wi.y;  qi[o4*4+1] += p.y*wr.y + p.x*wi.y;
        qr[o4*4+2] += p.x*wr.z - p.y*wi.z;  qi[o4*4+2] += p.y*wr.z + p.x*wi.z;
        qr[o4*4+3] += p.x*wr.w - p.y*wi.w;  qi[o4*4+3] += p.y*wr.w + p.x*wi.w;
      }
    }
    __nv_bfloat16* d16 = (__nv_bfloat16*)U2;
    int base = ((h>>1)*136)*2 + (h&1);
#pragma unroll
    for (int oo=0;oo<8;oo++){
      int n_re = 2*(nb0*16 + half*8 + oo);
      d16[base + n_re*2]     = __float2bfloat16_rn(qr[oo]);
      d16[base + (n_re+1)*2] = __float2bfloat16_rn(qi[oo]);
    }
  }
  __syncthreads();
  // GEMM2 inv-H: M=64, K=32(h), N=128, bf16 mma16
  float4 C3[2][4][2];
#pragma unroll
  for (int a=0;a<2;a++)
#pragma unroll
    for (int m=0;m<4;m++)
#pragma unroll
      for (int n=0;n<2;n++) C3[a][m][n] = make_float4(0.f,0.f,0.f,0.f);
#pragma unroll
  for (int kk=0; kk<2; kk++){
    int s0 = (kk*8+rid)*136, s1 = (kk*8+rid+4)*136;
    unsigned b0n0 = U2[s0 + wcol + qid];
    unsigned b1n0 = U2[s1 + wcol + qid];
    unsigned b0n1 = U2[s0 + wcol + 8 + qid];
    unsigned b1n1 = U2[s1 + wcol + 8 + qid];
#pragma unroll
    for (int mat=0; mat<2; mat++){
#pragma unroll
      for (int mt=0; mt<4; mt++){
        uint4 af = __ldg(&g_A4H[512 + ((mat*2+kk)*4+mt)*32 + lane]);
        mma16(C3[mat][mt][0], af, b0n0, b1n0);
        mma16(C3[mat][mt][1], af, b0n1, b1n1);
      }
    }
  }
  // epilogue: combine -> smem transpose (U, 64 rows x stride 68) -> coalesced STG.128
  // U is dead (sSpec fully consumed); U2 may still be read by lagging warps, untouched.
#pragma unroll
  for (int mt=0; mt<4; mt++)
#pragma unroll
    for (int nt=0; nt<2; nt++){
      float4 cc = C3[0][mt][nt], cs = C3[1][mt][nt];
      int c2 = warp*8+nt*4+rid, y0 = mt*16+qid;
      U[y0*68 + c2]     = bf2(cc.x-cs.y, cc.y+cs.x);
      U[(y0+8)*68 + c2] = bf2(cc.z-cs.w, cc.w+cs.z);
    }
  __syncthreads();
  {
    int r = tid>>2, sg = tid&3;
#pragma unroll
    for (int q=0; q<4; q++){
      uint4 v = *(const uint4*)(U + r*68 + sg*16 + q*4);
      *(uint4*)(gs + (size_t)r*32768 + sg*16 + q*4) = v;
    }
  }
}

// ---------------- K7: inverse rfft over L + residual ----------------
__global__ void __launch_bounds__(128) k_inv_l(const float* __restrict__ xin, float* __restrict__ out){
  __shared__ float2 tw[32];
  if (threadIdx.x < 32) tw[threadIdx.x] = TW32[threadIdx.x];
  __syncthreads();
  int site = blockIdx.x*2 + (threadIdx.x>>6);
  int c = threadIdx.x & 63;
  const uint2* ip = (const uint2*)g_s3h + (size_t)site*512 + c;
  float2 Xr[8], Xi[8];
#pragma unroll
  for (int l=0;l<8;l++){
    uint2 v = ip[l*64];
    float2 f0 = unbf2(v.x), f1 = unbf2(v.y);
    Xr[l] = make_float2(f0.x, f1.x);
    Xi[l] = make_float2(f0.y, f1.y);
  }
#pragma unroll
  for (int l=1;l<8;l++){ Xr[l].x*=2.f; Xr[l].y*=2.f; Xi[l].x*=2.f; Xi[l].y*=2.f; }
  const float s = 0.1767766952966369f;
  const float2* rp = (const float2*)(xin + (size_t)site*4096) + c;
  float2* op = (float2*)(out + (size_t)site*4096) + c;
#pragma unroll
  for (int t=0;t<16;t++){
    float2 E = Xr[0];
    float2 O = make_float2(0.f,0.f);
#pragma unroll
    for (int j=1;j<4;j++){
      float2 we = tw[(2*j*t)&31];
      E.x += Xr[2*j].x*we.x - Xi[2*j].x*we.y;
      E.y += Xr[2*j].y*we.x - Xi[2*j].y*we.y;
    }
#pragma unroll
    for (int j=0;j<4;j++){
      float2 wo = tw[((2*j+1)*t)&31];
      O.x += Xr[2*j+1].x*wo.x - Xi[2*j+1].x*wo.y;
      O.y += Xr[2*j+1].y*wo.x - Xi[2*j+1].y*wo.y;
    }
    float2 r0 = rp[t*64], r1 = rp[(t+16)*64];
    op[t*64]      = make_float2(fmaf(E.x+O.x, s, r0.x), fmaf(E.y+O.y, s, r0.y));
    op[(t+16)*64] = make_float2(fmaf(E.x-O.x, s, r1.x), fmaf(E.y-O.y, s, r1.y));
  }
}

// ---------------- launch ----------------
extern "C" void kernel_launch(void* const* d_in, const int* in_sizes, int n_in,
                              void* d_out, int out_size){
  (void)in_sizes; (void)n_in; (void)out_size;
  const float* x = (const float*)d_in[0];
  void *ps3, *ps2, *pah;
  cudaGetSymbolAddress(&ps3, g_s3h);
  cudaGetSymbolAddress(&ps2, g_s2h);
  cudaGetSymbolAddress(&pah, g_A4H);
  const unsigned* s3 = (const unsigned*)ps3;
  const unsigned* s2 = (const unsigned*)ps2;
  const uint4* ah = (const uint4*)pah;
  cudaFuncSetAttribute(k_mid, cudaFuncAttributeMaxDynamicSharedMemorySize, 43584);

  k_prep<<<8,256>>>((const float*)d_in[1], (const float*)d_in[2], (const float*)d_in[3],
                    (const float*)d_in[4], (const float*)d_in[5], (const float*)d_in[6],
                    (const float*)d_in[7], (const float*)d_in[8], (const float*)d_in[9],
                    (const float*)d_in[10], (const float*)d_in[11], (const float*)d_in[12],
                    (const float*)d_in[13]);
  k_init4h<<<4,256>>>();
  k_fwd_l<<<8192,128>>>(x);
  // fwd W: Out[32 w][1024C] = T @ In[64 xx][1024C], 256 (b,y) batches
  k_dft_mma<32,64, 1,8><<<dim3(32,256),128>>>(s3, (unsigned*)s2, ah, 65536, 32768);
  // fwd H + MLP + inv H, in place on g_s2h
  k_mid<<<dim3(512,4),256,43584>>>();
  // inv W: Out[64 xx][1024C] = T @ In[32 w][1024C]
  k_dft_mma<64,32,-1,6><<<dim3(32,256),128>>>(s2, (unsigned*)s3, ah + 512, 32768, 65536);
  k_inv_l<<<8192,128>>>(x, (float*)d_out);
}

// round 16
// speedup vs baseline: 1.3745x; 1.0352x over previous
#include <cuda_runtime.h>
#include <cuda_bf16.h>
#include <math.h>

// ---------------- scratch (bf16x2 complex intermediates) ----------------
__device__ __align__(16) unsigned g_s3h[16777216]; // [4][64][64][8][128] complexes (bf16 re,im)
__device__ __align__(16) unsigned g_s2h[8388608];  // [4][64][32][8][128] complexes
__device__ __align__(16) float  g_W[8192];
__device__ __align__(16) float  g_Bias[512];
__device__ __align__(16) uint4  g_A4H[1024];       // bf16 m16n8k16 fragments: [fwd M32K64: 512 | inv M64K32: 512]
__device__ __align__(16) uint4  g_A4L[64];         // inv-L bf16 fragments: M=32(t), K=16(2l+pp), x2 + 1/sqrt32 baked

__constant__ float2 TW32[32] = {
  { 1.000000000f, 0.000000000f},{ 0.980785280f, 0.195090322f},{ 0.923879533f, 0.382683432f},{ 0.831469612f, 0.555570233f},
  { 0.707106781f, 0.707106781f},{ 0.555570233f, 0.831469612f},{ 0.382683432f, 0.923879533f},{ 0.195090322f, 0.980785280f},
  { 0.000000000f, 1.000000000f},{-0.195090322f, 0.980785280f},{-0.382683432f, 0.923879533f},{-0.555570233f, 0.831469612f},
  {-0.707106781f, 0.707106781f},{-0.831469612f, 0.555570233f},{-0.923879533f, 0.382683432f},{-0.980785280f, 0.195090322f},
  {-1.000000000f, 0.000000000f},{-0.980785280f,-0.195090322f},{-0.923879533f,-0.382683432f},{-0.831469612f,-0.555570233f},
  {-0.707106781f,-0.707106781f},{-0.555570233f,-0.831469612f},{-0.382683432f,-0.923879533f},{-0.195090322f,-0.980785280f},
  { 0.000000000f,-1.000000000f},{ 0.195090322f,-0.980785280f},{ 0.382683432f,-0.923879533f},{ 0.555570233f,-0.831469612f},
  { 0.707106781f,-0.707106781f},{ 0.831469612f,-0.555570233f},{ 0.923879533f,-0.382683432f},{ 0.980785280f,-0.195090322f}
};

__device__ __forceinline__ float gelu_f(float v){
  return 0.5f*v*(1.0f+erff(v*0.7071067811865476f));
}
__device__ __forceinline__ unsigned bf2(float a, float b){
  __nv_bfloat162 h = __floats2bfloat162_rn(a, b);
  return *reinterpret_cast<unsigned*>(&h);
}
__device__ __forceinline__ float2 unbf2(unsigned u){
  __nv_bfloat162 h = *reinterpret_cast<__nv_bfloat162*>(&u);
  return __bfloat1622float2(h);
}
__device__ __forceinline__ void mma16(float4& d, uint4 a, unsigned b0, unsigned b1){
  asm volatile("mma.sync.aligned.m16n8k16.row.col.f32.bf16.bf16.f32 "
    "{%0,%1,%2,%3}, {%4,%5,%6,%7}, {%8,%9}, {%0,%1,%2,%3};"
    : "+f"(d.x), "+f"(d.y), "+f"(d.z), "+f"(d.w)
    : "r"(a.x), "r"(a.y), "r"(a.z), "r"(a.w), "r"(b0), "r"(b1));
}

// ---------------- K0a: bf16 m16n8k16 twiddle fragments ----------------
__global__ void k_init4h(){
  int j = blockIdx.x*256 + threadIdx.x;   // 0..1279 (guarded)
  int lane = j&31, qid = lane>>2, rid = lane&3;
  const double s32 = 0.17677669529663688911;
  if (j < 1024){
    int which = j>>9, t = j&511;
    int mat, kk16, mt;
    if (which==0){ mt=(t>>5)&1; kk16=(t>>6)&3; mat=t>>8; }   // fwd: M=32,K=64
    else         { mt=(t>>5)&3; kk16=(t>>7)&1; mat=t>>8; }   // inv: M=64,K=32
    int r0 = mt*16+qid, r1 = r0+8, k0 = kk16*16 + 2*rid;
    float v[8];
#pragma unroll
    for (int q=0; q<8; q++){
      int m = (q&1) ? r1 : r0;
      int k = k0 + (q>>2)*8 + ((q>>1)&1);
      double a = (double)(m*k)/32.0;
      v[q] = (float)((mat ? sinpi(a) : cospi(a))*0.125);
    }
    g_A4H[j] = make_uint4(bf2(v[0],v[2]), bf2(v[1],v[3]), bf2(v[4],v[6]), bf2(v[5],v[7]));
  } else if (j < 1088){
    int t = j-1024;                 // 0..63
    int mt = t>>5;                  // 0..1
    int r0 = mt*16+qid, r1 = r0+8;  // t-rows
    float v[8];
#pragma unroll
    for (int q=0; q<8; q++){
      int m = (q&1) ? r1 : r0;
      int k = 2*rid + (q>>2)*8 + ((q>>1)&1);
      int l = k>>1, pp = k&1;
      double cl = (l==0)?1.0:2.0;
      double a = (double)(m*l)/16.0;
      v[q] = (float)((pp==0 ? cl*cospi(a) : -cl*sinpi(a))*s32);
    }
    g_A4L[t] = make_uint4(bf2(v[0],v[2]), bf2(v[1],v[3]), bf2(v[4],v[6]), bf2(v[5],v[7]));
  }
}

// ---------------- K0: fold HydraLoRA ----------------
__global__ void k_prep(const float* __restrict__ w1, const float* __restrict__ b1,
                       const float* __restrict__ w2, const float* __restrict__ b2,
                       const float* __restrict__ A1r, const float* __restrict__ B1r,
                       const float* __restrict__ A1i, const float* __restrict__ B1i,
                       const float* __restrict__ A2r, const float* __restrict__ B2r,
                       const float* __restrict__ A2i, const float* __restrict__ B2i,
                       const float* __restrict__ ew){
  int k  = blockIdx.x;
  int io = threadIdx.x;
  int i = io >> 4, o = io & 15;
  float e0 = ew[0], e1 = ew[1], e2 = ew[2], e3 = ew[3];
  const float s = 0.03125f;
  const float* Ws[4] = { w1 + k*256, w1 + 2048 + k*256, w2 + k*256, w2 + 2048 + k*256 };
  const float* As[4] = { A1r + k*512, A1i + k*512, A2r + k*512, A2i + k*512 };
  const float* Bs[4] = { B1r + k*2048, B1i + k*2048, B2r + k*2048, B2i + k*2048 };
#pragma unroll
  for (int m = 0; m < 4; m++){
    const float* A  = As[m] + i*32;
    const float* Bb = Bs[m];
    float acc = 0.f;
    for (int r = 0; r < 32; r++){
      float bm = e0*Bb[r*16+o] + e1*Bb[512+r*16+o] + e2*Bb[1024+r*16+o] + e3*Bb[1536+r*16+o];
      acc = fmaf(A[r], bm, acc);
    }
    g_W[((m*8+k)*16+i)*16+o] = Ws[m][i*16+o] + s*acc;
  }
  if (io < 16){
    float b10 = b1[k*16+io], b11 = b1[128+k*16+io];
    float b20 = b2[k*16+io], b21 = b2[128+k*16+io];
    g_Bias[      k*16+io] = b10 - b11;
    g_Bias[128 + k*16+io] = b10 + b11;
    g_Bias[256 + k*16+io] = b20 - b21;
    g_Bias[384 + k*16+io] = b20 + b21;
  }
}

// ---------------- K1: forward rfft over L ----------------
__global__ void __launch_bounds__(128) k_fwd_l(const float* __restrict__ x){
  __shared__ float2 tw[32];
  if (threadIdx.x < 32) tw[threadIdx.x] = TW32[threadIdx.x];
  __syncthreads();
  int site = blockIdx.x*2 + (threadIdx.x>>6);
  int c = threadIdx.x & 63;
  const float2* xp = (const float2*)(x + (size_t)site*4096) + c;
  float2 u[16], dd[16];
#pragma unroll
  for (int t=0;t<16;t++){
    float2 a = xp[t*64], b2 = xp[(t+16)*64];
    u[t]  = make_float2(a.x+b2.x, a.y+b2.y);
    dd[t] = make_float2(a.x-b2.x, a.y-b2.y);
  }
  float2 ar[8], ai[8];
#pragma unroll
  for (int l=0;l<8;l++){ ar[l]=make_float2(0.f,0.f); ai[l]=make_float2(0.f,0.f); }
#pragma unroll
  for (int t=0;t<16;t++){
#pragma unroll
    for (int j=0;j<4;j++){
      float2 we = tw[(t*2*j)&31];
      ar[2*j].x = fmaf( u[t].x, we.x, ar[2*j].x);
      ar[2*j].y = fmaf( u[t].y, we.x, ar[2*j].y);
      ai[2*j].x = fmaf(-u[t].x, we.y, ai[2*j].x);
      ai[2*j].y = fmaf(-u[t].y, we.y, ai[2*j].y);
      float2 wo = tw[(t*(2*j+1))&31];
      ar[2*j+1].x = fmaf( dd[t].x, wo.x, ar[2*j+1].x);
      ar[2*j+1].y = fmaf( dd[t].y, wo.x, ar[2*j+1].y);
      ai[2*j+1].x = fmaf(-dd[t].x, wo.y, ai[2*j+1].x);
      ai[2*j+1].y = fmaf(-dd[t].y, wo.y, ai[2*j+1].y);
    }
  }
  const float s = 0.1767766952966369f;
  uint2* op = (uint2*)g_s3h + (size_t)site*512 + c;
#pragma unroll
  for (int l=0;l<8;l++)
    op[l*64] = make_uint2(bf2(ar[l].x*s, ai[l].x*s), bf2(ar[l].y*s, ai[l].y*s));
}

// ---------------- complex DFT GEMM (bf16 m16n8k16) + coalesced smem epilogue ----------------
template<int M, int K, int SGN, int MINB>
__global__ void __launch_bounds__(128, MINB) k_dft_mma(const unsigned* __restrict__ in,
                                                 unsigned* __restrict__ out,
                                                 const uint4* __restrict__ A4,
                                                 size_t inStrideC, size_t outStrideC){
  constexpr int KT16 = K/16;
  constexpr int MT = M/16;
  constexpr int K2 = K/2;
  constexpr int SMW = (K2*72 > M*36) ? K2*72 : M*36;
  __shared__ __align__(16) unsigned Bs[SMW];
  int tid = threadIdx.x;
  const unsigned* src = in + blockIdx.y*inStrideC + blockIdx.x*32;
  for (int i = tid; i < K2*16; i += 128){
    int k2 = i>>4, j2p = i&15;
    uint2 a = *(const uint2*)(src + (size_t)(2*k2)*1024 + 2*j2p);
    uint2 b = *(const uint2*)(src + (size_t)(2*k2+1)*1024 + 2*j2p);
    *(uint4*)(Bs + k2*72 + 4*j2p) = make_uint4(
      __byte_perm(a.x, b.x, 0x5410), __byte_perm(a.x, b.x, 0x7632),
      __byte_perm(a.y, b.y, 0x5410), __byte_perm(a.y, b.y, 0x7632));
  }
  __syncthreads();
  int warp = tid>>5, lane = tid&31;
  int qid = lane>>2, rid = lane&3;
  int wcol = warp*16;
  float4 C[2][MT][2];
#pragma unroll
  for (int a=0;a<2;a++)
#pragma unroll
    for (int b=0;b<MT;b++)
#pragma unroll
      for (int c=0;c<2;c++) C[a][b][c] = make_float4(0.f,0.f,0.f,0.f);
#pragma unroll
  for (int kk=0; kk<KT16; kk++){
    int s0 = (kk*8 + rid)*72, s1 = (kk*8 + rid + 4)*72;
    unsigned b0n0 = Bs[s0 + wcol + qid];
    unsigned b1n0 = Bs[s1 + wcol + qid];
    unsigned b0n1 = Bs[s0 + wcol + 8 + qid];
    unsigned b1n1 = Bs[s1 + wcol + 8 + qid];
#pragma unroll
    for (int mm=0; mm<2; mm++){
#pragma unroll
      for (int mt=0; mt<MT; mt++){
        uint4 af = __ldg(A4 + ((mm*KT16+kk)*MT+mt)*32 + lane);
        mma16(C[mm][mt][0], af, b0n0, b1n0);
        mma16(C[mm][mt][1], af, b0n1, b1n1);
      }
    }
  }
  __syncthreads();
#pragma unroll
  for (int mt=0; mt<MT; mt++){
#pragma unroll
    for (int nt=0; nt<2; nt++){
      float4 cr = C[0][mt][nt], ci = C[1][mt][nt];
      int colC = warp*8 + nt*4 + rid;
      int m0 = mt*16 + qid;
      if (SGN > 0){
        Bs[m0*36 + colC]     = bf2(cr.x + ci.y, cr.y - ci.x);
        Bs[(m0+8)*36 + colC] = bf2(cr.z + ci.w, cr.w - ci.z);
      } else {
        Bs[m0*36 + colC]     = bf2(cr.x - ci.y, cr.y + ci.x);
        Bs[(m0+8)*36 + colC] = bf2(cr.z - ci.w, cr.w + ci.z);
      }
    }
  }
  __syncthreads();
  unsigned* ob = out + blockIdx.y*outStrideC + blockIdx.x*32;
#pragma unroll
  for (int i = tid; i < M*4; i += 128){
    int r = i>>2, sg = i&3;
    uint4 w0 = *(const uint4*)(Bs + r*36 + sg*8);
    uint4 w1 = *(const uint4*)(Bs + r*36 + sg*8 + 4);
    *(uint4*)(ob + (size_t)r*1024 + sg*8)     = w0;
    *(uint4*)(ob + (size_t)r*1024 + sg*8 + 4) = w1;
  }
}

// ---------------- K_mid: fwd-H + MLP + inv-H in place (unchanged R15) ----------------
__global__ void __launch_bounds__(256,3) k_mid(){
  extern __shared__ float sm[];
  float* sW    = sm;
  float* sBias = sm + 4096;
  unsigned* U  = (unsigned*)(sm + 4368);
  unsigned* U2 = (unsigned*)(sm + 8720);
  int tid = threadIdx.x;
  int bx = blockIdx.x, b = blockIdx.y;
  int w = bx>>4, l = (bx>>1)&7, chalf = bx&1;
  for (int i=tid; i<1024; i+=256){
    int mg=i>>8, nb0=(i>>6)&3;
    ((float4*)sW)[i] = ((const float4*)g_W)[(mg*8+chalf*4+nb0)*64 + (i&63)];
  }
  { int mg=tid>>6, nb0=(tid>>4)&3, o=tid&15;
    sBias[(mg*4+nb0)*17+o] = g_Bias[mg*128 + (chalf*4+nb0)*16 + o]; }
  unsigned* gs = g_s2h + (size_t)b*2097152 + (size_t)w*1024 + l*128 + chalf*64;
  for (int i=tid; i<1024; i+=256){
    int k2 = i>>5, j2p = i&31;
    uint2 a = *(const uint2*)(gs + (size_t)(2*k2)*32768 + 2*j2p);
    uint2 bb = *(const uint2*)(gs + (size_t)(2*k2+1)*32768 + 2*j2p);
    *(uint4*)(U + k2*136 + 4*j2p) = make_uint4(
      __byte_perm(a.x, bb.x, 0x5410), __byte_perm(a.x, bb.x, 0x7632),
      __byte_perm(a.y, bb.y, 0x5410), __byte_perm(a.y, bb.y, 0x7632));
  }
  __syncthreads();
  int warp=tid>>5, lane=tid&31, qid=lane>>2, rid=lane&3;
  int wcol = warp*16;
  float4 C1[2][2][2];
#pragma unroll
  for (int a=0;a<2;a++)
#pragma unroll
    for (int m=0;m<2;m++)
#pragma unroll
      for (int n=0;n<2;n++) C1[a][m][n] = make_float4(0.f,0.f,0.f,0.f);
#pragma unroll
  for (int kk=0; kk<4; kk++){
    int s0 = (kk*8+rid)*136, s1 = (kk*8+rid+4)*136;
    unsigned b0n0 = U[s0 + wcol + qid];
    unsigned b1n0 = U[s1 + wcol + qid];
    unsigned b0n1 = U[s0 + wcol + 8 + qid];
    unsigned b1n1 = U[s1 + wcol + 8 + qid];
#pragma unroll
    for (int mat=0; mat<2; mat++){
#pragma unroll
      for (int mt=0; mt<2; mt++){
        uint4 af = __ldg(&g_A4H[((mat*4+kk)*2+mt)*32 + lane]);
        mma16(C1[mat][mt][0], af, b0n0, b1n0);
        mma16(C1[mat][mt][1], af, b0n1, b1n1);
      }
    }
  }
  __syncthreads();
  float2* sSpec = (float2*)U;
#pragma unroll
  for (int mt=0; mt<2; mt++)
#pragma unroll
    for (int nt=0; nt<2; nt++){
      float4 cc = C1[0][mt][nt], cs = C1[1][mt][nt];
      int c2 = warp*8+nt*4+rid, h0 = mt*16+qid;
      sSpec[h0*65 + c2]     = make_float2(cc.x+cs.y, cc.y-cs.x);
      sSpec[(h0+8)*65 + c2] = make_float2(cc.z+cs.w, cc.w-cs.z);
    }
  __syncthreads();
  {
    int inst=tid>>1, half=tid&1, nb0=inst>>5, h=inst&31;
    const float* W1R = sW + nb0*256;
    const float* W1I = sW + (4+nb0)*256;
    const float* W2R = sW + (8+nb0)*256;
    const float* W2I = sW + (12+nb0)*256;
    const float* Bb0 = sBias + nb0*17;
    const float* Bb1 = sBias + (4+nb0)*17;
    const float* Bb2 = sBias + (8+nb0)*17;
    const float* Bb3 = sBias + (12+nb0)*17;
    float2* myx = sSpec + h*65 + nb0*16;
    float xr[16], xi[16];
#pragma unroll
    for (int i=0;i<16;i++){ float2 v = myx[i]; xr[i]=v.x; xi[i]=v.y; }
    __syncthreads();
    float pr[8], pi[8];
#pragma unroll
    for (int oo=0;oo<8;oo++){ int o=half*8+oo; pr[oo]=Bb0[o]; pi[oo]=Bb1[o]; }
#pragma unroll
    for (int i=0;i<16;i++){
      float xrv = xr[i], xiv = xi[i];
#pragma unroll
      for (int o4=0;o4<2;o4++){
        float4 wr = *(const float4*)(W1R + i*16 + half*8 + o4*4);
        float4 wi = *(const float4*)(W1I + i*16 + half*8 + o4*4);
        pr[o4*4+0] += xrv*wr.x - xiv*wi.x;  pi[o4*4+0] += xiv*wr.x + xrv*wi.x;
        pr[o4*4+1] += xrv*wr.y - xiv*wi.y;  pi[o4*4+1] += xiv*wr.y + xrv*wi.y;
        pr[o4*4+2] += xrv*wr.z - xiv*wi.z;  pi[o4*4+2] += xiv*wr.z + xrv*wi.z;
        pr[o4*4+3] += xrv*wr.w - xiv*wi.w;  pi[o4*4+3] += xiv*wr.w + xrv*wi.w;
      }
    }
#pragma unroll
    for (int oo=0;oo<8;oo++){ pr[oo]=gelu_f(pr[oo]); pi[oo]=gelu_f(pi[oo]); }
#pragma unroll
    for (int oo=0;oo<8;oo++) myx[half*8+oo] = make_float2(pr[oo], pi[oo]);
    __syncthreads();
    float qr[8], qi[8];
#pragma unroll
    for (int oo=0;oo<8;oo++){ int o=half*8+oo; qr[oo]=Bb2[o]; qi[oo]=Bb3[o]; }
#pragma unroll
    for (int i=0;i<16;i++){
      float2 p = myx[i];
#pragma unroll
      for (int o4=0;o4<2;o4++){
        float4 wr = *(const float4*)(W2R + i*16 + half*8 + o4*4);
        float4 wi = *(const float4*)(W2I + i*16 + half*8 + o4*4);
        qr[o4*4+0] += p.x*wr.x - p.y*wi.x;  qi[o4*4+0] += p.y*wr.x + p.x*wi.x;
        qr[o4*4+1] += p.x*wr.y - p.y*wi.y;  qi[o4*4+1] += p.y*wr.y + p.x*wi.y;
        qr[o4*4+2] += p.x*wr.z - p.y*wi.z;  qi[o4*4+2] += p.y*wr.z + p.x*wi.z;
        qr[o4*4+3] += p.x*wr.w - p.y*wi.w;  qi[o4*4+3] += p.y*wr.w + p.x*wi.w;
      }
    }
    __nv_bfloat16* d16 = (__nv_bfloat16*)U2;
    int base = ((h>>1)*136)*2 + (h&1);
#pragma unroll
    for (int oo=0;oo<8;oo++){
      int n_re = 2*(nb0*16 + half*8 + oo);
      d16[base + n_re*2]     = __float2bfloat16_rn(qr[oo]);
      d16[base + (n_re+1)*2] = __float2bfloat16_rn(qi[oo]);
    }
  }
  __syncthreads();
  float4 C3[2][4][2];
#pragma unroll
  for (int a=0;a<2;a++)
#pragma unroll
    for (int m=0;m<4;m++)
#pragma unroll
      for (int n=0;n<2;n++) C3[a][m][n] = make_float4(0.f,0.f,0.f,0.f);
#pragma unroll
  for (int kk=0; kk<2; kk++){
    int s0 = (kk*8+rid)*136, s1 = (kk*8+rid+4)*136;
    unsigned b0n0 = U2[s0 + wcol + qid];
    unsigned b1n0 = U2[s1 + wcol + qid];
    unsigned b0n1 = U2[s0 + wcol + 8 + qid];
    unsigned b1n1 = U2[s1 + wcol + 8 + qid];
#pragma unroll
    for (int mat=0; mat<2; mat++){
#pragma unroll
      for (int mt=0; mt<4; mt++){
        uint4 af = __ldg(&g_A4H[512 + ((mat*2+kk)*4+mt)*32 + lane]);
        mma16(C3[mat][mt][0], af, b0n0, b1n0);
        mma16(C3[mat][mt][1], af, b0n1, b1n1);
      }
    }
  }
#pragma unroll
  for (int mt=0; mt<4; mt++)
#pragma unroll
    for (int nt=0; nt<2; nt++){
      float4 cc = C3[0][mt][nt], cs = C3[1][mt][nt];
      int c2 = warp*8+nt*4+rid, y0 = mt*16+qid;
      U[y0*68 + c2]     = bf2(cc.x-cs.y, cc.y+cs.x);
      U[(y0+8)*68 + c2] = bf2(cc.z-cs.w, cc.w+cs.z);
    }
  __syncthreads();
  {
    int r = tid>>2, sg = tid&3;
#pragma unroll
    for (int q=0; q<4; q++){
      uint4 v = *(const uint4*)(U + r*68 + sg*16 + q*4);
      *(uint4*)(gs + (size_t)r*32768 + sg*16 + q*4) = v;
    }
  }
}

// ---------------- K3: fused inverse (inv-W GEMM + inv-L GEMM + residual) ----------------
// grid (ct=16, y=64, b=4), 256 thr. All-bf16 mma16.
__global__ void __launch_bounds__(256,3) k_inv(const float* __restrict__ xin, float* __restrict__ out){
  __shared__ __align__(16) unsigned B1[2176];   // 16 w-pair slices x 136 words (N=128 float cols)
  __shared__ __align__(16) unsigned B2[4160];   // 8 l-slices x 520 words (N=512 real cols)
  int tid = threadIdx.x;
  int ct = blockIdx.x, y = blockIdx.y, b = blockIdx.z;
  const unsigned* gs = g_s2h + (size_t)b*2097152 + (size_t)y*32768 + ct*8;
  // stage B1: pack (w=2k2, 2k2+1) complex pairs; n = l*8+cc
  for (int i=tid; i<512; i+=256){
    int k2 = i>>5, l = (i>>2)&7, ccp = i&3;
    uint2 a  = *(const uint2*)(gs + (size_t)(2*k2)*1024 + l*128 + 2*ccp);
    uint2 bb = *(const uint2*)(gs + (size_t)(2*k2+1)*1024 + l*128 + 2*ccp);
    *(uint4*)(B1 + k2*136 + l*16 + 4*ccp) = make_uint4(
      __byte_perm(a.x, bb.x, 0x5410), __byte_perm(a.x, bb.x, 0x7632),
      __byte_perm(a.y, bb.y, 0x5410), __byte_perm(a.y, bb.y, 0x7632));
  }
  __syncthreads();
  int warp=tid>>5, lane=tid&31, qid=lane>>2, rid=lane&3;
  int wcol = warp*16;
  // GEMM1 inv-W: M=64(xx), K=32(w), N=128
  float4 C1[2][4][2];
#pragma unroll
  for (int a=0;a<2;a++)
#pragma unroll
    for (int m=0;m<4;m++)
#pragma unroll
      for (int n=0;n<2;n++) C1[a][m][n] = make_float4(0.f,0.f,0.f,0.f);
#pragma unroll
  for (int kk=0; kk<2; kk++){
    int s0 = (kk*8+rid)*136, s1 = (kk*8+rid+4)*136;
    unsigned b0n0 = B1[s0 + wcol + qid];
    unsigned b1n0 = B1[s1 + wcol + qid];
    unsigned b0n1 = B1[s0 + wcol + 8 + qid];
    unsigned b1n1 = B1[s1 + wcol + 8 + qid];
#pragma unroll
    for (int mat=0; mat<2; mat++){
#pragma unroll
      for (int mt=0; mt<4; mt++){
        uint4 af = __ldg(&g_A4H[512 + ((mat*2+kk)*4+mt)*32 + lane]);
        mma16(C1[mat][mt][0], af, b0n0, b1n0);
        mma16(C1[mat][mt][1], af, b0n1, b1n1);
      }
    }
  }
  // combine (inverse signs) -> B2: word (l, xx*8+cc) = complex = (re@k=2l, im@k=2l+1)
#pragma unroll
  for (int mt=0; mt<4; mt++)
#pragma unroll
    for (int nt=0; nt<2; nt++){
      float4 cc4 = C1[0][mt][nt], cs = C1[1][mt][nt];
      int colC = warp*8 + nt*4 + rid;
      int l = colC>>3, cc = colC&7;
      int xx0 = mt*16 + qid;
      B2[l*520 + xx0*8 + cc]     = bf2(cc4.x - cs.y, cc4.y + cs.x);
      B2[l*520 + (xx0+8)*8 + cc] = bf2(cc4.z - cs.w, cc4.w + cs.z);
    }
  __syncthreads();
  // GEMM2 inv-L: M=32(t), K=16(2l+pp), N=512 (xx*8+cc), single k-step
  float4 C2[2][8];
#pragma unroll
  for (int m=0;m<2;m++)
#pragma unroll
    for (int n=0;n<8;n++) C2[m][n] = make_float4(0.f,0.f,0.f,0.f);
  {
    int s0 = rid*520, s1 = (rid+4)*520;
    uint4 a0 = __ldg(&g_A4L[lane]);
    uint4 a1 = __ldg(&g_A4L[32+lane]);
#pragma unroll
    for (int nt=0; nt<8; nt++){
      unsigned b0 = B2[s0 + warp*64 + nt*8 + qid];
      unsigned b1 = B2[s1 + warp*64 + nt*8 + qid];
      mma16(C2[0][nt], a0, b0, b1);
      mma16(C2[1][nt], a1, b0, b1);
    }
  }
  // epilogue: residual + store (32B-sector aligned float2)
  const float* xb = xin + (size_t)(b*64+y)*262144 + ct*8;
  float* ob = out + (size_t)(b*64+y)*262144 + ct*8;
#pragma unroll
  for (int mt=0; mt<2; mt++)
#pragma unroll
    for (int nt=0; nt<8; nt++){
      float4 cv = C2[mt][nt];
      int n = warp*64 + nt*8 + rid*2;
      int xx = n>>3, cc = n&7;
      int t0 = mt*16 + qid;
      size_t a0 = (size_t)xx*4096 + t0*128 + cc;
      size_t a1 = (size_t)xx*4096 + (t0+8)*128 + cc;
      float2 r0 = *(const float2*)(xb + a0);
      float2 r1 = *(const float2*)(xb + a1);
      *(float2*)(ob + a0) = make_float2(cv.x + r0.x, cv.y + r0.y);
      *(float2*)(ob + a1) = make_float2(cv.z + r1.x, cv.w + r1.y);
    }
}

// ---------------- launch ----------------
extern "C" void kernel_launch(void* const* d_in, const int* in_sizes, int n_in,
                              void* d_out, int out_size){
  (void)in_sizes; (void)n_in; (void)out_size;
  const float* x = (const float*)d_in[0];
  void *ps3, *ps2, *pah;
  cudaGetSymbolAddress(&ps3, g_s3h);
  cudaGetSymbolAddress(&ps2, g_s2h);
  cudaGetSymbolAddress(&pah, g_A4H);
  const unsigned* s3 = (const unsigned*)ps3;
  const unsigned* s2 = (const unsigned*)ps2;
  const uint4* ah = (const uint4*)pah;
  cudaFuncSetAttribute(k_mid, cudaFuncAttributeMaxDynamicSharedMemorySize, 43584);

  k_prep<<<8,256>>>((const float*)d_in[1], (const float*)d_in[2], (const float*)d_in[3],
                    (const float*)d_in[4], (const float*)d_in[5], (const float*)d_in[6],
                    (const float*)d_in[7], (const float*)d_in[8], (const float*)d_in[9],
                    (const float*)d_in[10], (const float*)d_in[11], (const float*)d_in[12],
                    (const float*)d_in[13]);
  k_init4h<<<5,256>>>();
  k_fwd_l<<<8192,128>>>(x);
  // fwd W: Out[32 w][1024C] = T @ In[64 xx][1024C], 256 (b,y) batches
  k_dft_mma<32,64, 1,8><<<dim3(32,256),128>>>(s3, (unsigned*)s2, ah, 65536, 32768);
  // fwd H + MLP + inv H, in place on g_s2h
  k_mid<<<dim3(512,4),256,43584>>>();
  // fused inv W + inv L + residual
  k_inv<<<dim3(16,64,4),256>>>(x, (float*)d_out);
}